// round 8
// baseline (speedup 1.0000x reference)
#include <cuda_runtime.h>
#include <cuda_bf16.h>
#include <cstdint>

#define BATCH 8
#define SEQ   1024
#define FEAT  512
#define HEADS 8
#define DKDIM 64
#define TCUT  823
#define MTOT  (BATCH * SEQ)     // 8192
#define NQKV  1536

// ---------------- scratch (device globals; no runtime alloc) ----------------
__device__ __align__(256) __nv_bfloat16 g_ah[MTOT * FEAT];        // xn hi   [m][k]
__device__ __align__(256) __nv_bfloat16 g_al[MTOT * FEAT];        // xn lo
__device__ __align__(256) __nv_bfloat16 g_bh[NQKV * FEAT];        // W^T hi  [n][k]
__device__ __align__(256) __nv_bfloat16 g_bl[NQKV * FEAT];        // W^T lo
__device__ __align__(256) __nv_bfloat16 g_zh[MTOT * FEAT];        // z hi    [m][k]
__device__ __align__(256) __nv_bfloat16 g_zl[MTOT * FEAT];        // z lo
__device__ __align__(256) __nv_bfloat16 g_oh[FEAT * FEAT];        // WO^T hi [n][k]
__device__ __align__(256) __nv_bfloat16 g_ol[FEAT * FEAT];        // WO^T lo
// q,k: [b,h,s,d]; v transposed: [b,h,d,s]; all bf16 hi/lo
__device__ __align__(256) __nv_bfloat16 g_qh[64 * SEQ * DKDIM];
__device__ __align__(256) __nv_bfloat16 g_ql[64 * SEQ * DKDIM];
__device__ __align__(256) __nv_bfloat16 g_kh[64 * SEQ * DKDIM];
__device__ __align__(256) __nv_bfloat16 g_kl[64 * SEQ * DKDIM];
__device__ __align__(256) __nv_bfloat16 g_vth[64 * DKDIM * SEQ];
__device__ __align__(256) __nv_bfloat16 g_vtl[64 * DKDIM * SEQ];

// ---------------- helpers ----------------
__device__ __forceinline__ uint32_t smem_u32(const void* p) {
    uint32_t a;
    asm("{ .reg .u64 t; cvta.to.shared.u64 t, %1; cvt.u32.u64 %0, t; }" : "=r"(a) : "l"(p));
    return a;
}
__device__ __forceinline__ void ldm4(uint32_t* r, uint32_t addr) {
    asm volatile("ldmatrix.sync.aligned.m8n8.x4.shared.b16 {%0,%1,%2,%3}, [%4];"
                 : "=r"(r[0]), "=r"(r[1]), "=r"(r[2]), "=r"(r[3]) : "r"(addr));
}
__device__ __forceinline__ void mma16816(float* c, const uint32_t* a, uint32_t b0, uint32_t b1) {
    asm volatile("mma.sync.aligned.m16n8k16.row.col.f32.bf16.bf16.f32 "
                 "{%0,%1,%2,%3}, {%4,%5,%6,%7}, {%8,%9}, {%0,%1,%2,%3};"
                 : "+f"(c[0]), "+f"(c[1]), "+f"(c[2]), "+f"(c[3])
                 : "r"(a[0]), "r"(a[1]), "r"(a[2]), "r"(a[3]), "r"(b0), "r"(b1));
}
__device__ __forceinline__ uint32_t pack_bf16x2(float lo, float hi) {
    uint32_t r;
    asm("cvt.rn.bf16x2.f32 %0, %1, %2;" : "=r"(r) : "f"(hi), "f"(lo));
    return r;
}
__device__ __forceinline__ void split_pair(float x0, float x1, uint32_t& h, uint32_t& l) {
    h = pack_bf16x2(x0, x1);
    __nv_bfloat162 hb = *reinterpret_cast<__nv_bfloat162*>(&h);
    l = pack_bf16x2(x0 - __bfloat162float(hb.x), x1 - __bfloat162float(hb.y));
}
#define CP_ASYNC16(saddr, gaddr) \
    asm volatile("cp.async.ca.shared.global [%0], [%1], 16;" :: "r"(saddr), "l"(gaddr))
#define CP_COMMIT() asm volatile("cp.async.commit_group;" ::: "memory")
#define CP_WAIT1()  asm volatile("cp.async.wait_group 1;" ::: "memory")
#define CP_WAIT0()  asm volatile("cp.async.wait_group 0;" ::: "memory")

// ---------------- LayerNorm -> bf16 hi/lo ----------------
__global__ __launch_bounds__(128) void ln_kernel(const float* __restrict__ x,
                                                 const float* __restrict__ gamma,
                                                 const float* __restrict__ beta) {
    int row = blockIdx.x;
    int tid = threadIdx.x;
    const float4 xv = *(const float4*)(x + (size_t)row * FEAT + tid * 4);
    float s  = xv.x + xv.y + xv.z + xv.w;
    float ss = xv.x * xv.x + xv.y * xv.y + xv.z * xv.z + xv.w * xv.w;
#pragma unroll
    for (int o = 16; o > 0; o >>= 1) {
        s  += __shfl_xor_sync(0xffffffffu, s, o);
        ss += __shfl_xor_sync(0xffffffffu, ss, o);
    }
    __shared__ float ws[4], wss[4];
    if ((tid & 31) == 0) { ws[tid >> 5] = s; wss[tid >> 5] = ss; }
    __syncthreads();
    float st  = ws[0] + ws[1] + ws[2] + ws[3];
    float sst = wss[0] + wss[1] + wss[2] + wss[3];
    float mu   = st * (1.0f / FEAT);
    float var  = sst * (1.0f / FEAT) - mu * mu;
    float rstd = rsqrtf(var + 1e-5f);
    float4 g  = *(const float4*)(gamma + tid * 4);
    float4 be = *(const float4*)(beta + tid * 4);
    float o[4];
    o[0] = (xv.x - mu) * rstd * g.x + be.x;
    o[1] = (xv.y - mu) * rstd * g.y + be.y;
    o[2] = (xv.z - mu) * rstd * g.z + be.z;
    o[3] = (xv.w - mu) * rstd * g.w + be.w;
    size_t off = (size_t)row * FEAT + tid * 4;
#pragma unroll
    for (int i = 0; i < 4; i++) {
        __nv_bfloat16 hi = __float2bfloat16(o[i]);
        g_ah[off + i] = hi;
        g_al[off + i] = __float2bfloat16(o[i] - __bfloat162float(hi));
    }
}

// ---------------- repack fused QKV weights W^T [1536][512] bf16 hi/lo ----------------
__global__ __launch_bounds__(256) void repack_qkv(const float* __restrict__ WQ,
                                                  const float* __restrict__ WK,
                                                  const float* __restrict__ WV) {
    int idx = blockIdx.x * 256 + threadIdx.x;   // n*512 + f
    int n = idx >> 9;
    int f = idx & 511;
    int which = n >> 9;
    int h = (n >> 6) & 7;
    int d = n & 63;
    const float* W = (which == 0) ? WQ : ((which == 1) ? WK : WV);
    float v = W[((size_t)h * FEAT + f) * DKDIM + d];
    __nv_bfloat16 hi = __float2bfloat16(v);
    g_bh[idx] = hi;
    g_bl[idx] = __float2bfloat16(v - __bfloat162float(hi));
}

// ---------------- repack WO^T [512][512] bf16 hi/lo ----------------
__global__ __launch_bounds__(256) void repack_wo(const float* __restrict__ WO) {
    int idx = blockIdx.x * 256 + threadIdx.x;   // n*512 + k
    int n = idx >> 9;
    int k = idx & 511;
    float v = WO[(size_t)k * 512 + n];
    __nv_bfloat16 hi = __float2bfloat16(v);
    g_oh[idx] = hi;
    g_ol[idx] = __float2bfloat16(v - __bfloat162float(hi));
}

// ---------------- mma.sync GEMM core: 3-stage, 32KB/stage, 2 CTAs/SM, 1 sync/chunk ----
// Stage: A-combined [128 rows][128B] (hi cols 0-3, lo cols 4-7, SW128) @0, B-combined @16384.
// K-chunk = 32 bf16 (2 k-steps), 16 chunks over K=512.
#define GSTG 32768
#define GSMEM (3 * GSTG)

__device__ __forceinline__ void stage_load32(uint32_t sb, int stage, int chunk,
                                             const __nv_bfloat16* __restrict__ Ah,
                                             const __nv_bfloat16* __restrict__ Al,
                                             const __nv_bfloat16* __restrict__ Bh,
                                             const __nv_bfloat16* __restrict__ Bl,
                                             int m0, int n0) {
    int tid = threadIdx.x;
    uint32_t base = sb + stage * GSTG;
#pragma unroll
    for (int t = 0; t < 8; t++) {
        int idx = tid + t * 256;
        int mat = idx >> 10;           // 0 = A, 1 = B (constant per t)
        int pos = idx & 1023;
        int row = pos >> 3;
        int cu  = pos & 7;             // 0-3: hi, 4-7: lo
        const __nv_bfloat16* src;
        if (mat == 0)
            src = ((cu < 4) ? Ah : Al) + (size_t)(m0 + row) * FEAT + chunk * 32 + (cu & 3) * 8;
        else
            src = ((cu < 4) ? Bh : Bl) + (size_t)(n0 + row) * FEAT + chunk * 32 + (cu & 3) * 8;
        uint32_t s = base + mat * 16384 + row * 128 + (uint32_t)((cu ^ (row & 7)) << 4);
        CP_ASYNC16(s, src);
    }
    CP_COMMIT();
}

__device__ __forceinline__ void gemm_mma_core(const __nv_bfloat16* __restrict__ Ah,
                                              const __nv_bfloat16* __restrict__ Al,
                                              const __nv_bfloat16* __restrict__ Bh,
                                              const __nv_bfloat16* __restrict__ Bl,
                                              char* smem, float acc[2][8][4]) {
    uint32_t sb = smem_u32(smem);
    int tid = threadIdx.x;
    int wid = tid >> 5, lane = tid & 31;
    int wm = wid & 3, wn = wid >> 2;
    int m0 = blockIdx.y * 128;
    int n0 = blockIdx.x * 128;

#pragma unroll
    for (int mt = 0; mt < 2; mt++)
#pragma unroll
        for (int nt = 0; nt < 8; nt++)
#pragma unroll
            for (int i = 0; i < 4; i++) acc[mt][nt][i] = 0.0f;

    int rA = wm * 32 + (lane & 7) + ((lane >> 3) & 1) * 8;
    int hA = lane >> 4;
    int rB = wn * 64 + (lane & 7) + ((lane >> 4) & 1) * 8;
    int hB = (lane >> 3) & 1;

    stage_load32(sb, 0, 0, Ah, Al, Bh, Bl, m0, n0);
    stage_load32(sb, 1, 1, Ah, Al, Bh, Bl, m0, n0);

    for (int c = 0; c < 16; c++) {
        if (c < 15) { CP_WAIT1(); } else { CP_WAIT0(); }
        __syncthreads();                 // stage c ready for all; compute(c-1) done by all
        if (c < 14)
            stage_load32(sb, (c + 2) % 3, c + 2, Ah, Al, Bh, Bl, m0, n0);
        uint32_t buf = sb + (c % 3) * GSTG;
#pragma unroll
        for (int ks = 0; ks < 2; ks++) {
            uint32_t ah[2][4], al[2][4], bhf[4][4], blf[4][4];
#pragma unroll
            for (int mt = 0; mt < 2; mt++) {
                int row = rA + mt * 16;
                int c16 = ks * 2 + hA;
                uint32_t addr = buf + row * 128 + (uint32_t)(((c16 ^ (row & 7))) << 4);
                ldm4(ah[mt], addr);
                ldm4(al[mt], addr ^ 0x40u);
            }
#pragma unroll
            for (int np = 0; np < 4; np++) {
                int row = rB + np * 16;
                int c16 = ks * 2 + hB;
                uint32_t addr = buf + 16384 + row * 128 + (uint32_t)(((c16 ^ (row & 7))) << 4);
                ldm4(bhf[np], addr);
                ldm4(blf[np], addr ^ 0x40u);
            }
#pragma unroll
            for (int mt = 0; mt < 2; mt++) {
#pragma unroll
                for (int nt = 0; nt < 8; nt++) {
                    int np = nt >> 1, sel = (nt & 1) * 2;
                    mma16816(acc[mt][nt], ah[mt], bhf[np][sel], bhf[np][sel + 1]);
                    mma16816(acc[mt][nt], ah[mt], blf[np][sel], blf[np][sel + 1]);
                    mma16816(acc[mt][nt], al[mt], bhf[np][sel], bhf[np][sel + 1]);
                }
            }
        }
    }
}

// ---------------- QKV GEMM: epilogue -> bf16 hi/lo q,k [s,d]; v transposed [d,s] --------
__global__ __launch_bounds__(256, 2) void gemm_qkv_mma(const float* __restrict__ bq,
                                                       const float* __restrict__ bk,
                                                       const float* __restrict__ bv) {
    extern __shared__ char smem[];
    float acc[2][8][4];
    gemm_mma_core(g_ah, g_al, g_bh, g_bl, smem, acc);

    int tid = threadIdx.x;
    int wid = tid >> 5, lane = tid & 31;
    int wm = wid & 3, wn = wid >> 2;
    int m0 = blockIdx.y * 128, n0 = blockIdx.x * 128;
    int r = lane >> 2, cp2 = (lane & 3) * 2;

#pragma unroll
    for (int nt = 0; nt < 8; nt++) {
        int col = n0 + wn * 64 + nt * 8 + cp2;
        int which = col >> 9, h = (col >> 6) & 7, d = col & 63;
        const float* bias = (which == 0) ? bq : ((which == 1) ? bk : bv);
        float b0v = bias[h * 64 + d], b1v = bias[h * 64 + d + 1];
#pragma unroll
        for (int mt = 0; mt < 2; mt++) {
#pragma unroll
            for (int half = 0; half < 2; half++) {
                int m = m0 + wm * 32 + mt * 16 + r + half * 8;
                int bb = m >> 10, ss = m & 1023;
                int bh = bb * 8 + h;
                float v0 = acc[mt][nt][half * 2 + 0] + b0v;
                float v1 = acc[mt][nt][half * 2 + 1] + b1v;
                __nv_bfloat16 h0 = __float2bfloat16(v0);
                __nv_bfloat16 h1 = __float2bfloat16(v1);
                __nv_bfloat16 l0 = __float2bfloat16(v0 - __bfloat162float(h0));
                __nv_bfloat16 l1 = __float2bfloat16(v1 - __bfloat162float(h1));
                if (which == 2) {
                    size_t vi = ((size_t)bh * 64 + d) * 1024 + ss;
                    g_vth[vi] = h0;  g_vth[vi + 1024] = h1;
                    g_vtl[vi] = l0;  g_vtl[vi + 1024] = l1;
                } else {
                    size_t qi = ((size_t)bh * 1024 + ss) * 64 + d;
                    __nv_bfloat162 hp; hp.x = h0; hp.y = h1;
                    __nv_bfloat162 lp; lp.x = l0; lp.y = l1;
                    if (which == 0) {
                        *(__nv_bfloat162*)(g_qh + qi) = hp;
                        *(__nv_bfloat162*)(g_ql + qi) = lp;
                    } else {
                        *(__nv_bfloat162*)(g_kh + qi) = hp;
                        *(__nv_bfloat162*)(g_kl + qi) = lp;
                    }
                }
            }
        }
    }
}

// ---------------- output GEMM (mma.sync) ----------------
__global__ __launch_bounds__(256, 2) void gemm_out_mma(const float* __restrict__ bO,
                                                       float* __restrict__ out) {
    extern __shared__ char smem[];
    float acc[2][8][4];
    gemm_mma_core(g_zh, g_zl, g_oh, g_ol, smem, acc);

    int tid = threadIdx.x;
    int wid = tid >> 5, lane = tid & 31;
    int wm = wid & 3, wn = wid >> 2;
    int m0 = blockIdx.y * 128, n0 = blockIdx.x * 128;
    int r = lane >> 2, cp2 = (lane & 3) * 2;

#pragma unroll
    for (int nt = 0; nt < 8; nt++) {
        int col = n0 + wn * 64 + nt * 8 + cp2;
        float b0v = bO[col], b1v = bO[col + 1];
#pragma unroll
        for (int mt = 0; mt < 2; mt++) {
            int m = m0 + wm * 32 + mt * 16 + r;
            *(float2*)(out + (size_t)m * 512 + col) =
                make_float2(acc[mt][nt][0] + b0v, acc[mt][nt][1] + b1v);
            *(float2*)(out + (size_t)(m + 8) * 512 + col) =
                make_float2(acc[mt][nt][2] + b0v, acc[mt][nt][3] + b1v);
        }
    }
}

// ---------------- tensor-core flash attention: K-tile 64, 2 CTAs/SM, 1 sync/tile ------
// smem: Q hi/lo 32KB @0; stage s (s=0,1) @32768 + s*32768:
//       K hi @+0, K lo @+8192, VT hi @+16384, VT lo @+24576
#define ASTG 32768
#define AT_SMEM (32768 + 2 * ASTG)

__device__ __forceinline__ void attn_stage_load(uint32_t sb, int stage, int k0,
                                                size_t qkb, int bh) {
    int tid = threadIdx.x;
    uint32_t stb = sb + 32768 + stage * ASTG;
#pragma unroll
    for (int tt = 0; tt < 8; tt++) {
        int idx = tid + tt * 256;
        int mat = idx >> 9;            // 0 Kh, 1 Kl, 2 VTh, 3 VTl (constant per tt)
        int pos = idx & 511;
        int row = pos >> 3, cu = pos & 7;
        const __nv_bfloat16* src;
        if (mat < 2)
            src = (mat ? g_kl : g_kh) + qkb + (size_t)(k0 + row) * 64 + cu * 8;
        else
            src = ((mat == 3) ? g_vtl : g_vth) + ((size_t)bh * 64 + row) * 1024 + k0 + cu * 8;
        CP_ASYNC16(stb + mat * 8192 + row * 128 + (uint32_t)((cu ^ (row & 7)) << 4), src);
    }
    CP_COMMIT();
}

__global__ __launch_bounds__(256, 2) void attn_mma() {
    extern __shared__ char smc[];
    uint32_t sb = smem_u32(smc);
    int tid = threadIdx.x, wid = tid >> 5, lane = tid & 31;
    int bh = blockIdx.y;
    int q0 = blockIdx.x * 128;
    size_t qkb = (size_t)bh * (SEQ * DKDIM);

    int last = q0 + 127;
    int blk_lim = (last < TCUT) ? TCUT : ((last == SEQ - 1) ? SEQ : last);
    int ntiles = (blk_lim + 63) >> 6;

    // ---- issue Q tile (group 0) ----
#pragma unroll
    for (int t = 0; t < 8; t++) {
        int idx = tid + t * 256;
        int mat = idx >> 10;
        int pos = idx & 1023;
        int row = pos >> 3, cu = pos & 7;
        const __nv_bfloat16* src = (mat ? g_ql : g_qh) + qkb + (size_t)(q0 + row) * 64 + cu * 8;
        CP_ASYNC16(sb + mat * 16384 + row * 128 + (uint32_t)((cu ^ (row & 7)) << 4), src);
    }
    CP_COMMIT();

    // ---- issue K/VT stage 0 (group 1) ----
    attn_stage_load(sb, 0, 0, qkb, bh);

    int gr0 = q0 + wid * 16 + (lane >> 2);
    int gr1 = gr0 + 8;
    int lim0 = (gr0 < TCUT) ? TCUT : ((gr0 == SEQ - 1) ? SEQ : gr0);
    int lim1 = (gr1 < TCUT) ? TCUT : ((gr1 == SEQ - 1) ? SEQ : gr1);

    float mr0 = -1e30f, mr1 = -1e30f, lr0 = 0.0f, lr1 = 0.0f;
    float o[8][4];
#pragma unroll
    for (int nt = 0; nt < 8; nt++)
#pragma unroll
        for (int i = 0; i < 4; i++) o[nt][i] = 0.0f;

    CP_WAIT1();      // Q landed
    __syncthreads();

    // ---- loop-invariant Q fragments ----
    uint32_t qf[4][2][4];
    {
        int rqa = wid * 16 + (lane & 7) + ((lane >> 3) & 1) * 8;
        int hA = lane >> 4;
#pragma unroll
        for (int kk = 0; kk < 4; kk++) {
            int c16 = kk * 2 + hA;
            uint32_t addr = sb + rqa * 128 + (uint32_t)(((c16 ^ (rqa & 7))) << 4);
            ldm4(qf[kk][0], addr);
            ldm4(qf[kk][1], addr + 16384);
        }
    }

    int rB = (lane & 7) + ((lane >> 4) & 1) * 8;
    int hB = (lane >> 3) & 1;

    for (int t = 0; t < ntiles; t++) {
        int k0 = t * 64;
        CP_WAIT0();        // stage t landed
        __syncthreads();   // all warps done with buffer (t-1)&1 == (t+1)&1
        if (t + 1 < ntiles)
            attn_stage_load(sb, (t + 1) & 1, (t + 1) * 64, qkb, bh);

        uint32_t stb = sb + 32768 + (t & 1) * ASTG;

        // ---- S = Q K^T (3-term hi/lo): 64 keys -> s[0..7] ----
        float s[8][4];
#pragma unroll
        for (int nt = 0; nt < 8; nt++)
#pragma unroll
            for (int i = 0; i < 4; i++) s[nt][i] = 0.0f;
#pragma unroll
        for (int kk = 0; kk < 4; kk++) {
#pragma unroll
            for (int np = 0; np < 4; np++) {
                int row = rB + np * 16;
                int c16 = kk * 2 + hB;
                uint32_t addr = stb + row * 128 + (uint32_t)(((c16 ^ (row & 7))) << 4);
                uint32_t kbh[4], kbl[4];
                ldm4(kbh, addr);
                ldm4(kbl, addr + 8192);
                mma16816(s[2 * np],     qf[kk][0], kbh[0], kbh[1]);
                mma16816(s[2 * np],     qf[kk][0], kbl[0], kbl[1]);
                mma16816(s[2 * np],     qf[kk][1], kbh[0], kbh[1]);
                mma16816(s[2 * np + 1], qf[kk][0], kbh[2], kbh[3]);
                mma16816(s[2 * np + 1], qf[kk][0], kbl[2], kbl[3]);
                mma16816(s[2 * np + 1], qf[kk][1], kbh[2], kbh[3]);
            }
        }

        // ---- mask + online softmax ----
        float mx0 = -1e30f, mx1 = -1e30f;
#pragma unroll
        for (int nt = 0; nt < 8; nt++) {
            int kb = k0 + nt * 8 + (lane & 3) * 2;
            float v0 = (kb     < lim0) ? s[nt][0] * 0.125f : -1e30f;
            float v1 = (kb + 1 < lim0) ? s[nt][1] * 0.125f : -1e30f;
            float v2 = (kb     < lim1) ? s[nt][2] * 0.125f : -1e30f;
            float v3 = (kb + 1 < lim1) ? s[nt][3] * 0.125f : -1e30f;
            s[nt][0] = v0; s[nt][1] = v1; s[nt][2] = v2; s[nt][3] = v3;
            mx0 = fmaxf(mx0, fmaxf(v0, v1));
            mx1 = fmaxf(mx1, fmaxf(v2, v3));
        }
        mx0 = fmaxf(mx0, __shfl_xor_sync(0xffffffffu, mx0, 1));
        mx0 = fmaxf(mx0, __shfl_xor_sync(0xffffffffu, mx0, 2));
        mx1 = fmaxf(mx1, __shfl_xor_sync(0xffffffffu, mx1, 1));
        mx1 = fmaxf(mx1, __shfl_xor_sync(0xffffffffu, mx1, 2));
        float nm0 = fmaxf(mr0, mx0), nm1 = fmaxf(mr1, mx1);
        float a0 = __expf(mr0 - nm0), a1 = __expf(mr1 - nm1);
        float ls0 = 0.0f, ls1 = 0.0f;
#pragma unroll
        for (int nt = 0; nt < 8; nt++) {
            float p0 = __expf(s[nt][0] - nm0);
            float p1 = __expf(s[nt][1] - nm0);
            float p2 = __expf(s[nt][2] - nm1);
            float p3 = __expf(s[nt][3] - nm1);
            s[nt][0] = p0; s[nt][1] = p1; s[nt][2] = p2; s[nt][3] = p3;
            ls0 += p0 + p1;
            ls1 += p2 + p3;
        }
        ls0 += __shfl_xor_sync(0xffffffffu, ls0, 1);
        ls0 += __shfl_xor_sync(0xffffffffu, ls0, 2);
        ls1 += __shfl_xor_sync(0xffffffffu, ls1, 1);
        ls1 += __shfl_xor_sync(0xffffffffu, ls1, 2);
        lr0 = lr0 * a0 + ls0;
        lr1 = lr1 * a1 + ls1;
        mr0 = nm0; mr1 = nm1;
#pragma unroll
        for (int nt = 0; nt < 8; nt++) {
            o[nt][0] *= a0; o[nt][1] *= a0;
            o[nt][2] *= a1; o[nt][3] *= a1;
        }

        // ---- O += P V (3-term hi/lo): 64 keys = 4 k-steps ----
#pragma unroll
        for (int kk2 = 0; kk2 < 4; kk2++) {
            uint32_t pah[4], pal[4];
            split_pair(s[2 * kk2][0],     s[2 * kk2][1],     pah[0], pal[0]);
            split_pair(s[2 * kk2][2],     s[2 * kk2][3],     pah[1], pal[1]);
            split_pair(s[2 * kk2 + 1][0], s[2 * kk2 + 1][1], pah[2], pal[2]);
            split_pair(s[2 * kk2 + 1][2], s[2 * kk2 + 1][3], pah[3], pal[3]);
            int c16 = kk2 * 2 + hB;
#pragma unroll
            for (int np = 0; np < 4; np++) {
                int row = rB + np * 16;
                uint32_t addr = stb + 16384 + row * 128 +
                                (uint32_t)(((c16 ^ (row & 7))) << 4);
                uint32_t vbh[4], vbl[4];
                ldm4(vbh, addr);
                ldm4(vbl, addr + 8192);
                mma16816(o[2 * np],     pah, vbh[0], vbh[1]);
                mma16816(o[2 * np],     pah, vbl[0], vbl[1]);
                mma16816(o[2 * np],     pal, vbh[0], vbh[1]);
                mma16816(o[2 * np + 1], pah, vbh[2], vbh[3]);
                mma16816(o[2 * np + 1], pah, vbl[2], vbl[3]);
                mma16816(o[2 * np + 1], pal, vbh[2], vbh[3]);
            }
        }
    }

    // ---- epilogue: z hi/lo ----
    float inv0 = 1.0f / lr0, inv1 = 1.0f / lr1;
    int b = bh >> 3, h = bh & 7;
    size_t z0 = (size_t)(b * SEQ + gr0) * FEAT + h * 64;
    size_t z1 = (size_t)(b * SEQ + gr1) * FEAT + h * 64;
#pragma unroll
    for (int nt = 0; nt < 8; nt++) {
        int col = nt * 8 + (lane & 3) * 2;
        float v0 = o[nt][0] * inv0, v1 = o[nt][1] * inv0;
        float v2 = o[nt][2] * inv1, v3 = o[nt][3] * inv1;
        __nv_bfloat16 h0 = __float2bfloat16(v0), h1 = __float2bfloat16(v1);
        __nv_bfloat16 h2 = __float2bfloat16(v2), h3 = __float2bfloat16(v3);
        __nv_bfloat162 hp0; hp0.x = h0; hp0.y = h1;
        __nv_bfloat162 hp1; hp1.x = h2; hp1.y = h3;
        __nv_bfloat162 lp0; lp0.x = __float2bfloat16(v0 - __bfloat162float(h0));
        lp0.y = __float2bfloat16(v1 - __bfloat162float(h1));
        __nv_bfloat162 lp1; lp1.x = __float2bfloat16(v2 - __bfloat162float(h2));
        lp1.y = __float2bfloat16(v3 - __bfloat162float(h3));
        *(__nv_bfloat162*)(g_zh + z0 + col) = hp0;
        *(__nv_bfloat162*)(g_zl + z0 + col) = lp0;
        *(__nv_bfloat162*)(g_zh + z1 + col) = hp1;
        *(__nv_bfloat162*)(g_zl + z1 + col) = lp1;
    }
}

// ---------------- launch ----------------
extern "C" void kernel_launch(void* const* d_in, const int* in_sizes, int n_in,
                              void* d_out, int out_size) {
    const float* x     = (const float*)d_in[0];
    const float* gamma = (const float*)d_in[1];
    const float* beta  = (const float*)d_in[2];
    const float* WQ    = (const float*)d_in[3];
    const float* bq    = (const float*)d_in[4];
    const float* WK    = (const float*)d_in[5];
    const float* bk    = (const float*)d_in[6];
    const float* WV    = (const float*)d_in[7];
    const float* bv    = (const float*)d_in[8];
    const float* WO    = (const float*)d_in[9];
    const float* bO    = (const float*)d_in[10];
    float* out = (float*)d_out;

    (void)in_sizes; (void)n_in; (void)out_size;

    cudaFuncSetAttribute(attn_mma, cudaFuncAttributeMaxDynamicSharedMemorySize, AT_SMEM);
    cudaFuncSetAttribute(gemm_qkv_mma, cudaFuncAttributeMaxDynamicSharedMemorySize, GSMEM);
    cudaFuncSetAttribute(gemm_out_mma, cudaFuncAttributeMaxDynamicSharedMemorySize, GSMEM);

    ln_kernel<<<MTOT, 128>>>(x, gamma, beta);
    repack_qkv<<<(NQKV * FEAT) / 256, 256>>>(WQ, WK, WV);
    repack_wo<<<(FEAT * FEAT) / 256, 256>>>(WO);
    gemm_qkv_mma<<<dim3(NQKV / 128, MTOT / 128), 256, GSMEM>>>(bq, bk, bv);
    attn_mma<<<dim3(SEQ / 128, BATCH * HEADS), 256, AT_SMEM>>>();
    gemm_out_mma<<<dim3(512 / 128, MTOT / 128), 256, GSMEM>>>(bO, out);
}

// round 9
// speedup vs baseline: 1.0234x; 1.0234x over previous
#include <cuda_runtime.h>
#include <cuda_bf16.h>
#include <cstdint>

#define BATCH 8
#define SEQ   1024
#define FEAT  512
#define HEADS 8
#define DKDIM 64
#define TCUT  823
#define MTOT  (BATCH * SEQ)     // 8192
#define NQKV  1536

// ---------------- scratch (device globals; no runtime alloc) ----------------
__device__ __align__(256) __nv_bfloat16 g_ah[MTOT * FEAT];        // xn hi   [m][k]
__device__ __align__(256) __nv_bfloat16 g_al[MTOT * FEAT];        // xn lo
__device__ __align__(256) __nv_bfloat16 g_bh[NQKV * FEAT];        // W^T hi  [n][k]
__device__ __align__(256) __nv_bfloat16 g_bl[NQKV * FEAT];        // W^T lo
__device__ __align__(256) __nv_bfloat16 g_zh[MTOT * FEAT];        // z hi    [m][k]
__device__ __align__(256) __nv_bfloat16 g_zl[MTOT * FEAT];        // z lo
__device__ __align__(256) __nv_bfloat16 g_oh[FEAT * FEAT];        // WO^T hi [n][k]
__device__ __align__(256) __nv_bfloat16 g_ol[FEAT * FEAT];        // WO^T lo
// q,k: [b,h,s,d]; v transposed: [b,h,d,s]; all bf16 hi/lo
__device__ __align__(256) __nv_bfloat16 g_qh[64 * SEQ * DKDIM];
__device__ __align__(256) __nv_bfloat16 g_ql[64 * SEQ * DKDIM];
__device__ __align__(256) __nv_bfloat16 g_kh[64 * SEQ * DKDIM];
__device__ __align__(256) __nv_bfloat16 g_kl[64 * SEQ * DKDIM];
__device__ __align__(256) __nv_bfloat16 g_vth[64 * DKDIM * SEQ];
__device__ __align__(256) __nv_bfloat16 g_vtl[64 * DKDIM * SEQ];

// ---------------- helpers ----------------
__device__ __forceinline__ uint32_t smem_u32(const void* p) {
    uint32_t a;
    asm("{ .reg .u64 t; cvta.to.shared.u64 t, %1; cvt.u32.u64 %0, t; }" : "=r"(a) : "l"(p));
    return a;
}
__device__ __forceinline__ void ldm4(uint32_t* r, uint32_t addr) {
    asm volatile("ldmatrix.sync.aligned.m8n8.x4.shared.b16 {%0,%1,%2,%3}, [%4];"
                 : "=r"(r[0]), "=r"(r[1]), "=r"(r[2]), "=r"(r[3]) : "r"(addr));
}
__device__ __forceinline__ void mma16816(float* c, const uint32_t* a, uint32_t b0, uint32_t b1) {
    asm volatile("mma.sync.aligned.m16n8k16.row.col.f32.bf16.bf16.f32 "
                 "{%0,%1,%2,%3}, {%4,%5,%6,%7}, {%8,%9}, {%0,%1,%2,%3};"
                 : "+f"(c[0]), "+f"(c[1]), "+f"(c[2]), "+f"(c[3])
                 : "r"(a[0]), "r"(a[1]), "r"(a[2]), "r"(a[3]), "r"(b0), "r"(b1));
}
__device__ __forceinline__ uint32_t pack_bf16x2(float lo, float hi) {
    uint32_t r;
    asm("cvt.rn.bf16x2.f32 %0, %1, %2;" : "=r"(r) : "f"(hi), "f"(lo));
    return r;
}
__device__ __forceinline__ void split_pair(float x0, float x1, uint32_t& h, uint32_t& l) {
    h = pack_bf16x2(x0, x1);
    __nv_bfloat162 hb = *reinterpret_cast<__nv_bfloat162*>(&h);
    l = pack_bf16x2(x0 - __bfloat162float(hb.x), x1 - __bfloat162float(hb.y));
}
#define CP_ASYNC16(saddr, gaddr) \
    asm volatile("cp.async.ca.shared.global [%0], [%1], 16;" :: "r"(saddr), "l"(gaddr))
#define CP_COMMIT() asm volatile("cp.async.commit_group;" ::: "memory")
#define CP_WAIT1()  asm volatile("cp.async.wait_group 1;" ::: "memory")
#define CP_WAIT0()  asm volatile("cp.async.wait_group 0;" ::: "memory")

// ---------------- LayerNorm -> bf16 hi/lo ----------------
__global__ __launch_bounds__(128) void ln_kernel(const float* __restrict__ x,
                                                 const float* __restrict__ gamma,
                                                 const float* __restrict__ beta) {
    int row = blockIdx.x;
    int tid = threadIdx.x;
    const float4 xv = *(const float4*)(x + (size_t)row * FEAT + tid * 4);
    float s  = xv.x + xv.y + xv.z + xv.w;
    float ss = xv.x * xv.x + xv.y * xv.y + xv.z * xv.z + xv.w * xv.w;
#pragma unroll
    for (int o = 16; o > 0; o >>= 1) {
        s  += __shfl_xor_sync(0xffffffffu, s, o);
        ss += __shfl_xor_sync(0xffffffffu, ss, o);
    }
    __shared__ float ws[4], wss[4];
    if ((tid & 31) == 0) { ws[tid >> 5] = s; wss[tid >> 5] = ss; }
    __syncthreads();
    float st  = ws[0] + ws[1] + ws[2] + ws[3];
    float sst = wss[0] + wss[1] + wss[2] + wss[3];
    float mu   = st * (1.0f / FEAT);
    float var  = sst * (1.0f / FEAT) - mu * mu;
    float rstd = rsqrtf(var + 1e-5f);
    float4 g  = *(const float4*)(gamma + tid * 4);
    float4 be = *(const float4*)(beta + tid * 4);
    float o[4];
    o[0] = (xv.x - mu) * rstd * g.x + be.x;
    o[1] = (xv.y - mu) * rstd * g.y + be.y;
    o[2] = (xv.z - mu) * rstd * g.z + be.z;
    o[3] = (xv.w - mu) * rstd * g.w + be.w;
    size_t off = (size_t)row * FEAT + tid * 4;
#pragma unroll
    for (int i = 0; i < 4; i++) {
        __nv_bfloat16 hi = __float2bfloat16(o[i]);
        g_ah[off + i] = hi;
        g_al[off + i] = __float2bfloat16(o[i] - __bfloat162float(hi));
    }
}

// ---------------- repack fused QKV weights W^T [1536][512] bf16 hi/lo ----------------
__global__ __launch_bounds__(256) void repack_qkv(const float* __restrict__ WQ,
                                                  const float* __restrict__ WK,
                                                  const float* __restrict__ WV) {
    int idx = blockIdx.x * 256 + threadIdx.x;   // n*512 + f
    int n = idx >> 9;
    int f = idx & 511;
    int which = n >> 9;
    int h = (n >> 6) & 7;
    int d = n & 63;
    const float* W = (which == 0) ? WQ : ((which == 1) ? WK : WV);
    float v = W[((size_t)h * FEAT + f) * DKDIM + d];
    __nv_bfloat16 hi = __float2bfloat16(v);
    g_bh[idx] = hi;
    g_bl[idx] = __float2bfloat16(v - __bfloat162float(hi));
}

// ---------------- repack WO^T [512][512] bf16 hi/lo ----------------
__global__ __launch_bounds__(256) void repack_wo(const float* __restrict__ WO) {
    int idx = blockIdx.x * 256 + threadIdx.x;   // n*512 + k
    int n = idx >> 9;
    int k = idx & 511;
    float v = WO[(size_t)k * 512 + n];
    __nv_bfloat16 hi = __float2bfloat16(v);
    g_oh[idx] = hi;
    g_ol[idx] = __float2bfloat16(v - __bfloat162float(hi));
}

// ---------------- mma.sync GEMM core (round-5 layout, 3-stage single-sync) ----------
// Stage (64KB): Ah [128][64]bf16 @0, Al @16384, Bh @32768, Bl @49152; SW128-swizzled.
// K-chunk = 64 bf16 (4 k-steps), 8 chunks over K=512.
#define GSTG 65536
#define GSMEM (3 * GSTG)

__device__ __forceinline__ void stage_load(uint32_t sb, int stage, int chunk,
                                           const __nv_bfloat16* __restrict__ Ah,
                                           const __nv_bfloat16* __restrict__ Al,
                                           const __nv_bfloat16* __restrict__ Bh,
                                           const __nv_bfloat16* __restrict__ Bl,
                                           int m0, int n0) {
    int tid = threadIdx.x;
    uint32_t base = sb + stage * GSTG;
#pragma unroll
    for (int t = 0; t < 16; t++) {
        int idx = tid + t * 256;
        int mat = idx >> 10;          // constant per t
        int pos = idx & 1023;
        int row = pos >> 3;
        int cu  = pos & 7;
        const __nv_bfloat16* src =
            (mat == 0) ? Ah + (size_t)(m0 + row) * FEAT :
            (mat == 1) ? Al + (size_t)(m0 + row) * FEAT :
            (mat == 2) ? Bh + (size_t)(n0 + row) * FEAT :
                         Bl + (size_t)(n0 + row) * FEAT;
        const __nv_bfloat16* g = src + chunk * 64 + cu * 8;
        uint32_t s = base + mat * 16384 + row * 128 + (uint32_t)((cu ^ (row & 7)) << 4);
        CP_ASYNC16(s, g);
    }
    CP_COMMIT();
}

__device__ __forceinline__ void gemm_mma_core(const __nv_bfloat16* __restrict__ Ah,
                                              const __nv_bfloat16* __restrict__ Al,
                                              const __nv_bfloat16* __restrict__ Bh,
                                              const __nv_bfloat16* __restrict__ Bl,
                                              char* smem, float acc[2][8][4]) {
    uint32_t sb = smem_u32(smem);
    int tid = threadIdx.x;
    int wid = tid >> 5, lane = tid & 31;
    int wm = wid & 3, wn = wid >> 2;
    int m0 = blockIdx.y * 128;
    int n0 = blockIdx.x * 128;

#pragma unroll
    for (int mt = 0; mt < 2; mt++)
#pragma unroll
        for (int nt = 0; nt < 8; nt++)
#pragma unroll
            for (int i = 0; i < 4; i++) acc[mt][nt][i] = 0.0f;

    int rA = wm * 32 + (lane & 7) + ((lane >> 3) & 1) * 8;
    int hA = lane >> 4;
    int rB = wn * 64 + (lane & 7) + ((lane >> 4) & 1) * 8;
    int hB = (lane >> 3) & 1;

    stage_load(sb, 0, 0, Ah, Al, Bh, Bl, m0, n0);
    stage_load(sb, 1, 1, Ah, Al, Bh, Bl, m0, n0);

    for (int c = 0; c < 8; c++) {
        if (c < 7) { CP_WAIT1(); } else { CP_WAIT0(); }
        __syncthreads();      // stage c landed for all; everyone done computing c-1
        if (c < 6)
            stage_load(sb, (c + 2) % 3, c + 2, Ah, Al, Bh, Bl, m0, n0);
        uint32_t buf = sb + (c % 3) * GSTG;
#pragma unroll
        for (int ks = 0; ks < 4; ks++) {
            uint32_t ah[2][4], al[2][4], bhf[4][4], blf[4][4];
#pragma unroll
            for (int mt = 0; mt < 2; mt++) {
                int row = rA + mt * 16;
                int c16 = ks * 2 + hA;
                uint32_t addr = buf + row * 128 + (uint32_t)(((c16 ^ (row & 7))) << 4);
                ldm4(ah[mt], addr);
                ldm4(al[mt], addr + 16384);
            }
#pragma unroll
            for (int np = 0; np < 4; np++) {
                int row = rB + np * 16;
                int c16 = ks * 2 + hB;
                uint32_t addr = buf + 32768 + row * 128 + (uint32_t)(((c16 ^ (row & 7))) << 4);
                ldm4(bhf[np], addr);
                ldm4(blf[np], addr + 16384);
            }
#pragma unroll
            for (int mt = 0; mt < 2; mt++) {
#pragma unroll
                for (int nt = 0; nt < 8; nt++) {
                    int np = nt >> 1, sel = (nt & 1) * 2;
                    mma16816(acc[mt][nt], ah[mt], bhf[np][sel], bhf[np][sel + 1]);
                    mma16816(acc[mt][nt], ah[mt], blf[np][sel], blf[np][sel + 1]);
                    mma16816(acc[mt][nt], al[mt], bhf[np][sel], bhf[np][sel + 1]);
                }
            }
        }
    }
}

// ---------------- QKV GEMM: epilogue -> bf16 hi/lo q,k [s,d]; v transposed [d,s] --------
__global__ __launch_bounds__(256) void gemm_qkv_mma(const float* __restrict__ bq,
                                                    const float* __restrict__ bk,
                                                    const float* __restrict__ bv) {
    extern __shared__ char smem[];
    float acc[2][8][4];
    gemm_mma_core(g_ah, g_al, g_bh, g_bl, smem, acc);

    int tid = threadIdx.x;
    int wid = tid >> 5, lane = tid & 31;
    int wm = wid & 3, wn = wid >> 2;
    int m0 = blockIdx.y * 128, n0 = blockIdx.x * 128;
    int r = lane >> 2, cp2 = (lane & 3) * 2;

#pragma unroll
    for (int nt = 0; nt < 8; nt++) {
        int col = n0 + wn * 64 + nt * 8 + cp2;
        int which = col >> 9, h = (col >> 6) & 7, d = col & 63;
        const float* bias = (which == 0) ? bq : ((which == 1) ? bk : bv);
        float b0v = bias[h * 64 + d], b1v = bias[h * 64 + d + 1];
#pragma unroll
        for (int mt = 0; mt < 2; mt++) {
#pragma unroll
            for (int half = 0; half < 2; half++) {
                int m = m0 + wm * 32 + mt * 16 + r + half * 8;
                int bb = m >> 10, ss = m & 1023;
                int bh = bb * 8 + h;
                float v0 = acc[mt][nt][half * 2 + 0] + b0v;
                float v1 = acc[mt][nt][half * 2 + 1] + b1v;
                __nv_bfloat16 h0 = __float2bfloat16(v0);
                __nv_bfloat16 h1 = __float2bfloat16(v1);
                __nv_bfloat16 l0 = __float2bfloat16(v0 - __bfloat162float(h0));
                __nv_bfloat16 l1 = __float2bfloat16(v1 - __bfloat162float(h1));
                if (which == 2) {
                    size_t vi = ((size_t)bh * 64 + d) * 1024 + ss;
                    g_vth[vi] = h0;  g_vth[vi + 1024] = h1;
                    g_vtl[vi] = l0;  g_vtl[vi + 1024] = l1;
                } else {
                    size_t qi = ((size_t)bh * 1024 + ss) * 64 + d;
                    __nv_bfloat162 hp; hp.x = h0; hp.y = h1;
                    __nv_bfloat162 lp; lp.x = l0; lp.y = l1;
                    if (which == 0) {
                        *(__nv_bfloat162*)(g_qh + qi) = hp;
                        *(__nv_bfloat162*)(g_ql + qi) = lp;
                    } else {
                        *(__nv_bfloat162*)(g_kh + qi) = hp;
                        *(__nv_bfloat162*)(g_kl + qi) = lp;
                    }
                }
            }
        }
    }
}

// ---------------- output GEMM (mma.sync) ----------------
__global__ __launch_bounds__(256) void gemm_out_mma(const float* __restrict__ bO,
                                                    float* __restrict__ out) {
    extern __shared__ char smem[];
    float acc[2][8][4];
    gemm_mma_core(g_zh, g_zl, g_oh, g_ol, smem, acc);

    int tid = threadIdx.x;
    int wid = tid >> 5, lane = tid & 31;
    int wm = wid & 3, wn = wid >> 2;
    int m0 = blockIdx.y * 128, n0 = blockIdx.x * 128;
    int r = lane >> 2, cp2 = (lane & 3) * 2;

#pragma unroll
    for (int nt = 0; nt < 8; nt++) {
        int col = n0 + wn * 64 + nt * 8 + cp2;
        float b0v = bO[col], b1v = bO[col + 1];
#pragma unroll
        for (int mt = 0; mt < 2; mt++) {
            int m = m0 + wm * 32 + mt * 16 + r;
            *(float2*)(out + (size_t)m * 512 + col) =
                make_float2(acc[mt][nt][0] + b0v, acc[mt][nt][1] + b1v);
            *(float2*)(out + (size_t)(m + 8) * 512 + col) =
                make_float2(acc[mt][nt][2] + b0v, acc[mt][nt][3] + b1v);
        }
    }
}

// ---------------- tensor-core flash attention (round-7 layout, single-sync loop) -------
// smem: Q hi/lo 32KB @0; stage s (s=0,1) @32768 + s*65536:
//       K hi @+0, K lo @+16384, VT hi @+32768, VT lo @+49152
#define AT_SMEM (32768 + 2 * 65536)

__device__ __forceinline__ void attn_stage_load(uint32_t sb, int stage, int k0,
                                                size_t qkb, int bh) {
    int tid = threadIdx.x;
    uint32_t stb = sb + 32768 + stage * 65536;
#pragma unroll
    for (int tt = 0; tt < 8; tt++) {
        int idx = tid + tt * 256;
        int mat = idx >> 10;
        int pos = idx & 1023;
        int row = pos >> 3, cu = pos & 7;
        const __nv_bfloat16* src = (mat ? g_kl : g_kh) + qkb + (size_t)(k0 + row) * 64 + cu * 8;
        CP_ASYNC16(stb + mat * 16384 + row * 128 + (uint32_t)((cu ^ (row & 7)) << 4), src);
    }
#pragma unroll
    for (int tt = 0; tt < 8; tt++) {
        int idx = tid + tt * 256;
        int mat = idx >> 10;
        int pos = idx & 1023;
        int half = pos >> 9;
        int d = (pos >> 3) & 63, cu = pos & 7;
        const __nv_bfloat16* src = (mat ? g_vtl : g_vth) +
            ((size_t)bh * 64 + d) * 1024 + k0 + half * 64 + cu * 8;
        CP_ASYNC16(stb + 32768 + mat * 16384 + half * 8192 + d * 128 +
                   (uint32_t)((cu ^ (d & 7)) << 4), src);
    }
    CP_COMMIT();
}

__global__ __launch_bounds__(256, 1) void attn_mma() {
    extern __shared__ char smc[];
    uint32_t sb = smem_u32(smc);
    int tid = threadIdx.x, wid = tid >> 5, lane = tid & 31;
    int bh = blockIdx.y;
    int q0 = blockIdx.x * 128;
    size_t qkb = (size_t)bh * (SEQ * DKDIM);

    int last = q0 + 127;
    int blk_lim = (last < TCUT) ? TCUT : ((last == SEQ - 1) ? SEQ : last);
    int ntiles = (blk_lim + 127) >> 7;

    // ---- prologue: Q tile + stage 0, one wait ----
#pragma unroll
    for (int t = 0; t < 8; t++) {
        int idx = tid + t * 256;
        int mat = idx >> 10;
        int pos = idx & 1023;
        int row = pos >> 3, cu = pos & 7;
        const __nv_bfloat16* src = (mat ? g_ql : g_qh) + qkb + (size_t)(q0 + row) * 64 + cu * 8;
        CP_ASYNC16(sb + mat * 16384 + row * 128 + (uint32_t)((cu ^ (row & 7)) << 4), src);
    }
    CP_COMMIT();
    attn_stage_load(sb, 0, 0, qkb, bh);

    int gr0 = q0 + wid * 16 + (lane >> 2);
    int gr1 = gr0 + 8;
    int lim0 = (gr0 < TCUT) ? TCUT : ((gr0 == SEQ - 1) ? SEQ : gr0);
    int lim1 = (gr1 < TCUT) ? TCUT : ((gr1 == SEQ - 1) ? SEQ : gr1);

    float mr0 = -1e30f, mr1 = -1e30f, lr0 = 0.0f, lr1 = 0.0f;
    float o[8][4];
#pragma unroll
    for (int nt = 0; nt < 8; nt++)
#pragma unroll
        for (int i = 0; i < 4; i++) o[nt][i] = 0.0f;

    CP_WAIT0();     // Q + stage 0 landed
    __syncthreads();

    // ---- loop-invariant Q fragments ----
    uint32_t qf[4][2][4];
    {
        int rqa = wid * 16 + (lane & 7) + ((lane >> 3) & 1) * 8;
        int hA = lane >> 4;
#pragma unroll
        for (int kk = 0; kk < 4; kk++) {
            int c16 = kk * 2 + hA;
            uint32_t addr = sb + rqa * 128 + (uint32_t)(((c16 ^ (rqa & 7))) << 4);
            ldm4(qf[kk][0], addr);
            ldm4(qf[kk][1], addr + 16384);
        }
    }

    int rB = (lane & 7) + ((lane >> 4) & 1) * 8;
    int hB = (lane >> 3) & 1;

    for (int t = 0; t < ntiles; t++) {
        int k0 = t * 128;
        if (t > 0) {
            CP_WAIT0();      // stage t landed
            __syncthreads(); // all warps done computing stage t-1
        }
        if (t + 1 < ntiles)
            attn_stage_load(sb, (t + 1) & 1, (t + 1) * 128, qkb, bh);

        uint32_t stb = sb + 32768 + (t & 1) * 65536;

        // ---- S = Q K^T (3-term hi/lo) ----
        float s[16][4];
#pragma unroll
        for (int nt = 0; nt < 16; nt++)
#pragma unroll
            for (int i = 0; i < 4; i++) s[nt][i] = 0.0f;
#pragma unroll
        for (int kk = 0; kk < 4; kk++) {
#pragma unroll
            for (int np = 0; np < 8; np++) {
                int row = rB + np * 16;
                int c16 = kk * 2 + hB;
                uint32_t addr = stb + row * 128 + (uint32_t)(((c16 ^ (row & 7))) << 4);
                uint32_t kbh[4], kbl[4];
                ldm4(kbh, addr);
                ldm4(kbl, addr + 16384);
                mma16816(s[2 * np],     qf[kk][0], kbh[0], kbh[1]);
                mma16816(s[2 * np],     qf[kk][0], kbl[0], kbl[1]);
                mma16816(s[2 * np],     qf[kk][1], kbh[0], kbh[1]);
                mma16816(s[2 * np + 1], qf[kk][0], kbh[2], kbh[3]);
                mma16816(s[2 * np + 1], qf[kk][0], kbl[2], kbl[3]);
                mma16816(s[2 * np + 1], qf[kk][1], kbh[2], kbh[3]);
            }
        }

        // ---- mask + online softmax ----
        float mx0 = -1e30f, mx1 = -1e30f;
#pragma unroll
        for (int nt = 0; nt < 16; nt++) {
            int kb = k0 + nt * 8 + (lane & 3) * 2;
            float v0 = (kb     < lim0) ? s[nt][0] * 0.125f : -1e30f;
            float v1 = (kb + 1 < lim0) ? s[nt][1] * 0.125f : -1e30f;
            float v2 = (kb     < lim1) ? s[nt][2] * 0.125f : -1e30f;
            float v3 = (kb + 1 < lim1) ? s[nt][3] * 0.125f : -1e30f;
            s[nt][0] = v0; s[nt][1] = v1; s[nt][2] = v2; s[nt][3] = v3;
            mx0 = fmaxf(mx0, fmaxf(v0, v1));
            mx1 = fmaxf(mx1, fmaxf(v2, v3));
        }
        mx0 = fmaxf(mx0, __shfl_xor_sync(0xffffffffu, mx0, 1));
        mx0 = fmaxf(mx0, __shfl_xor_sync(0xffffffffu, mx0, 2));
        mx1 = fmaxf(mx1, __shfl_xor_sync(0xffffffffu, mx1, 1));
        mx1 = fmaxf(mx1, __shfl_xor_sync(0xffffffffu, mx1, 2));
        float nm0 = fmaxf(mr0, mx0), nm1 = fmaxf(mr1, mx1);
        float a0 = __expf(mr0 - nm0), a1 = __expf(mr1 - nm1);
        float ls0 = 0.0f, ls1 = 0.0f;
#pragma unroll
        for (int nt = 0; nt < 16; nt++) {
            float p0 = __expf(s[nt][0] - nm0);
            float p1 = __expf(s[nt][1] - nm0);
            float p2 = __expf(s[nt][2] - nm1);
            float p3 = __expf(s[nt][3] - nm1);
            s[nt][0] = p0; s[nt][1] = p1; s[nt][2] = p2; s[nt][3] = p3;
            ls0 += p0 + p1;
            ls1 += p2 + p3;
        }
        ls0 += __shfl_xor_sync(0xffffffffu, ls0, 1);
        ls0 += __shfl_xor_sync(0xffffffffu, ls0, 2);
        ls1 += __shfl_xor_sync(0xffffffffu, ls1, 1);
        ls1 += __shfl_xor_sync(0xffffffffu, ls1, 2);
        lr0 = lr0 * a0 + ls0;
        lr1 = lr1 * a1 + ls1;
        mr0 = nm0; mr1 = nm1;
#pragma unroll
        for (int nt = 0; nt < 8; nt++) {
            o[nt][0] *= a0; o[nt][1] *= a0;
            o[nt][2] *= a1; o[nt][3] *= a1;
        }

        // ---- O += P V (3-term hi/lo) ----
#pragma unroll
        for (int kk2 = 0; kk2 < 8; kk2++) {
            uint32_t pah[4], pal[4];
            split_pair(s[2 * kk2][0],     s[2 * kk2][1],     pah[0], pal[0]);
            split_pair(s[2 * kk2][2],     s[2 * kk2][3],     pah[1], pal[1]);
            split_pair(s[2 * kk2 + 1][0], s[2 * kk2 + 1][1], pah[2], pal[2]);
            split_pair(s[2 * kk2 + 1][2], s[2 * kk2 + 1][3], pah[3], pal[3]);
            int half = kk2 >> 2;
            int c16 = (kk2 & 3) * 2 + hB;
#pragma unroll
            for (int np = 0; np < 4; np++) {
                int row = rB + np * 16;
                uint32_t addr = stb + 32768 + half * 8192 + row * 128 +
                                (uint32_t)(((c16 ^ (row & 7))) << 4);
                uint32_t vbh[4], vbl[4];
                ldm4(vbh, addr);
                ldm4(vbl, addr + 16384);
                mma16816(o[2 * np],     pah, vbh[0], vbh[1]);
                mma16816(o[2 * np],     pah, vbl[0], vbl[1]);
                mma16816(o[2 * np],     pal, vbh[0], vbh[1]);
                mma16816(o[2 * np + 1], pah, vbh[2], vbh[3]);
                mma16816(o[2 * np + 1], pah, vbl[2], vbl[3]);
                mma16816(o[2 * np + 1], pal, vbh[2], vbh[3]);
            }
        }
    }

    // ---- epilogue: z hi/lo ----
    float inv0 = 1.0f / lr0, inv1 = 1.0f / lr1;
    int b = bh >> 3, h = bh & 7;
    size_t z0 = (size_t)(b * SEQ + gr0) * FEAT + h * 64;
    size_t z1 = (size_t)(b * SEQ + gr1) * FEAT + h * 64;
#pragma unroll
    for (int nt = 0; nt < 8; nt++) {
        int col = nt * 8 + (lane & 3) * 2;
        float v0 = o[nt][0] * inv0, v1 = o[nt][1] * inv0;
        float v2 = o[nt][2] * inv1, v3 = o[nt][3] * inv1;
        __nv_bfloat16 h0 = __float2bfloat16(v0), h1 = __float2bfloat16(v1);
        __nv_bfloat16 h2 = __float2bfloat16(v2), h3 = __float2bfloat16(v3);
        __nv_bfloat162 hp0; hp0.x = h0; hp0.y = h1;
        __nv_bfloat162 hp1; hp1.x = h2; hp1.y = h3;
        __nv_bfloat162 lp0; lp0.x = __float2bfloat16(v0 - __bfloat162float(h0));
        lp0.y = __float2bfloat16(v1 - __bfloat162float(h1));
        __nv_bfloat162 lp1; lp1.x = __float2bfloat16(v2 - __bfloat162float(h2));
        lp1.y = __float2bfloat16(v3 - __bfloat162float(h3));
        *(__nv_bfloat162*)(g_zh + z0 + col) = hp0;
        *(__nv_bfloat162*)(g_zl + z0 + col) = lp0;
        *(__nv_bfloat162*)(g_zh + z1 + col) = hp1;
        *(__nv_bfloat162*)(g_zl + z1 + col) = lp1;
    }
}

// ---------------- launch ----------------
extern "C" void kernel_launch(void* const* d_in, const int* in_sizes, int n_in,
                              void* d_out, int out_size) {
    const float* x     = (const float*)d_in[0];
    const float* gamma = (const float*)d_in[1];
    const float* beta  = (const float*)d_in[2];
    const float* WQ    = (const float*)d_in[3];
    const float* bq    = (const float*)d_in[4];
    const float* WK    = (const float*)d_in[5];
    const float* bk    = (const float*)d_in[6];
    const float* WV    = (const float*)d_in[7];
    const float* bv    = (const float*)d_in[8];
    const float* WO    = (const float*)d_in[9];
    const float* bO    = (const float*)d_in[10];
    float* out = (float*)d_out;

    (void)in_sizes; (void)n_in; (void)out_size;

    cudaFuncSetAttribute(attn_mma, cudaFuncAttributeMaxDynamicSharedMemorySize, AT_SMEM);
    cudaFuncSetAttribute(gemm_qkv_mma, cudaFuncAttributeMaxDynamicSharedMemorySize, GSMEM);
    cudaFuncSetAttribute(gemm_out_mma, cudaFuncAttributeMaxDynamicSharedMemorySize, GSMEM);

    ln_kernel<<<MTOT, 128>>>(x, gamma, beta);
    repack_qkv<<<(NQKV * FEAT) / 256, 256>>>(WQ, WK, WV);
    repack_wo<<<(FEAT * FEAT) / 256, 256>>>(WO);
    gemm_qkv_mma<<<dim3(NQKV / 128, MTOT / 128), 256, GSMEM>>>(bq, bk, bv);
    attn_mma<<<dim3(SEQ / 128, BATCH * HEADS), 256, AT_SMEM>>>();
    gemm_out_mma<<<dim3(512 / 128, MTOT / 128), 256, GSMEM>>>(bO, out);
}

// round 10
// speedup vs baseline: 1.0298x; 1.0063x over previous
#include <cuda_runtime.h>
#include <cuda_bf16.h>
#include <cstdint>

#define BATCH 8
#define SEQ   1024
#define FEAT  512
#define HEADS 8
#define DKDIM 64
#define TCUT  823
#define MTOT  (BATCH * SEQ)     // 8192
#define NQKV  1536

// ---------------- scratch (device globals; no runtime alloc) ----------------
__device__ __align__(256) __nv_bfloat16 g_ah[MTOT * FEAT];        // xn hi   [m][k]
__device__ __align__(256) __nv_bfloat16 g_al[MTOT * FEAT];        // xn lo
__device__ __align__(256) __nv_bfloat16 g_bh[NQKV * FEAT];        // W^T hi  [n][k]
__device__ __align__(256) __nv_bfloat16 g_bl[NQKV * FEAT];        // W^T lo
__device__ __align__(256) __nv_bfloat16 g_zh[MTOT * FEAT];        // z hi    [m][k]
__device__ __align__(256) __nv_bfloat16 g_zl[MTOT * FEAT];        // z lo
__device__ __align__(256) __nv_bfloat16 g_oh[FEAT * FEAT];        // WO^T hi [n][k]
__device__ __align__(256) __nv_bfloat16 g_ol[FEAT * FEAT];        // WO^T lo
// q,k: [b,h,s,d]; v transposed: [b,h,d,s]; all bf16 hi/lo
__device__ __align__(256) __nv_bfloat16 g_qh[64 * SEQ * DKDIM];
__device__ __align__(256) __nv_bfloat16 g_ql[64 * SEQ * DKDIM];
__device__ __align__(256) __nv_bfloat16 g_kh[64 * SEQ * DKDIM];
__device__ __align__(256) __nv_bfloat16 g_kl[64 * SEQ * DKDIM];
__device__ __align__(256) __nv_bfloat16 g_vth[64 * DKDIM * SEQ];
__device__ __align__(256) __nv_bfloat16 g_vtl[64 * DKDIM * SEQ];

// ---------------- helpers ----------------
__device__ __forceinline__ uint32_t smem_u32(const void* p) {
    uint32_t a;
    asm("{ .reg .u64 t; cvta.to.shared.u64 t, %1; cvt.u32.u64 %0, t; }" : "=r"(a) : "l"(p));
    return a;
}
__device__ __forceinline__ void ldm4(uint32_t* r, uint32_t addr) {
    asm volatile("ldmatrix.sync.aligned.m8n8.x4.shared.b16 {%0,%1,%2,%3}, [%4];"
                 : "=r"(r[0]), "=r"(r[1]), "=r"(r[2]), "=r"(r[3]) : "r"(addr));
}
__device__ __forceinline__ void mma16816(float* c, const uint32_t* a, uint32_t b0, uint32_t b1) {
    asm volatile("mma.sync.aligned.m16n8k16.row.col.f32.bf16.bf16.f32 "
                 "{%0,%1,%2,%3}, {%4,%5,%6,%7}, {%8,%9}, {%0,%1,%2,%3};"
                 : "+f"(c[0]), "+f"(c[1]), "+f"(c[2]), "+f"(c[3])
                 : "r"(a[0]), "r"(a[1]), "r"(a[2]), "r"(a[3]), "r"(b0), "r"(b1));
}
__device__ __forceinline__ uint32_t pack_bf16x2(float lo, float hi) {
    uint32_t r;
    asm("cvt.rn.bf16x2.f32 %0, %1, %2;" : "=r"(r) : "f"(hi), "f"(lo));
    return r;
}
__device__ __forceinline__ void split_pair(float x0, float x1, uint32_t& h, uint32_t& l) {
    h = pack_bf16x2(x0, x1);
    __nv_bfloat162 hb = *reinterpret_cast<__nv_bfloat162*>(&h);
    l = pack_bf16x2(x0 - __bfloat162float(hb.x), x1 - __bfloat162float(hb.y));
}
#define CP_ASYNC16(saddr, gaddr) \
    asm volatile("cp.async.ca.shared.global [%0], [%1], 16;" :: "r"(saddr), "l"(gaddr))
#define CP_COMMIT() asm volatile("cp.async.commit_group;" ::: "memory")
#define CP_WAIT1()  asm volatile("cp.async.wait_group 1;" ::: "memory")
#define CP_WAIT0()  asm volatile("cp.async.wait_group 0;" ::: "memory")

// ---------------- LayerNorm -> bf16 hi/lo ----------------
__global__ __launch_bounds__(128) void ln_kernel(const float* __restrict__ x,
                                                 const float* __restrict__ gamma,
                                                 const float* __restrict__ beta) {
    int row = blockIdx.x;
    int tid = threadIdx.x;
    const float4 xv = *(const float4*)(x + (size_t)row * FEAT + tid * 4);
    float s  = xv.x + xv.y + xv.z + xv.w;
    float ss = xv.x * xv.x + xv.y * xv.y + xv.z * xv.z + xv.w * xv.w;
#pragma unroll
    for (int o = 16; o > 0; o >>= 1) {
        s  += __shfl_xor_sync(0xffffffffu, s, o);
        ss += __shfl_xor_sync(0xffffffffu, ss, o);
    }
    __shared__ float ws[4], wss[4];
    if ((tid & 31) == 0) { ws[tid >> 5] = s; wss[tid >> 5] = ss; }
    __syncthreads();
    float st  = ws[0] + ws[1] + ws[2] + ws[3];
    float sst = wss[0] + wss[1] + wss[2] + wss[3];
    float mu   = st * (1.0f / FEAT);
    float var  = sst * (1.0f / FEAT) - mu * mu;
    float rstd = rsqrtf(var + 1e-5f);
    float4 g  = *(const float4*)(gamma + tid * 4);
    float4 be = *(const float4*)(beta + tid * 4);
    float o[4];
    o[0] = (xv.x - mu) * rstd * g.x + be.x;
    o[1] = (xv.y - mu) * rstd * g.y + be.y;
    o[2] = (xv.z - mu) * rstd * g.z + be.z;
    o[3] = (xv.w - mu) * rstd * g.w + be.w;
    size_t off = (size_t)row * FEAT + tid * 4;
#pragma unroll
    for (int i = 0; i < 4; i++) {
        __nv_bfloat16 hi = __float2bfloat16(o[i]);
        g_ah[off + i] = hi;
        g_al[off + i] = __float2bfloat16(o[i] - __bfloat162float(hi));
    }
}

// ---------------- repack fused QKV weights W^T [1536][512] bf16 hi/lo ----------------
__global__ __launch_bounds__(256) void repack_qkv(const float* __restrict__ WQ,
                                                  const float* __restrict__ WK,
                                                  const float* __restrict__ WV) {
    int idx = blockIdx.x * 256 + threadIdx.x;   // n*512 + f
    int n = idx >> 9;
    int f = idx & 511;
    int which = n >> 9;
    int h = (n >> 6) & 7;
    int d = n & 63;
    const float* W = (which == 0) ? WQ : ((which == 1) ? WK : WV);
    float v = W[((size_t)h * FEAT + f) * DKDIM + d];
    __nv_bfloat16 hi = __float2bfloat16(v);
    g_bh[idx] = hi;
    g_bl[idx] = __float2bfloat16(v - __bfloat162float(hi));
}

// ---------------- repack WO^T [512][512] bf16 hi/lo ----------------
__global__ __launch_bounds__(256) void repack_wo(const float* __restrict__ WO) {
    int idx = blockIdx.x * 256 + threadIdx.x;   // n*512 + k
    int n = idx >> 9;
    int k = idx & 511;
    float v = WO[(size_t)k * 512 + n];
    __nv_bfloat16 hi = __float2bfloat16(v);
    g_oh[idx] = hi;
    g_ol[idx] = __float2bfloat16(v - __bfloat162float(hi));
}

// ---------------- mma.sync GEMM core: 512 threads, 16 warps (4m x 4n), 3-stage -------
// Stage (64KB): Ah [128][64]bf16 @0, Al @16384, Bh @32768, Bl @49152; SW128-swizzled.
// K-chunk = 64 bf16 (4 k-steps), 8 chunks over K=512. Warp tile 32x32.
#define GSTG 65536
#define GSMEM (3 * GSTG)
#define GTHREADS 512

__device__ __forceinline__ void stage_load(uint32_t sb, int stage, int chunk,
                                           const __nv_bfloat16* __restrict__ Ah,
                                           const __nv_bfloat16* __restrict__ Al,
                                           const __nv_bfloat16* __restrict__ Bh,
                                           const __nv_bfloat16* __restrict__ Bl,
                                           int m0, int n0) {
    int tid = threadIdx.x;
    uint32_t base = sb + stage * GSTG;
#pragma unroll
    for (int t = 0; t < 8; t++) {
        int idx = tid + t * GTHREADS;
        int mat = idx >> 10;          // constant per t (1024 idx per matrix)
        int pos = idx & 1023;
        int row = pos >> 3;
        int cu  = pos & 7;
        const __nv_bfloat16* src =
            (mat == 0) ? Ah + (size_t)(m0 + row) * FEAT :
            (mat == 1) ? Al + (size_t)(m0 + row) * FEAT :
            (mat == 2) ? Bh + (size_t)(n0 + row) * FEAT :
                         Bl + (size_t)(n0 + row) * FEAT;
        const __nv_bfloat16* g = src + chunk * 64 + cu * 8;
        uint32_t s = base + mat * 16384 + row * 128 + (uint32_t)((cu ^ (row & 7)) << 4);
        CP_ASYNC16(s, g);
    }
    CP_COMMIT();
}

__device__ __forceinline__ void gemm_mma_core(const __nv_bfloat16* __restrict__ Ah,
                                              const __nv_bfloat16* __restrict__ Al,
                                              const __nv_bfloat16* __restrict__ Bh,
                                              const __nv_bfloat16* __restrict__ Bl,
                                              char* smem, float acc[2][4][4]) {
    uint32_t sb = smem_u32(smem);
    int tid = threadIdx.x;
    int wid = tid >> 5, lane = tid & 31;
    int wm = wid & 3, wn = wid >> 2;       // 4 x 4 warp grid
    int m0 = blockIdx.y * 128;
    int n0 = blockIdx.x * 128;

#pragma unroll
    for (int mt = 0; mt < 2; mt++)
#pragma unroll
        for (int nt = 0; nt < 4; nt++)
#pragma unroll
            for (int i = 0; i < 4; i++) acc[mt][nt][i] = 0.0f;

    int rA = wm * 32 + (lane & 7) + ((lane >> 3) & 1) * 8;   // + mt*16
    int hA = lane >> 4;
    int rB = wn * 32 + (lane & 7) + ((lane >> 4) & 1) * 8;   // + np*16
    int hB = (lane >> 3) & 1;

    stage_load(sb, 0, 0, Ah, Al, Bh, Bl, m0, n0);
    stage_load(sb, 1, 1, Ah, Al, Bh, Bl, m0, n0);

    for (int c = 0; c < 8; c++) {
        if (c < 7) { CP_WAIT1(); } else { CP_WAIT0(); }
        __syncthreads();      // stage c landed for all; everyone done computing c-1
        if (c < 6)
            stage_load(sb, (c + 2) % 3, c + 2, Ah, Al, Bh, Bl, m0, n0);
        uint32_t buf = sb + (c % 3) * GSTG;
#pragma unroll
        for (int ks = 0; ks < 4; ks++) {
            uint32_t ah[2][4], al[2][4], bhf[2][4], blf[2][4];
#pragma unroll
            for (int mt = 0; mt < 2; mt++) {
                int row = rA + mt * 16;
                int c16 = ks * 2 + hA;
                uint32_t addr = buf + row * 128 + (uint32_t)(((c16 ^ (row & 7))) << 4);
                ldm4(ah[mt], addr);
                ldm4(al[mt], addr + 16384);
            }
#pragma unroll
            for (int np = 0; np < 2; np++) {
                int row = rB + np * 16;
                int c16 = ks * 2 + hB;
                uint32_t addr = buf + 32768 + row * 128 + (uint32_t)(((c16 ^ (row & 7))) << 4);
                ldm4(bhf[np], addr);
                ldm4(blf[np], addr + 16384);
            }
#pragma unroll
            for (int mt = 0; mt < 2; mt++) {
#pragma unroll
                for (int nt = 0; nt < 4; nt++) {
                    int np = nt >> 1, sel = (nt & 1) * 2;
                    mma16816(acc[mt][nt], ah[mt], bhf[np][sel], bhf[np][sel + 1]);
                    mma16816(acc[mt][nt], ah[mt], blf[np][sel], blf[np][sel + 1]);
                    mma16816(acc[mt][nt], al[mt], bhf[np][sel], bhf[np][sel + 1]);
                }
            }
        }
    }
}

// ---------------- QKV GEMM: epilogue -> bf16 hi/lo q,k [s,d]; v transposed [d,s] --------
__global__ __launch_bounds__(GTHREADS) void gemm_qkv_mma(const float* __restrict__ bq,
                                                         const float* __restrict__ bk,
                                                         const float* __restrict__ bv) {
    extern __shared__ char smem[];
    float acc[2][4][4];
    gemm_mma_core(g_ah, g_al, g_bh, g_bl, smem, acc);

    int tid = threadIdx.x;
    int wid = tid >> 5, lane = tid & 31;
    int wm = wid & 3, wn = wid >> 2;
    int m0 = blockIdx.y * 128, n0 = blockIdx.x * 128;
    int r = lane >> 2, cp2 = (lane & 3) * 2;

#pragma unroll
    for (int nt = 0; nt < 4; nt++) {
        int col = n0 + wn * 32 + nt * 8 + cp2;
        int which = col >> 9, h = (col >> 6) & 7, d = col & 63;
        const float* bias = (which == 0) ? bq : ((which == 1) ? bk : bv);
        float b0v = bias[h * 64 + d], b1v = bias[h * 64 + d + 1];
#pragma unroll
        for (int mt = 0; mt < 2; mt++) {
#pragma unroll
            for (int half = 0; half < 2; half++) {
                int m = m0 + wm * 32 + mt * 16 + r + half * 8;
                int bb = m >> 10, ss = m & 1023;
                int bh = bb * 8 + h;
                float v0 = acc[mt][nt][half * 2 + 0] + b0v;
                float v1 = acc[mt][nt][half * 2 + 1] + b1v;
                __nv_bfloat16 h0 = __float2bfloat16(v0);
                __nv_bfloat16 h1 = __float2bfloat16(v1);
                __nv_bfloat16 l0 = __float2bfloat16(v0 - __bfloat162float(h0));
                __nv_bfloat16 l1 = __float2bfloat16(v1 - __bfloat162float(h1));
                if (which == 2) {
                    size_t vi = ((size_t)bh * 64 + d) * 1024 + ss;
                    g_vth[vi] = h0;  g_vth[vi + 1024] = h1;
                    g_vtl[vi] = l0;  g_vtl[vi + 1024] = l1;
                } else {
                    size_t qi = ((size_t)bh * 1024 + ss) * 64 + d;
                    __nv_bfloat162 hp; hp.x = h0; hp.y = h1;
                    __nv_bfloat162 lp; lp.x = l0; lp.y = l1;
                    if (which == 0) {
                        *(__nv_bfloat162*)(g_qh + qi) = hp;
                        *(__nv_bfloat162*)(g_ql + qi) = lp;
                    } else {
                        *(__nv_bfloat162*)(g_kh + qi) = hp;
                        *(__nv_bfloat162*)(g_kl + qi) = lp;
                    }
                }
            }
        }
    }
}

// ---------------- output GEMM (mma.sync) ----------------
__global__ __launch_bounds__(GTHREADS) void gemm_out_mma(const float* __restrict__ bO,
                                                         float* __restrict__ out) {
    extern __shared__ char smem[];
    float acc[2][4][4];
    gemm_mma_core(g_zh, g_zl, g_oh, g_ol, smem, acc);

    int tid = threadIdx.x;
    int wid = tid >> 5, lane = tid & 31;
    int wm = wid & 3, wn = wid >> 2;
    int m0 = blockIdx.y * 128, n0 = blockIdx.x * 128;
    int r = lane >> 2, cp2 = (lane & 3) * 2;

#pragma unroll
    for (int nt = 0; nt < 4; nt++) {
        int col = n0 + wn * 32 + nt * 8 + cp2;
        float b0v = bO[col], b1v = bO[col + 1];
#pragma unroll
        for (int mt = 0; mt < 2; mt++) {
            int m = m0 + wm * 32 + mt * 16 + r;
            *(float2*)(out + (size_t)m * 512 + col) =
                make_float2(acc[mt][nt][0] + b0v, acc[mt][nt][1] + b1v);
            *(float2*)(out + (size_t)(m + 8) * 512 + col) =
                make_float2(acc[mt][nt][2] + b0v, acc[mt][nt][3] + b1v);
        }
    }
}

// ---------------- tensor-core flash attention (round-9, unchanged) --------------------
// smem: Q hi/lo 32KB @0; stage s (s=0,1) @32768 + s*65536:
//       K hi @+0, K lo @+16384, VT hi @+32768, VT lo @+49152
#define AT_SMEM (32768 + 2 * 65536)

__device__ __forceinline__ void attn_stage_load(uint32_t sb, int stage, int k0,
                                                size_t qkb, int bh) {
    int tid = threadIdx.x;
    uint32_t stb = sb + 32768 + stage * 65536;
#pragma unroll
    for (int tt = 0; tt < 8; tt++) {
        int idx = tid + tt * 256;
        int mat = idx >> 10;
        int pos = idx & 1023;
        int row = pos >> 3, cu = pos & 7;
        const __nv_bfloat16* src = (mat ? g_kl : g_kh) + qkb + (size_t)(k0 + row) * 64 + cu * 8;
        CP_ASYNC16(stb + mat * 16384 + row * 128 + (uint32_t)((cu ^ (row & 7)) << 4), src);
    }
#pragma unroll
    for (int tt = 0; tt < 8; tt++) {
        int idx = tid + tt * 256;
        int mat = idx >> 10;
        int pos = idx & 1023;
        int half = pos >> 9;
        int d = (pos >> 3) & 63, cu = pos & 7;
        const __nv_bfloat16* src = (mat ? g_vtl : g_vth) +
            ((size_t)bh * 64 + d) * 1024 + k0 + half * 64 + cu * 8;
        CP_ASYNC16(stb + 32768 + mat * 16384 + half * 8192 + d * 128 +
                   (uint32_t)((cu ^ (d & 7)) << 4), src);
    }
    CP_COMMIT();
}

__global__ __launch_bounds__(256, 1) void attn_mma() {
    extern __shared__ char smc[];
    uint32_t sb = smem_u32(smc);
    int tid = threadIdx.x, wid = tid >> 5, lane = tid & 31;
    int bh = blockIdx.y;
    int q0 = blockIdx.x * 128;
    size_t qkb = (size_t)bh * (SEQ * DKDIM);

    int last = q0 + 127;
    int blk_lim = (last < TCUT) ? TCUT : ((last == SEQ - 1) ? SEQ : last);
    int ntiles = (blk_lim + 127) >> 7;

    // ---- prologue: Q tile + stage 0, one wait ----
#pragma unroll
    for (int t = 0; t < 8; t++) {
        int idx = tid + t * 256;
        int mat = idx >> 10;
        int pos = idx & 1023;
        int row = pos >> 3, cu = pos & 7;
        const __nv_bfloat16* src = (mat ? g_ql : g_qh) + qkb + (size_t)(q0 + row) * 64 + cu * 8;
        CP_ASYNC16(sb + mat * 16384 + row * 128 + (uint32_t)((cu ^ (row & 7)) << 4), src);
    }
    CP_COMMIT();
    attn_stage_load(sb, 0, 0, qkb, bh);

    int gr0 = q0 + wid * 16 + (lane >> 2);
    int gr1 = gr0 + 8;
    int lim0 = (gr0 < TCUT) ? TCUT : ((gr0 == SEQ - 1) ? SEQ : gr0);
    int lim1 = (gr1 < TCUT) ? TCUT : ((gr1 == SEQ - 1) ? SEQ : gr1);

    float mr0 = -1e30f, mr1 = -1e30f, lr0 = 0.0f, lr1 = 0.0f;
    float o[8][4];
#pragma unroll
    for (int nt = 0; nt < 8; nt++)
#pragma unroll
        for (int i = 0; i < 4; i++) o[nt][i] = 0.0f;

    CP_WAIT0();     // Q + stage 0 landed
    __syncthreads();

    // ---- loop-invariant Q fragments ----
    uint32_t qf[4][2][4];
    {
        int rqa = wid * 16 + (lane & 7) + ((lane >> 3) & 1) * 8;
        int hA = lane >> 4;
#pragma unroll
        for (int kk = 0; kk < 4; kk++) {
            int c16 = kk * 2 + hA;
            uint32_t addr = sb + rqa * 128 + (uint32_t)(((c16 ^ (rqa & 7))) << 4);
            ldm4(qf[kk][0], addr);
            ldm4(qf[kk][1], addr + 16384);
        }
    }

    int rB = (lane & 7) + ((lane >> 4) & 1) * 8;
    int hB = (lane >> 3) & 1;

    for (int t = 0; t < ntiles; t++) {
        int k0 = t * 128;
        if (t > 0) {
            CP_WAIT0();      // stage t landed
            __syncthreads(); // all warps done computing stage t-1
        }
        if (t + 1 < ntiles)
            attn_stage_load(sb, (t + 1) & 1, (t + 1) * 128, qkb, bh);

        uint32_t stb = sb + 32768 + (t & 1) * 65536;

        // ---- S = Q K^T (3-term hi/lo) ----
        float s[16][4];
#pragma unroll
        for (int nt = 0; nt < 16; nt++)
#pragma unroll
            for (int i = 0; i < 4; i++) s[nt][i] = 0.0f;
#pragma unroll
        for (int kk = 0; kk < 4; kk++) {
#pragma unroll
            for (int np = 0; np < 8; np++) {
                int row = rB + np * 16;
                int c16 = kk * 2 + hB;
                uint32_t addr = stb + row * 128 + (uint32_t)(((c16 ^ (row & 7))) << 4);
                uint32_t kbh[4], kbl[4];
                ldm4(kbh, addr);
                ldm4(kbl, addr + 16384);
                mma16816(s[2 * np],     qf[kk][0], kbh[0], kbh[1]);
                mma16816(s[2 * np],     qf[kk][0], kbl[0], kbl[1]);
                mma16816(s[2 * np],     qf[kk][1], kbh[0], kbh[1]);
                mma16816(s[2 * np + 1], qf[kk][0], kbh[2], kbh[3]);
                mma16816(s[2 * np + 1], qf[kk][0], kbl[2], kbl[3]);
                mma16816(s[2 * np + 1], qf[kk][1], kbh[2], kbh[3]);
            }
        }

        // ---- mask + online softmax ----
        float mx0 = -1e30f, mx1 = -1e30f;
#pragma unroll
        for (int nt = 0; nt < 16; nt++) {
            int kb = k0 + nt * 8 + (lane & 3) * 2;
            float v0 = (kb     < lim0) ? s[nt][0] * 0.125f : -1e30f;
            float v1 = (kb + 1 < lim0) ? s[nt][1] * 0.125f : -1e30f;
            float v2 = (kb     < lim1) ? s[nt][2] * 0.125f : -1e30f;
            float v3 = (kb + 1 < lim1) ? s[nt][3] * 0.125f : -1e30f;
            s[nt][0] = v0; s[nt][1] = v1; s[nt][2] = v2; s[nt][3] = v3;
            mx0 = fmaxf(mx0, fmaxf(v0, v1));
            mx1 = fmaxf(mx1, fmaxf(v2, v3));
        }
        mx0 = fmaxf(mx0, __shfl_xor_sync(0xffffffffu, mx0, 1));
        mx0 = fmaxf(mx0, __shfl_xor_sync(0xffffffffu, mx0, 2));
        mx1 = fmaxf(mx1, __shfl_xor_sync(0xffffffffu, mx1, 1));
        mx1 = fmaxf(mx1, __shfl_xor_sync(0xffffffffu, mx1, 2));
        float nm0 = fmaxf(mr0, mx0), nm1 = fmaxf(mr1, mx1);
        float a0 = __expf(mr0 - nm0), a1 = __expf(mr1 - nm1);
        float ls0 = 0.0f, ls1 = 0.0f;
#pragma unroll
        for (int nt = 0; nt < 16; nt++) {
            float p0 = __expf(s[nt][0] - nm0);
            float p1 = __expf(s[nt][1] - nm0);
            float p2 = __expf(s[nt][2] - nm1);
            float p3 = __expf(s[nt][3] - nm1);
            s[nt][0] = p0; s[nt][1] = p1; s[nt][2] = p2; s[nt][3] = p3;
            ls0 += p0 + p1;
            ls1 += p2 + p3;
        }
        ls0 += __shfl_xor_sync(0xffffffffu, ls0, 1);
        ls0 += __shfl_xor_sync(0xffffffffu, ls0, 2);
        ls1 += __shfl_xor_sync(0xffffffffu, ls1, 1);
        ls1 += __shfl_xor_sync(0xffffffffu, ls1, 2);
        lr0 = lr0 * a0 + ls0;
        lr1 = lr1 * a1 + ls1;
        mr0 = nm0; mr1 = nm1;
#pragma unroll
        for (int nt = 0; nt < 8; nt++) {
            o[nt][0] *= a0; o[nt][1] *= a0;
            o[nt][2] *= a1; o[nt][3] *= a1;
        }

        // ---- O += P V (3-term hi/lo) ----
#pragma unroll
        for (int kk2 = 0; kk2 < 8; kk2++) {
            uint32_t pah[4], pal[4];
            split_pair(s[2 * kk2][0],     s[2 * kk2][1],     pah[0], pal[0]);
            split_pair(s[2 * kk2][2],     s[2 * kk2][3],     pah[1], pal[1]);
            split_pair(s[2 * kk2 + 1][0], s[2 * kk2 + 1][1], pah[2], pal[2]);
            split_pair(s[2 * kk2 + 1][2], s[2 * kk2 + 1][3], pah[3], pal[3]);
            int half = kk2 >> 2;
            int c16 = (kk2 & 3) * 2 + hB;
#pragma unroll
            for (int np = 0; np < 4; np++) {
                int row = rB + np * 16;
                uint32_t addr = stb + 32768 + half * 8192 + row * 128 +
                                (uint32_t)(((c16 ^ (row & 7))) << 4);
                uint32_t vbh[4], vbl[4];
                ldm4(vbh, addr);
                ldm4(vbl, addr + 16384);
                mma16816(o[2 * np],     pah, vbh[0], vbh[1]);
                mma16816(o[2 * np],     pah, vbl[0], vbl[1]);
                mma16816(o[2 * np],     pal, vbh[0], vbh[1]);
                mma16816(o[2 * np + 1], pah, vbh[2], vbh[3]);
                mma16816(o[2 * np + 1], pah, vbl[2], vbl[3]);
                mma16816(o[2 * np + 1], pal, vbh[2], vbh[3]);
            }
        }
    }

    // ---- epilogue: z hi/lo ----
    float inv0 = 1.0f / lr0, inv1 = 1.0f / lr1;
    int b = bh >> 3, h = bh & 7;
    size_t z0 = (size_t)(b * SEQ + gr0) * FEAT + h * 64;
    size_t z1 = (size_t)(b * SEQ + gr1) * FEAT + h * 64;
#pragma unroll
    for (int nt = 0; nt < 8; nt++) {
        int col = nt * 8 + (lane & 3) * 2;
        float v0 = o[nt][0] * inv0, v1 = o[nt][1] * inv0;
        float v2 = o[nt][2] * inv1, v3 = o[nt][3] * inv1;
        __nv_bfloat16 h0 = __float2bfloat16(v0), h1 = __float2bfloat16(v1);
        __nv_bfloat16 h2 = __float2bfloat16(v2), h3 = __float2bfloat16(v3);
        __nv_bfloat162 hp0; hp0.x = h0; hp0.y = h1;
        __nv_bfloat162 hp1; hp1.x = h2; hp1.y = h3;
        __nv_bfloat162 lp0; lp0.x = __float2bfloat16(v0 - __bfloat162float(h0));
        lp0.y = __float2bfloat16(v1 - __bfloat162float(h1));
        __nv_bfloat162 lp1; lp1.x = __float2bfloat16(v2 - __bfloat162float(h2));
        lp1.y = __float2bfloat16(v3 - __bfloat162float(h3));
        *(__nv_bfloat162*)(g_zh + z0 + col) = hp0;
        *(__nv_bfloat162*)(g_zl + z0 + col) = lp0;
        *(__nv_bfloat162*)(g_zh + z1 + col) = hp1;
        *(__nv_bfloat162*)(g_zl + z1 + col) = lp1;
    }
}

// ---------------- launch ----------------
extern "C" void kernel_launch(void* const* d_in, const int* in_sizes, int n_in,
                              void* d_out, int out_size) {
    const float* x     = (const float*)d_in[0];
    const float* gamma = (const float*)d_in[1];
    const float* beta  = (const float*)d_in[2];
    const float* WQ    = (const float*)d_in[3];
    const float* bq    = (const float*)d_in[4];
    const float* WK    = (const float*)d_in[5];
    const float* bk    = (const float*)d_in[6];
    const float* WV    = (const float*)d_in[7];
    const float* bv    = (const float*)d_in[8];
    const float* WO    = (const float*)d_in[9];
    const float* bO    = (const float*)d_in[10];
    float* out = (float*)d_out;

    (void)in_sizes; (void)n_in; (void)out_size;

    cudaFuncSetAttribute(attn_mma, cudaFuncAttributeMaxDynamicSharedMemorySize, AT_SMEM);
    cudaFuncSetAttribute(gemm_qkv_mma, cudaFuncAttributeMaxDynamicSharedMemorySize, GSMEM);
    cudaFuncSetAttribute(gemm_out_mma, cudaFuncAttributeMaxDynamicSharedMemorySize, GSMEM);

    ln_kernel<<<MTOT, 128>>>(x, gamma, beta);
    repack_qkv<<<(NQKV * FEAT) / 256, 256>>>(WQ, WK, WV);
    repack_wo<<<(FEAT * FEAT) / 256, 256>>>(WO);
    gemm_qkv_mma<<<dim3(NQKV / 128, MTOT / 128), GTHREADS, GSMEM>>>(bq, bk, bv);
    attn_mma<<<dim3(SEQ / 128, BATCH * HEADS), 256, AT_SMEM>>>();
    gemm_out_mma<<<dim3(512 / 128, MTOT / 128), GTHREADS, GSMEM>>>(bO, out);
}

// round 12
// speedup vs baseline: 1.1762x; 1.1421x over previous
#include <cuda_runtime.h>
#include <cuda_bf16.h>
#include <cuda_fp16.h>
#include <cstdint>

#define BATCH 8
#define SEQ   1024
#define FEAT  512
#define HEADS 8
#define DKDIM 64
#define TCUT  823
#define MTOT  (BATCH * SEQ)     // 8192
#define NQKV  1536

// ---------------- scratch (device globals; no runtime alloc) ----------------
__device__ __align__(256) __nv_bfloat16 g_ah[MTOT * FEAT];        // xn hi   [m][k] bf16
__device__ __align__(256) __nv_bfloat16 g_al[MTOT * FEAT];        // xn lo   bf16
__device__ __align__(256) __nv_bfloat16 g_bh[NQKV * FEAT];        // W^T hi  [n][k] bf16
__device__ __align__(256) __nv_bfloat16 g_bl[NQKV * FEAT];        // W^T lo  bf16
__device__ __align__(256) __half        g_z [MTOT * FEAT];        // z fp16  [m][k]
__device__ __align__(256) __half        g_oh[FEAT * FEAT];        // WO^T hi [n][k] fp16
__device__ __align__(256) __half        g_ol[FEAT * FEAT];        // WO^T lo fp16
// q,k: [b,h,s,d] bf16 hi/lo (exact split); v transposed [b,h,d,s] fp16 single
__device__ __align__(256) __nv_bfloat16 g_qh[64 * SEQ * DKDIM];
__device__ __align__(256) __nv_bfloat16 g_ql[64 * SEQ * DKDIM];
__device__ __align__(256) __nv_bfloat16 g_kh[64 * SEQ * DKDIM];
__device__ __align__(256) __nv_bfloat16 g_kl[64 * SEQ * DKDIM];
__device__ __align__(256) __half        g_vt[64 * DKDIM * SEQ];

// ---------------- helpers ----------------
__device__ __forceinline__ uint32_t smem_u32(const void* p) {
    uint32_t a;
    asm("{ .reg .u64 t; cvta.to.shared.u64 t, %1; cvt.u32.u64 %0, t; }" : "=r"(a) : "l"(p));
    return a;
}
__device__ __forceinline__ void ldm4(uint32_t* r, uint32_t addr) {
    asm volatile("ldmatrix.sync.aligned.m8n8.x4.shared.b16 {%0,%1,%2,%3}, [%4];"
                 : "=r"(r[0]), "=r"(r[1]), "=r"(r[2]), "=r"(r[3]) : "r"(addr));
}
__device__ __forceinline__ void mma16816(float* c, const uint32_t* a, uint32_t b0, uint32_t b1) {
    asm volatile("mma.sync.aligned.m16n8k16.row.col.f32.bf16.bf16.f32 "
                 "{%0,%1,%2,%3}, {%4,%5,%6,%7}, {%8,%9}, {%0,%1,%2,%3};"
                 : "+f"(c[0]), "+f"(c[1]), "+f"(c[2]), "+f"(c[3])
                 : "r"(a[0]), "r"(a[1]), "r"(a[2]), "r"(a[3]), "r"(b0), "r"(b1));
}
__device__ __forceinline__ void mma16816h(float* c, const uint32_t* a, uint32_t b0, uint32_t b1) {
    asm volatile("mma.sync.aligned.m16n8k16.row.col.f32.f16.f16.f32 "
                 "{%0,%1,%2,%3}, {%4,%5,%6,%7}, {%8,%9}, {%0,%1,%2,%3};"
                 : "+f"(c[0]), "+f"(c[1]), "+f"(c[2]), "+f"(c[3])
                 : "r"(a[0]), "r"(a[1]), "r"(a[2]), "r"(a[3]), "r"(b0), "r"(b1));
}
__device__ __forceinline__ uint32_t pack_f16x2(float lo, float hi) {
    uint32_t r;
    asm("cvt.rn.f16x2.f32 %0, %1, %2;" : "=r"(r) : "f"(hi), "f"(lo));
    return r;
}
__device__ __forceinline__ void split_pair_h(float x0, float x1, uint32_t& h, uint32_t& l) {
    h = pack_f16x2(x0, x1);
    __half2 hb = *reinterpret_cast<__half2*>(&h);
    l = pack_f16x2(x0 - __half2float(hb.x), x1 - __half2float(hb.y));
}
#define CP_ASYNC16(saddr, gaddr) \
    asm volatile("cp.async.ca.shared.global [%0], [%1], 16;" :: "r"(saddr), "l"(gaddr))
#define CP_COMMIT() asm volatile("cp.async.commit_group;" ::: "memory")
#define CP_WAIT1()  asm volatile("cp.async.wait_group 1;" ::: "memory")
#define CP_WAIT0()  asm volatile("cp.async.wait_group 0;" ::: "memory")

// ---------------- LayerNorm -> bf16 hi/lo ----------------
__global__ __launch_bounds__(128) void ln_kernel(const float* __restrict__ x,
                                                 const float* __restrict__ gamma,
                                                 const float* __restrict__ beta) {
    int row = blockIdx.x;
    int tid = threadIdx.x;
    const float4 xv = *(const float4*)(x + (size_t)row * FEAT + tid * 4);
    float s  = xv.x + xv.y + xv.z + xv.w;
    float ss = xv.x * xv.x + xv.y * xv.y + xv.z * xv.z + xv.w * xv.w;
#pragma unroll
    for (int o = 16; o > 0; o >>= 1) {
        s  += __shfl_xor_sync(0xffffffffu, s, o);
        ss += __shfl_xor_sync(0xffffffffu, ss, o);
    }
    __shared__ float ws[4], wss[4];
    if ((tid & 31) == 0) { ws[tid >> 5] = s; wss[tid >> 5] = ss; }
    __syncthreads();
    float st  = ws[0] + ws[1] + ws[2] + ws[3];
    float sst = wss[0] + wss[1] + wss[2] + wss[3];
    float mu   = st * (1.0f / FEAT);
    float var  = sst * (1.0f / FEAT) - mu * mu;
    float rstd = rsqrtf(var + 1e-5f);
    float4 g  = *(const float4*)(gamma + tid * 4);
    float4 be = *(const float4*)(beta + tid * 4);
    float o[4];
    o[0] = (xv.x - mu) * rstd * g.x + be.x;
    o[1] = (xv.y - mu) * rstd * g.y + be.y;
    o[2] = (xv.z - mu) * rstd * g.z + be.z;
    o[3] = (xv.w - mu) * rstd * g.w + be.w;
    size_t off = (size_t)row * FEAT + tid * 4;
#pragma unroll
    for (int i = 0; i < 4; i++) {
        __nv_bfloat16 hi = __float2bfloat16(o[i]);
        g_ah[off + i] = hi;
        g_al[off + i] = __float2bfloat16(o[i] - __bfloat162float(hi));
    }
}

// ---------------- repack fused QKV weights W^T [1536][512] bf16 hi/lo ----------------
__global__ __launch_bounds__(256) void repack_qkv(const float* __restrict__ WQ,
                                                  const float* __restrict__ WK,
                                                  const float* __restrict__ WV) {
    int idx = blockIdx.x * 256 + threadIdx.x;
    int n = idx >> 9;
    int f = idx & 511;
    int which = n >> 9;
    int h = (n >> 6) & 7;
    int d = n & 63;
    const float* W = (which == 0) ? WQ : ((which == 1) ? WK : WV);
    float v = W[((size_t)h * FEAT + f) * DKDIM + d];
    __nv_bfloat16 hi = __float2bfloat16(v);
    g_bh[idx] = hi;
    g_bl[idx] = __float2bfloat16(v - __bfloat162float(hi));
}

// ---------------- repack WO^T [512][512] fp16 hi/lo ----------------
__global__ __launch_bounds__(256) void repack_wo(const float* __restrict__ WO) {
    int idx = blockIdx.x * 256 + threadIdx.x;
    int n = idx >> 9;
    int k = idx & 511;
    float v = WO[(size_t)k * 512 + n];
    __half hi = __float2half(v);
    g_oh[idx] = hi;
    g_ol[idx] = __float2half(v - __half2float(hi));
}

// ---------------- QKV GEMM core: 3-term bf16, 512 thr, 3-stage (R10 proven) ----------
#define GSTG 65536
#define GSMEM (3 * GSTG)
#define GTHREADS 512

__device__ __forceinline__ void stage_load4(uint32_t sb, int stage, int chunk,
                                            int m0, int n0) {
    int tid = threadIdx.x;
    uint32_t base = sb + stage * GSTG;
#pragma unroll
    for (int t = 0; t < 8; t++) {
        int idx = tid + t * GTHREADS;
        int mat = idx >> 10;
        int pos = idx & 1023;
        int row = pos >> 3;
        int cu  = pos & 7;
        const __nv_bfloat16* src =
            (mat == 0) ? g_ah + (size_t)(m0 + row) * FEAT :
            (mat == 1) ? g_al + (size_t)(m0 + row) * FEAT :
            (mat == 2) ? g_bh + (size_t)(n0 + row) * FEAT :
                         g_bl + (size_t)(n0 + row) * FEAT;
        const __nv_bfloat16* g = src + chunk * 64 + cu * 8;
        uint32_t s = base + mat * 16384 + row * 128 + (uint32_t)((cu ^ (row & 7)) << 4);
        CP_ASYNC16(s, g);
    }
    CP_COMMIT();
}

__global__ __launch_bounds__(GTHREADS) void gemm_qkv_mma(const float* __restrict__ bq,
                                                         const float* __restrict__ bk,
                                                         const float* __restrict__ bv) {
    extern __shared__ char smem[];
    uint32_t sb = smem_u32(smem);
    int tid = threadIdx.x;
    int wid = tid >> 5, lane = tid & 31;
    int wm = wid & 3, wn = wid >> 2;
    int m0 = blockIdx.y * 128;
    int n0 = blockIdx.x * 128;

    float acc[2][4][4];
#pragma unroll
    for (int mt = 0; mt < 2; mt++)
#pragma unroll
        for (int nt = 0; nt < 4; nt++)
#pragma unroll
            for (int i = 0; i < 4; i++) acc[mt][nt][i] = 0.0f;

    int rA = wm * 32 + (lane & 7) + ((lane >> 3) & 1) * 8;
    int hA = lane >> 4;
    int rB = wn * 32 + (lane & 7) + ((lane >> 4) & 1) * 8;
    int hB = (lane >> 3) & 1;

    stage_load4(sb, 0, 0, m0, n0);
    stage_load4(sb, 1, 1, m0, n0);

    for (int c = 0; c < 8; c++) {
        if (c < 7) { CP_WAIT1(); } else { CP_WAIT0(); }
        __syncthreads();
        if (c < 6)
            stage_load4(sb, (c + 2) % 3, c + 2, m0, n0);
        uint32_t buf = sb + (c % 3) * GSTG;
#pragma unroll
        for (int ks = 0; ks < 4; ks++) {
            uint32_t ah[2][4], al[2][4], bhf[2][4], blf[2][4];
#pragma unroll
            for (int mt = 0; mt < 2; mt++) {
                int row = rA + mt * 16;
                int c16 = ks * 2 + hA;
                uint32_t addr = buf + row * 128 + (uint32_t)(((c16 ^ (row & 7))) << 4);
                ldm4(ah[mt], addr);
                ldm4(al[mt], addr + 16384);
            }
#pragma unroll
            for (int np = 0; np < 2; np++) {
                int row = rB + np * 16;
                int c16 = ks * 2 + hB;
                uint32_t addr = buf + 32768 + row * 128 + (uint32_t)(((c16 ^ (row & 7))) << 4);
                ldm4(bhf[np], addr);
                ldm4(blf[np], addr + 16384);
            }
#pragma unroll
            for (int mt = 0; mt < 2; mt++) {
#pragma unroll
                for (int nt = 0; nt < 4; nt++) {
                    int np = nt >> 1, sel = (nt & 1) * 2;
                    mma16816(acc[mt][nt], ah[mt], bhf[np][sel], bhf[np][sel + 1]);
                    mma16816(acc[mt][nt], ah[mt], blf[np][sel], blf[np][sel + 1]);
                    mma16816(acc[mt][nt], al[mt], bhf[np][sel], bhf[np][sel + 1]);
                }
            }
        }
    }

    int r = lane >> 2, cp2 = (lane & 3) * 2;
#pragma unroll
    for (int nt = 0; nt < 4; nt++) {
        int col = n0 + wn * 32 + nt * 8 + cp2;
        int which = col >> 9, h = (col >> 6) & 7, d = col & 63;
        const float* bias = (which == 0) ? bq : ((which == 1) ? bk : bv);
        float b0v = bias[h * 64 + d], b1v = bias[h * 64 + d + 1];
#pragma unroll
        for (int mt = 0; mt < 2; mt++) {
#pragma unroll
            for (int half = 0; half < 2; half++) {
                int m = m0 + wm * 32 + mt * 16 + r + half * 8;
                int bb = m >> 10, ss = m & 1023;
                int bh = bb * 8 + h;
                float v0 = acc[mt][nt][half * 2 + 0] + b0v;
                float v1 = acc[mt][nt][half * 2 + 1] + b1v;
                if (which == 2) {
                    size_t vi = ((size_t)bh * 64 + d) * 1024 + ss;
                    g_vt[vi] = __float2half(v0);
                    g_vt[vi + 1024] = __float2half(v1);
                } else {
                    __nv_bfloat16 h0 = __float2bfloat16(v0);
                    __nv_bfloat16 h1 = __float2bfloat16(v1);
                    __nv_bfloat16 l0 = __float2bfloat16(v0 - __bfloat162float(h0));
                    __nv_bfloat16 l1 = __float2bfloat16(v1 - __bfloat162float(h1));
                    size_t qi = ((size_t)bh * 1024 + ss) * 64 + d;
                    __nv_bfloat162 hp; hp.x = h0; hp.y = h1;
                    __nv_bfloat162 lp; lp.x = l0; lp.y = l1;
                    if (which == 0) {
                        *(__nv_bfloat162*)(g_qh + qi) = hp;
                        *(__nv_bfloat162*)(g_ql + qi) = lp;
                    } else {
                        *(__nv_bfloat162*)(g_kh + qi) = hp;
                        *(__nv_bfloat162*)(g_kl + qi) = lp;
                    }
                }
            }
        }
    }
}

// ---------------- out GEMM core: 2-term fp16 (z single, WO hi/lo), 512 thr, 3-stage ---
#define OSTG 49152
#define OSMEM (3 * OSTG)

__device__ __forceinline__ void stage_load3(uint32_t sb, int stage, int chunk,
                                            int m0, int n0) {
    int tid = threadIdx.x;
    uint32_t base = sb + stage * OSTG;
#pragma unroll
    for (int t = 0; t < 6; t++) {
        int idx = tid + t * GTHREADS;
        int mat = idx >> 10;          // 0=z, 1=WOh, 2=WOl
        int pos = idx & 1023;
        int row = pos >> 3;
        int cu  = pos & 7;
        const __half* src =
            (mat == 0) ? g_z  + (size_t)(m0 + row) * FEAT :
            (mat == 1) ? g_oh + (size_t)(n0 + row) * FEAT :
                         g_ol + (size_t)(n0 + row) * FEAT;
        const __half* g = src + chunk * 64 + cu * 8;
        uint32_t s = base + mat * 16384 + row * 128 + (uint32_t)((cu ^ (row & 7)) << 4);
        CP_ASYNC16(s, g);
    }
    CP_COMMIT();
}

__global__ __launch_bounds__(GTHREADS) void gemm_out_mma(const float* __restrict__ bO,
                                                         float* __restrict__ out) {
    extern __shared__ char smem[];
    uint32_t sb = smem_u32(smem);
    int tid = threadIdx.x;
    int wid = tid >> 5, lane = tid & 31;
    int wm = wid & 3, wn = wid >> 2;
    int m0 = blockIdx.y * 128;
    int n0 = blockIdx.x * 128;

    float acc[2][4][4];
#pragma unroll
    for (int mt = 0; mt < 2; mt++)
#pragma unroll
        for (int nt = 0; nt < 4; nt++)
#pragma unroll
            for (int i = 0; i < 4; i++) acc[mt][nt][i] = 0.0f;

    int rA = wm * 32 + (lane & 7) + ((lane >> 3) & 1) * 8;
    int hA = lane >> 4;
    int rB = wn * 32 + (lane & 7) + ((lane >> 4) & 1) * 8;
    int hB = (lane >> 3) & 1;

    stage_load3(sb, 0, 0, m0, n0);
    stage_load3(sb, 1, 1, m0, n0);

    for (int c = 0; c < 8; c++) {
        if (c < 7) { CP_WAIT1(); } else { CP_WAIT0(); }
        __syncthreads();
        if (c < 6)
            stage_load3(sb, (c + 2) % 3, c + 2, m0, n0);
        uint32_t buf = sb + (c % 3) * OSTG;
#pragma unroll
        for (int ks = 0; ks < 4; ks++) {
            uint32_t ah[2][4], bhf[2][4], blf[2][4];
#pragma unroll
            for (int mt = 0; mt < 2; mt++) {
                int row = rA + mt * 16;
                int c16 = ks * 2 + hA;
                ldm4(ah[mt], buf + row * 128 + (uint32_t)(((c16 ^ (row & 7))) << 4));
            }
#pragma unroll
            for (int np = 0; np < 2; np++) {
                int row = rB + np * 16;
                int c16 = ks * 2 + hB;
                uint32_t addr = buf + 16384 + row * 128 + (uint32_t)(((c16 ^ (row & 7))) << 4);
                ldm4(bhf[np], addr);
                ldm4(blf[np], addr + 16384);
            }
#pragma unroll
            for (int mt = 0; mt < 2; mt++) {
#pragma unroll
                for (int nt = 0; nt < 4; nt++) {
                    int np = nt >> 1, sel = (nt & 1) * 2;
                    mma16816h(acc[mt][nt], ah[mt], bhf[np][sel], bhf[np][sel + 1]);
                    mma16816h(acc[mt][nt], ah[mt], blf[np][sel], blf[np][sel + 1]);
                }
            }
        }
    }

    int r = lane >> 2, cp2 = (lane & 3) * 2;
#pragma unroll
    for (int nt = 0; nt < 4; nt++) {
        int col = n0 + wn * 32 + nt * 8 + cp2;
        float b0v = bO[col], b1v = bO[col + 1];
#pragma unroll
        for (int mt = 0; mt < 2; mt++) {
            int m = m0 + wm * 32 + mt * 16 + r;
            *(float2*)(out + (size_t)m * 512 + col) =
                make_float2(acc[mt][nt][0] + b0v, acc[mt][nt][1] + b1v);
            *(float2*)(out + (size_t)(m + 8) * 512 + col) =
                make_float2(acc[mt][nt][2] + b0v, acc[mt][nt][3] + b1v);
        }
    }
}

// ---------------- flash attention: QK 3-term bf16, PV 2-term fp16 ----------
// smem: Q hi/lo 32KB @0; stage s (s=0,1) @32768 + s*49152:
//       K hi @+0, K lo @+16384, VT fp16 @+32768 (16KB)
#define ASTG 49152
#define AT_SMEM (32768 + 2 * ASTG)

__device__ __forceinline__ void attn_stage_load(uint32_t sb, int stage, int k0,
                                                size_t qkb, int bh) {
    int tid = threadIdx.x;
    uint32_t stb = sb + 32768 + stage * ASTG;
#pragma unroll
    for (int tt = 0; tt < 8; tt++) {
        int idx = tid + tt * 256;
        int mat = idx >> 10;
        int pos = idx & 1023;
        int row = pos >> 3, cu = pos & 7;
        const __nv_bfloat16* src = (mat ? g_kl : g_kh) + qkb + (size_t)(k0 + row) * 64 + cu * 8;
        CP_ASYNC16(stb + mat * 16384 + row * 128 + (uint32_t)((cu ^ (row & 7)) << 4), src);
    }
#pragma unroll
    for (int tt = 0; tt < 4; tt++) {
        int pos = tid + tt * 256;      // 0..1023
        int half = pos >> 9;
        int d = (pos >> 3) & 63, cu = pos & 7;
        const __half* src = g_vt + ((size_t)bh * 64 + d) * 1024 + k0 + half * 64 + cu * 8;
        CP_ASYNC16(stb + 32768 + half * 8192 + d * 128 +
                   (uint32_t)((cu ^ (d & 7)) << 4), src);
    }
    CP_COMMIT();
}

__global__ __launch_bounds__(256, 1) void attn_mma() {
    extern __shared__ char smc[];
    uint32_t sb = smem_u32(smc);
    int tid = threadIdx.x, wid = tid >> 5, lane = tid & 31;
    int bh = blockIdx.y;
    int q0 = blockIdx.x * 128;
    size_t qkb = (size_t)bh * (SEQ * DKDIM);

    int last = q0 + 127;
    int blk_lim = (last < TCUT) ? TCUT : ((last == SEQ - 1) ? SEQ : last);
    int ntiles = (blk_lim + 127) >> 7;

    // ---- prologue: Q tile (hi/lo) + stage 0 ----
#pragma unroll
    for (int t = 0; t < 8; t++) {
        int idx = tid + t * 256;
        int mat = idx >> 10;
        int pos = idx & 1023;
        int row = pos >> 3, cu = pos & 7;
        const __nv_bfloat16* src = (mat ? g_ql : g_qh) + qkb + (size_t)(q0 + row) * 64 + cu * 8;
        CP_ASYNC16(sb + mat * 16384 + row * 128 + (uint32_t)((cu ^ (row & 7)) << 4), src);
    }
    CP_COMMIT();
    attn_stage_load(sb, 0, 0, qkb, bh);

    int gr0 = q0 + wid * 16 + (lane >> 2);
    int gr1 = gr0 + 8;
    int lim0 = (gr0 < TCUT) ? TCUT : ((gr0 == SEQ - 1) ? SEQ : gr0);
    int lim1 = (gr1 < TCUT) ? TCUT : ((gr1 == SEQ - 1) ? SEQ : gr1);

    float mr0 = -1e30f, mr1 = -1e30f, lr0 = 0.0f, lr1 = 0.0f;
    float o[8][4];
#pragma unroll
    for (int nt = 0; nt < 8; nt++)
#pragma unroll
        for (int i = 0; i < 4; i++) o[nt][i] = 0.0f;

    CP_WAIT0();
    __syncthreads();

    // ---- loop-invariant Q fragments ----
    uint32_t qf[4][2][4];
    {
        int rqa = wid * 16 + (lane & 7) + ((lane >> 3) & 1) * 8;
        int hA = lane >> 4;
#pragma unroll
        for (int kk = 0; kk < 4; kk++) {
            int c16 = kk * 2 + hA;
            uint32_t addr = sb + rqa * 128 + (uint32_t)(((c16 ^ (rqa & 7))) << 4);
            ldm4(qf[kk][0], addr);
            ldm4(qf[kk][1], addr + 16384);
        }
    }

    int rB = (lane & 7) + ((lane >> 4) & 1) * 8;
    int hB = (lane >> 3) & 1;

    for (int t = 0; t < ntiles; t++) {
        int k0 = t * 128;
        if (t > 0) {
            CP_WAIT0();
            __syncthreads();
        }
        if (t + 1 < ntiles)
            attn_stage_load(sb, (t + 1) & 1, (t + 1) * 128, qkb, bh);

        uint32_t stb = sb + 32768 + (t & 1) * ASTG;

        // ---- S = Q K^T (3-term bf16 hi/lo) ----
        float s[16][4];
#pragma unroll
        for (int nt = 0; nt < 16; nt++)
#pragma unroll
            for (int i = 0; i < 4; i++) s[nt][i] = 0.0f;
#pragma unroll
        for (int kk = 0; kk < 4; kk++) {
#pragma unroll
            for (int np = 0; np < 8; np++) {
                int row = rB + np * 16;
                int c16 = kk * 2 + hB;
                uint32_t addr = stb + row * 128 + (uint32_t)(((c16 ^ (row & 7))) << 4);
                uint32_t kbh[4], kbl[4];
                ldm4(kbh, addr);
                ldm4(kbl, addr + 16384);
                mma16816(s[2 * np],     qf[kk][0], kbh[0], kbh[1]);
                mma16816(s[2 * np],     qf[kk][0], kbl[0], kbl[1]);
                mma16816(s[2 * np],     qf[kk][1], kbh[0], kbh[1]);
                mma16816(s[2 * np + 1], qf[kk][0], kbh[2], kbh[3]);
                mma16816(s[2 * np + 1], qf[kk][0], kbl[2], kbl[3]);
                mma16816(s[2 * np + 1], qf[kk][1], kbh[2], kbh[3]);
            }
        }

        // ---- mask + online softmax ----
        float mx0 = -1e30f, mx1 = -1e30f;
#pragma unroll
        for (int nt = 0; nt < 16; nt++) {
            int kb = k0 + nt * 8 + (lane & 3) * 2;
            float v0 = (kb     < lim0) ? s[nt][0] * 0.125f : -1e30f;
            float v1 = (kb + 1 < lim0) ? s[nt][1] * 0.125f : -1e30f;
            float v2 = (kb     < lim1) ? s[nt][2] * 0.125f : -1e30f;
            float v3 = (kb + 1 < lim1) ? s[nt][3] * 0.125f : -1e30f;
            s[nt][0] = v0; s[nt][1] = v1; s[nt][2] = v2; s[nt][3] = v3;
            mx0 = fmaxf(mx0, fmaxf(v0, v1));
            mx1 = fmaxf(mx1, fmaxf(v2, v3));
        }
        mx0 = fmaxf(mx0, __shfl_xor_sync(0xffffffffu, mx0, 1));
        mx0 = fmaxf(mx0, __shfl_xor_sync(0xffffffffu, mx0, 2));
        mx1 = fmaxf(mx1, __shfl_xor_sync(0xffffffffu, mx1, 1));
        mx1 = fmaxf(mx1, __shfl_xor_sync(0xffffffffu, mx1, 2));
        float nm0 = fmaxf(mr0, mx0), nm1 = fmaxf(mr1, mx1);
        float a0 = __expf(mr0 - nm0), a1 = __expf(mr1 - nm1);
        float ls0 = 0.0f, ls1 = 0.0f;
#pragma unroll
        for (int nt = 0; nt < 16; nt++) {
            float p0 = __expf(s[nt][0] - nm0);
            float p1 = __expf(s[nt][1] - nm0);
            float p2 = __expf(s[nt][2] - nm1);
            float p3 = __expf(s[nt][3] - nm1);
            s[nt][0] = p0; s[nt][1] = p1; s[nt][2] = p2; s[nt][3] = p3;
            ls0 += p0 + p1;
            ls1 += p2 + p3;
        }
        ls0 += __shfl_xor_sync(0xffffffffu, ls0, 1);
        ls0 += __shfl_xor_sync(0xffffffffu, ls0, 2);
        ls1 += __shfl_xor_sync(0xffffffffu, ls1, 1);
        ls1 += __shfl_xor_sync(0xffffffffu, ls1, 2);
        lr0 = lr0 * a0 + ls0;
        lr1 = lr1 * a1 + ls1;
        mr0 = nm0; mr1 = nm1;
#pragma unroll
        for (int nt = 0; nt < 8; nt++) {
            o[nt][0] *= a0; o[nt][1] *= a0;
            o[nt][2] *= a1; o[nt][3] *= a1;
        }

        // ---- O += P V (2-term fp16: P exact hi/lo split, V fp16-single) ----
#pragma unroll
        for (int kk2 = 0; kk2 < 8; kk2++) {
            uint32_t pah[4], pal[4];
            split_pair_h(s[2 * kk2][0],     s[2 * kk2][1],     pah[0], pal[0]);
            split_pair_h(s[2 * kk2][2],     s[2 * kk2][3],     pah[1], pal[1]);
            split_pair_h(s[2 * kk2 + 1][0], s[2 * kk2 + 1][1], pah[2], pal[2]);
            split_pair_h(s[2 * kk2 + 1][2], s[2 * kk2 + 1][3], pah[3], pal[3]);
            int half = kk2 >> 2;
            int c16 = (kk2 & 3) * 2 + hB;
#pragma unroll
            for (int np = 0; np < 4; np++) {
                int row = rB + np * 16;
                uint32_t addr = stb + 32768 + half * 8192 + row * 128 +
                                (uint32_t)(((c16 ^ (row & 7))) << 4);
                uint32_t vb[4];
                ldm4(vb, addr);
                mma16816h(o[2 * np],     pah, vb[0], vb[1]);
                mma16816h(o[2 * np],     pal, vb[0], vb[1]);
                mma16816h(o[2 * np + 1], pah, vb[2], vb[3]);
                mma16816h(o[2 * np + 1], pal, vb[2], vb[3]);
            }
        }
    }

    // ---- epilogue: z fp16 single ----
    float inv0 = 1.0f / lr0, inv1 = 1.0f / lr1;
    int b = bh >> 3, h = bh & 7;
    size_t z0 = (size_t)(b * SEQ + gr0) * FEAT + h * 64;
    size_t z1 = (size_t)(b * SEQ + gr1) * FEAT + h * 64;
#pragma unroll
    for (int nt = 0; nt < 8; nt++) {
        int col = nt * 8 + (lane & 3) * 2;
        __half2 hp0;
        hp0.x = __float2half(o[nt][0] * inv0);
        hp0.y = __float2half(o[nt][1] * inv0);
        __half2 hp1;
        hp1.x = __float2half(o[nt][2] * inv1);
        hp1.y = __float2half(o[nt][3] * inv1);
        *(__half2*)(g_z + z0 + col) = hp0;
        *(__half2*)(g_z + z1 + col) = hp1;
    }
}

// ---------------- launch ----------------
extern "C" void kernel_launch(void* const* d_in, const int* in_sizes, int n_in,
                              void* d_out, int out_size) {
    const float* x     = (const float*)d_in[0];
    const float* gamma = (const float*)d_in[1];
    const float* beta  = (const float*)d_in[2];
    const float* WQ    = (const float*)d_in[3];
    const float* bq    = (const float*)d_in[4];
    const float* WK    = (const float*)d_in[5];
    const float* bk    = (const float*)d_in[6];
    const float* WV    = (const float*)d_in[7];
    const float* bv    = (const float*)d_in[8];
    const float* WO    = (const float*)d_in[9];
    const float* bO    = (const float*)d_in[10];
    float* out = (float*)d_out;

    (void)in_sizes; (void)n_in; (void)out_size;

    cudaFuncSetAttribute(attn_mma, cudaFuncAttributeMaxDynamicSharedMemorySize, AT_SMEM);
    cudaFuncSetAttribute(gemm_qkv_mma, cudaFuncAttributeMaxDynamicSharedMemorySize, GSMEM);
    cudaFuncSetAttribute(gemm_out_mma, cudaFuncAttributeMaxDynamicSharedMemorySize, OSMEM);

    ln_kernel<<<MTOT, 128>>>(x, gamma, beta);
    repack_qkv<<<(NQKV * FEAT) / 256, 256>>>(WQ, WK, WV);
    repack_wo<<<(FEAT * FEAT) / 256, 256>>>(WO);
    gemm_qkv_mma<<<dim3(NQKV / 128, MTOT / 128), GTHREADS, GSMEM>>>(bq, bk, bv);
    attn_mma<<<dim3(SEQ / 128, BATCH * HEADS), 256, AT_SMEM>>>();
    gemm_out_mma<<<dim3(512 / 128, MTOT / 128), GTHREADS, OSMEM>>>(bO, out);
}

// round 13
// speedup vs baseline: 1.2280x; 1.0441x over previous
#include <cuda_runtime.h>
#include <cuda_bf16.h>
#include <cuda_fp16.h>
#include <cstdint>

#define BATCH 8
#define SEQ   1024
#define FEAT  512
#define HEADS 8
#define DKDIM 64
#define TCUT  823
#define MTOT  (BATCH * SEQ)     // 8192
#define NQKV  1536

// ---------------- scratch (device globals; no runtime alloc) ----------------
__device__ __align__(256) __nv_bfloat16 g_ah[MTOT * FEAT];        // xn hi   [m][k] bf16
__device__ __align__(256) __nv_bfloat16 g_al[MTOT * FEAT];        // xn lo   bf16
__device__ __align__(256) __nv_bfloat16 g_bh[NQKV * FEAT];        // W^T hi  [n][k] bf16
__device__ __align__(256) __nv_bfloat16 g_bl[NQKV * FEAT];        // W^T lo  bf16
__device__ __align__(256) __half        g_z [MTOT * FEAT];        // z fp16  [m][k]
__device__ __align__(256) __half        g_oh[FEAT * FEAT];        // WO^T hi [n][k] fp16
__device__ __align__(256) __half        g_ol[FEAT * FEAT];        // WO^T lo fp16
// q,k: [b,h,s,d] bf16 hi/lo (exact split); v transposed [b,h,d,s] fp16 single
__device__ __align__(256) __nv_bfloat16 g_qh[64 * SEQ * DKDIM];
__device__ __align__(256) __nv_bfloat16 g_ql[64 * SEQ * DKDIM];
__device__ __align__(256) __nv_bfloat16 g_kh[64 * SEQ * DKDIM];
__device__ __align__(256) __nv_bfloat16 g_kl[64 * SEQ * DKDIM];
__device__ __align__(256) __half        g_vt[64 * DKDIM * SEQ];

// ---------------- helpers ----------------
__device__ __forceinline__ uint32_t smem_u32(const void* p) {
    uint32_t a;
    asm("{ .reg .u64 t; cvta.to.shared.u64 t, %1; cvt.u32.u64 %0, t; }" : "=r"(a) : "l"(p));
    return a;
}
__device__ __forceinline__ void ldm4(uint32_t* r, uint32_t addr) {
    asm volatile("ldmatrix.sync.aligned.m8n8.x4.shared.b16 {%0,%1,%2,%3}, [%4];"
                 : "=r"(r[0]), "=r"(r[1]), "=r"(r[2]), "=r"(r[3]) : "r"(addr));
}
__device__ __forceinline__ void mma16816(float* c, const uint32_t* a, uint32_t b0, uint32_t b1) {
    asm volatile("mma.sync.aligned.m16n8k16.row.col.f32.bf16.bf16.f32 "
                 "{%0,%1,%2,%3}, {%4,%5,%6,%7}, {%8,%9}, {%0,%1,%2,%3};"
                 : "+f"(c[0]), "+f"(c[1]), "+f"(c[2]), "+f"(c[3])
                 : "r"(a[0]), "r"(a[1]), "r"(a[2]), "r"(a[3]), "r"(b0), "r"(b1));
}
__device__ __forceinline__ void mma16816h(float* c, const uint32_t* a, uint32_t b0, uint32_t b1) {
    asm volatile("mma.sync.aligned.m16n8k16.row.col.f32.f16.f16.f32 "
                 "{%0,%1,%2,%3}, {%4,%5,%6,%7}, {%8,%9}, {%0,%1,%2,%3};"
                 : "+f"(c[0]), "+f"(c[1]), "+f"(c[2]), "+f"(c[3])
                 : "r"(a[0]), "r"(a[1]), "r"(a[2]), "r"(a[3]), "r"(b0), "r"(b1));
}
__device__ __forceinline__ uint32_t pack_f16x2(float lo, float hi) {
    uint32_t r;
    asm("cvt.rn.f16x2.f32 %0, %1, %2;" : "=r"(r) : "f"(hi), "f"(lo));
    return r;
}
__device__ __forceinline__ void split_pair_h(float x0, float x1, uint32_t& h, uint32_t& l) {
    h = pack_f16x2(x0, x1);
    __half2 hb = *reinterpret_cast<__half2*>(&h);
    l = pack_f16x2(x0 - __half2float(hb.x), x1 - __half2float(hb.y));
}
#define CP_ASYNC16(saddr, gaddr) \
    asm volatile("cp.async.ca.shared.global [%0], [%1], 16;" :: "r"(saddr), "l"(gaddr))
#define CP_COMMIT() asm volatile("cp.async.commit_group;" ::: "memory")
#define CP_WAIT0()  asm volatile("cp.async.wait_group 0;" ::: "memory")

// ---------------- LayerNorm -> bf16 hi/lo ----------------
__global__ __launch_bounds__(128) void ln_kernel(const float* __restrict__ x,
                                                 const float* __restrict__ gamma,
                                                 const float* __restrict__ beta) {
    int row = blockIdx.x;
    int tid = threadIdx.x;
    const float4 xv = *(const float4*)(x + (size_t)row * FEAT + tid * 4);
    float s  = xv.x + xv.y + xv.z + xv.w;
    float ss = xv.x * xv.x + xv.y * xv.y + xv.z * xv.z + xv.w * xv.w;
#pragma unroll
    for (int o = 16; o > 0; o >>= 1) {
        s  += __shfl_xor_sync(0xffffffffu, s, o);
        ss += __shfl_xor_sync(0xffffffffu, ss, o);
    }
    __shared__ float ws[4], wss[4];
    if ((tid & 31) == 0) { ws[tid >> 5] = s; wss[tid >> 5] = ss; }
    __syncthreads();
    float st  = ws[0] + ws[1] + ws[2] + ws[3];
    float sst = wss[0] + wss[1] + wss[2] + wss[3];
    float mu   = st * (1.0f / FEAT);
    float var  = sst * (1.0f / FEAT) - mu * mu;
    float rstd = rsqrtf(var + 1e-5f);
    float4 g  = *(const float4*)(gamma + tid * 4);
    float4 be = *(const float4*)(beta + tid * 4);
    float o[4];
    o[0] = (xv.x - mu) * rstd * g.x + be.x;
    o[1] = (xv.y - mu) * rstd * g.y + be.y;
    o[2] = (xv.z - mu) * rstd * g.z + be.z;
    o[3] = (xv.w - mu) * rstd * g.w + be.w;
    size_t off = (size_t)row * FEAT + tid * 4;
#pragma unroll
    for (int i = 0; i < 4; i++) {
        __nv_bfloat16 hi = __float2bfloat16(o[i]);
        g_ah[off + i] = hi;
        g_al[off + i] = __float2bfloat16(o[i] - __bfloat162float(hi));
    }
}

// ---------------- repack fused QKV weights W^T [1536][512] bf16 hi/lo ----------------
__global__ __launch_bounds__(256) void repack_qkv(const float* __restrict__ WQ,
                                                  const float* __restrict__ WK,
                                                  const float* __restrict__ WV) {
    int idx = blockIdx.x * 256 + threadIdx.x;
    int n = idx >> 9;
    int f = idx & 511;
    int which = n >> 9;
    int h = (n >> 6) & 7;
    int d = n & 63;
    const float* W = (which == 0) ? WQ : ((which == 1) ? WK : WV);
    float v = W[((size_t)h * FEAT + f) * DKDIM + d];
    __nv_bfloat16 hi = __float2bfloat16(v);
    g_bh[idx] = hi;
    g_bl[idx] = __float2bfloat16(v - __bfloat162float(hi));
}

// ---------------- repack WO^T [512][512] fp16 hi/lo ----------------
__global__ __launch_bounds__(256) void repack_wo(const float* __restrict__ WO) {
    int idx = blockIdx.x * 256 + threadIdx.x;
    int n = idx >> 9;
    int k = idx & 511;
    float v = WO[(size_t)k * 512 + n];
    __half hi = __float2half(v);
    g_oh[idx] = hi;
    g_ol[idx] = __float2half(v - __half2float(hi));
}

// ---------------- QKV GEMM: 128x256 tile, 3-term bf16, 512 thr, 2-stage --------------
// Stage (96KB): Ah [128][64] 16KB @0, Al @16384, Bh [256][64] 32KB @32768, Bl @65536.
// Warp grid 4m x 4n; warp tile 32m x 64n. K-chunk 64 (4 k-steps), 8 chunks.
#define GSTG 98304
#define GSMEM (2 * GSTG)
#define GTHREADS 512

__device__ __forceinline__ void stage_load4(uint32_t sb, int stage, int chunk,
                                            int m0, int n0) {
    int tid = threadIdx.x;
    uint32_t base = sb + stage * GSTG;
#pragma unroll
    for (int t = 0; t < 12; t++) {
        int idx = tid + t * GTHREADS;   // 0..6143; region constant per t
        if (idx < 2048) {
            int whichA = idx >> 10;     // 0 hi, 1 lo
            int pos = idx & 1023;
            int row = pos >> 3, cu = pos & 7;
            const __nv_bfloat16* src =
                (whichA ? g_al : g_ah) + (size_t)(m0 + row) * FEAT + chunk * 64 + cu * 8;
            CP_ASYNC16(base + whichA * 16384 + row * 128 +
                       (uint32_t)((cu ^ (row & 7)) << 4), src);
        } else {
            int j = idx - 2048;         // 0..4095
            int whichB = j >> 11;       // 0 hi, 1 lo
            int pos = j & 2047;
            int row = pos >> 3, cu = pos & 7;   // row 0..255
            const __nv_bfloat16* src =
                (whichB ? g_bl : g_bh) + (size_t)(n0 + row) * FEAT + chunk * 64 + cu * 8;
            CP_ASYNC16(base + 32768 + whichB * 32768 + row * 128 +
                       (uint32_t)((cu ^ (row & 7)) << 4), src);
        }
    }
    CP_COMMIT();
}

__global__ __launch_bounds__(GTHREADS, 1) void gemm_qkv_mma(const float* __restrict__ bq,
                                                            const float* __restrict__ bk,
                                                            const float* __restrict__ bv) {
    extern __shared__ char smem[];
    uint32_t sb = smem_u32(smem);
    int tid = threadIdx.x;
    int wid = tid >> 5, lane = tid & 31;
    int wm = wid & 3, wn = wid >> 2;
    int m0 = blockIdx.y * 128;
    int n0 = blockIdx.x * 256;

    float acc[2][8][4];
#pragma unroll
    for (int mt = 0; mt < 2; mt++)
#pragma unroll
        for (int nt = 0; nt < 8; nt++)
#pragma unroll
            for (int i = 0; i < 4; i++) acc[mt][nt][i] = 0.0f;

    int rA = wm * 32 + (lane & 7) + ((lane >> 3) & 1) * 8;
    int hA = lane >> 4;
    int rB = wn * 64 + (lane & 7) + ((lane >> 4) & 1) * 8;
    int hB = (lane >> 3) & 1;

    stage_load4(sb, 0, 0, m0, n0);

    for (int c = 0; c < 8; c++) {
        CP_WAIT0();       // stage c landed (only outstanding group)
        __syncthreads();  // all warps done computing c-1 (frees buf (c+1)&1)
        if (c < 7)
            stage_load4(sb, (c + 1) & 1, c + 1, m0, n0);
        uint32_t buf = sb + (c & 1) * GSTG;
#pragma unroll
        for (int ks = 0; ks < 4; ks++) {
            uint32_t ah[2][4], al[2][4];
#pragma unroll
            for (int mt = 0; mt < 2; mt++) {
                int row = rA + mt * 16;
                int c16 = ks * 2 + hA;
                uint32_t addr = buf + row * 128 + (uint32_t)(((c16 ^ (row & 7))) << 4);
                ldm4(ah[mt], addr);
                ldm4(al[mt], addr + 16384);
            }
#pragma unroll
            for (int np = 0; np < 4; np++) {
                int row = rB + np * 16;
                int c16 = ks * 2 + hB;
                uint32_t addr = buf + 32768 + row * 128 + (uint32_t)(((c16 ^ (row & 7))) << 4);
                uint32_t bh4[4], bl4[4];
                ldm4(bh4, addr);
                ldm4(bl4, addr + 32768);
#pragma unroll
                for (int mt = 0; mt < 2; mt++) {
#pragma unroll
                    for (int sub = 0; sub < 2; sub++) {
                        int nt = np * 2 + sub;
                        int sel = sub * 2;
                        mma16816(acc[mt][nt], ah[mt], bh4[sel], bh4[sel + 1]);
                        mma16816(acc[mt][nt], ah[mt], bl4[sel], bl4[sel + 1]);
                        mma16816(acc[mt][nt], al[mt], bh4[sel], bh4[sel + 1]);
                    }
                }
            }
        }
    }

    int r = lane >> 2, cp2 = (lane & 3) * 2;
#pragma unroll
    for (int nt = 0; nt < 8; nt++) {
        int col = n0 + wn * 64 + nt * 8 + cp2;
        int which = col >> 9, h = (col >> 6) & 7, d = col & 63;
        const float* bias = (which == 0) ? bq : ((which == 1) ? bk : bv);
        float b0v = bias[h * 64 + d], b1v = bias[h * 64 + d + 1];
#pragma unroll
        for (int mt = 0; mt < 2; mt++) {
#pragma unroll
            for (int half = 0; half < 2; half++) {
                int m = m0 + wm * 32 + mt * 16 + r + half * 8;
                int bb = m >> 10, ss = m & 1023;
                int bh = bb * 8 + h;
                float v0 = acc[mt][nt][half * 2 + 0] + b0v;
                float v1 = acc[mt][nt][half * 2 + 1] + b1v;
                if (which == 2) {
                    size_t vi = ((size_t)bh * 64 + d) * 1024 + ss;
                    g_vt[vi] = __float2half(v0);
                    g_vt[vi + 1024] = __float2half(v1);
                } else {
                    __nv_bfloat16 h0 = __float2bfloat16(v0);
                    __nv_bfloat16 h1 = __float2bfloat16(v1);
                    __nv_bfloat16 l0 = __float2bfloat16(v0 - __bfloat162float(h0));
                    __nv_bfloat16 l1 = __float2bfloat16(v1 - __bfloat162float(h1));
                    size_t qi = ((size_t)bh * 1024 + ss) * 64 + d;
                    __nv_bfloat162 hp; hp.x = h0; hp.y = h1;
                    __nv_bfloat162 lp; lp.x = l0; lp.y = l1;
                    if (which == 0) {
                        *(__nv_bfloat162*)(g_qh + qi) = hp;
                        *(__nv_bfloat162*)(g_ql + qi) = lp;
                    } else {
                        *(__nv_bfloat162*)(g_kh + qi) = hp;
                        *(__nv_bfloat162*)(g_kl + qi) = lp;
                    }
                }
            }
        }
    }
}

// ---------------- out GEMM: 128x256 tile, 2-term fp16, 512 thr, 2-stage --------------
// Stage (80KB): z [128][64] 16KB @0, WOh [256][64] 32KB @16384, WOl @49152.
#define OSTG 81920
#define OSMEM (2 * OSTG)

__device__ __forceinline__ void stage_load3(uint32_t sb, int stage, int chunk,
                                            int m0, int n0) {
    int tid = threadIdx.x;
    uint32_t base = sb + stage * OSTG;
#pragma unroll
    for (int t = 0; t < 10; t++) {
        int idx = tid + t * GTHREADS;   // 0..5119; region constant per t
        if (idx < 1024) {
            int row = idx >> 3, cu = idx & 7;
            const __half* src = g_z + (size_t)(m0 + row) * FEAT + chunk * 64 + cu * 8;
            CP_ASYNC16(base + row * 128 + (uint32_t)((cu ^ (row & 7)) << 4), src);
        } else {
            int j = idx - 1024;         // 0..4095
            int whichB = j >> 11;
            int pos = j & 2047;
            int row = pos >> 3, cu = pos & 7;
            const __half* src =
                (whichB ? g_ol : g_oh) + (size_t)(n0 + row) * FEAT + chunk * 64 + cu * 8;
            CP_ASYNC16(base + 16384 + whichB * 32768 + row * 128 +
                       (uint32_t)((cu ^ (row & 7)) << 4), src);
        }
    }
    CP_COMMIT();
}

__global__ __launch_bounds__(GTHREADS, 1) void gemm_out_mma(const float* __restrict__ bO,
                                                            float* __restrict__ out) {
    extern __shared__ char smem[];
    uint32_t sb = smem_u32(smem);
    int tid = threadIdx.x;
    int wid = tid >> 5, lane = tid & 31;
    int wm = wid & 3, wn = wid >> 2;
    int m0 = blockIdx.y * 128;
    int n0 = blockIdx.x * 256;

    float acc[2][8][4];
#pragma unroll
    for (int mt = 0; mt < 2; mt++)
#pragma unroll
        for (int nt = 0; nt < 8; nt++)
#pragma unroll
            for (int i = 0; i < 4; i++) acc[mt][nt][i] = 0.0f;

    int rA = wm * 32 + (lane & 7) + ((lane >> 3) & 1) * 8;
    int hA = lane >> 4;
    int rB = wn * 64 + (lane & 7) + ((lane >> 4) & 1) * 8;
    int hB = (lane >> 3) & 1;

    stage_load3(sb, 0, 0, m0, n0);

    for (int c = 0; c < 8; c++) {
        CP_WAIT0();
        __syncthreads();
        if (c < 7)
            stage_load3(sb, (c + 1) & 1, c + 1, m0, n0);
        uint32_t buf = sb + (c & 1) * OSTG;
#pragma unroll
        for (int ks = 0; ks < 4; ks++) {
            uint32_t ah[2][4];
#pragma unroll
            for (int mt = 0; mt < 2; mt++) {
                int row = rA + mt * 16;
                int c16 = ks * 2 + hA;
                ldm4(ah[mt], buf + row * 128 + (uint32_t)(((c16 ^ (row & 7))) << 4));
            }
#pragma unroll
            for (int np = 0; np < 4; np++) {
                int row = rB + np * 16;
                int c16 = ks * 2 + hB;
                uint32_t addr = buf + 16384 + row * 128 + (uint32_t)(((c16 ^ (row & 7))) << 4);
                uint32_t bh4[4], bl4[4];
                ldm4(bh4, addr);
                ldm4(bl4, addr + 32768);
#pragma unroll
                for (int mt = 0; mt < 2; mt++) {
#pragma unroll
                    for (int sub = 0; sub < 2; sub++) {
                        int nt = np * 2 + sub;
                        int sel = sub * 2;
                        mma16816h(acc[mt][nt], ah[mt], bh4[sel], bh4[sel + 1]);
                        mma16816h(acc[mt][nt], ah[mt], bl4[sel], bl4[sel + 1]);
                    }
                }
            }
        }
    }

    int r = lane >> 2, cp2 = (lane & 3) * 2;
#pragma unroll
    for (int nt = 0; nt < 8; nt++) {
        int col = n0 + wn * 64 + nt * 8 + cp2;
        float b0v = bO[col], b1v = bO[col + 1];
#pragma unroll
        for (int mt = 0; mt < 2; mt++) {
            int m = m0 + wm * 32 + mt * 16 + r;
            *(float2*)(out + (size_t)m * 512 + col) =
                make_float2(acc[mt][nt][0] + b0v, acc[mt][nt][1] + b1v);
            *(float2*)(out + (size_t)(m + 8) * 512 + col) =
                make_float2(acc[mt][nt][2] + b0v, acc[mt][nt][3] + b1v);
        }
    }
}

// ---------------- flash attention: QK 3-term bf16, PV 2-term fp16 (R12 proven) --------
#define ASTG 49152
#define AT_SMEM (32768 + 2 * ASTG)

__device__ __forceinline__ void attn_stage_load(uint32_t sb, int stage, int k0,
                                                size_t qkb, int bh) {
    int tid = threadIdx.x;
    uint32_t stb = sb + 32768 + stage * ASTG;
#pragma unroll
    for (int tt = 0; tt < 8; tt++) {
        int idx = tid + tt * 256;
        int mat = idx >> 10;
        int pos = idx & 1023;
        int row = pos >> 3, cu = pos & 7;
        const __nv_bfloat16* src = (mat ? g_kl : g_kh) + qkb + (size_t)(k0 + row) * 64 + cu * 8;
        CP_ASYNC16(stb + mat * 16384 + row * 128 + (uint32_t)((cu ^ (row & 7)) << 4), src);
    }
#pragma unroll
    for (int tt = 0; tt < 4; tt++) {
        int pos = tid + tt * 256;
        int half = pos >> 9;
        int d = (pos >> 3) & 63, cu = pos & 7;
        const __half* src = g_vt + ((size_t)bh * 64 + d) * 1024 + k0 + half * 64 + cu * 8;
        CP_ASYNC16(stb + 32768 + half * 8192 + d * 128 +
                   (uint32_t)((cu ^ (d & 7)) << 4), src);
    }
    CP_COMMIT();
}

__global__ __launch_bounds__(256, 1) void attn_mma() {
    extern __shared__ char smc[];
    uint32_t sb = smem_u32(smc);
    int tid = threadIdx.x, wid = tid >> 5, lane = tid & 31;
    int bh = blockIdx.y;
    int q0 = blockIdx.x * 128;
    size_t qkb = (size_t)bh * (SEQ * DKDIM);

    int last = q0 + 127;
    int blk_lim = (last < TCUT) ? TCUT : ((last == SEQ - 1) ? SEQ : last);
    int ntiles = (blk_lim + 127) >> 7;

#pragma unroll
    for (int t = 0; t < 8; t++) {
        int idx = tid + t * 256;
        int mat = idx >> 10;
        int pos = idx & 1023;
        int row = pos >> 3, cu = pos & 7;
        const __nv_bfloat16* src = (mat ? g_ql : g_qh) + qkb + (size_t)(q0 + row) * 64 + cu * 8;
        CP_ASYNC16(sb + mat * 16384 + row * 128 + (uint32_t)((cu ^ (row & 7)) << 4), src);
    }
    CP_COMMIT();
    attn_stage_load(sb, 0, 0, qkb, bh);

    int gr0 = q0 + wid * 16 + (lane >> 2);
    int gr1 = gr0 + 8;
    int lim0 = (gr0 < TCUT) ? TCUT : ((gr0 == SEQ - 1) ? SEQ : gr0);
    int lim1 = (gr1 < TCUT) ? TCUT : ((gr1 == SEQ - 1) ? SEQ : gr1);

    float mr0 = -1e30f, mr1 = -1e30f, lr0 = 0.0f, lr1 = 0.0f;
    float o[8][4];
#pragma unroll
    for (int nt = 0; nt < 8; nt++)
#pragma unroll
        for (int i = 0; i < 4; i++) o[nt][i] = 0.0f;

    CP_WAIT0();
    __syncthreads();

    uint32_t qf[4][2][4];
    {
        int rqa = wid * 16 + (lane & 7) + ((lane >> 3) & 1) * 8;
        int hA = lane >> 4;
#pragma unroll
        for (int kk = 0; kk < 4; kk++) {
            int c16 = kk * 2 + hA;
            uint32_t addr = sb + rqa * 128 + (uint32_t)(((c16 ^ (rqa & 7))) << 4);
            ldm4(qf[kk][0], addr);
            ldm4(qf[kk][1], addr + 16384);
        }
    }

    int rB = (lane & 7) + ((lane >> 4) & 1) * 8;
    int hB = (lane >> 3) & 1;

    for (int t = 0; t < ntiles; t++) {
        int k0 = t * 128;
        if (t > 0) {
            CP_WAIT0();
            __syncthreads();
        }
        if (t + 1 < ntiles)
            attn_stage_load(sb, (t + 1) & 1, (t + 1) * 128, qkb, bh);

        uint32_t stb = sb + 32768 + (t & 1) * ASTG;

        float s[16][4];
#pragma unroll
        for (int nt = 0; nt < 16; nt++)
#pragma unroll
            for (int i = 0; i < 4; i++) s[nt][i] = 0.0f;
#pragma unroll
        for (int kk = 0; kk < 4; kk++) {
#pragma unroll
            for (int np = 0; np < 8; np++) {
                int row = rB + np * 16;
                int c16 = kk * 2 + hB;
                uint32_t addr = stb + row * 128 + (uint32_t)(((c16 ^ (row & 7))) << 4);
                uint32_t kbh[4], kbl[4];
                ldm4(kbh, addr);
                ldm4(kbl, addr + 16384);
                mma16816(s[2 * np],     qf[kk][0], kbh[0], kbh[1]);
                mma16816(s[2 * np],     qf[kk][0], kbl[0], kbl[1]);
                mma16816(s[2 * np],     qf[kk][1], kbh[0], kbh[1]);
                mma16816(s[2 * np + 1], qf[kk][0], kbh[2], kbh[3]);
                mma16816(s[2 * np + 1], qf[kk][0], kbl[2], kbl[3]);
                mma16816(s[2 * np + 1], qf[kk][1], kbh[2], kbh[3]);
            }
        }

        float mx0 = -1e30f, mx1 = -1e30f;
#pragma unroll
        for (int nt = 0; nt < 16; nt++) {
            int kb = k0 + nt * 8 + (lane & 3) * 2;
            float v0 = (kb     < lim0) ? s[nt][0] * 0.125f : -1e30f;
            float v1 = (kb + 1 < lim0) ? s[nt][1] * 0.125f : -1e30f;
            float v2 = (kb     < lim1) ? s[nt][2] * 0.125f : -1e30f;
            float v3 = (kb + 1 < lim1) ? s[nt][3] * 0.125f : -1e30f;
            s[nt][0] = v0; s[nt][1] = v1; s[nt][2] = v2; s[nt][3] = v3;
            mx0 = fmaxf(mx0, fmaxf(v0, v1));
            mx1 = fmaxf(mx1, fmaxf(v2, v3));
        }
        mx0 = fmaxf(mx0, __shfl_xor_sync(0xffffffffu, mx0, 1));
        mx0 = fmaxf(mx0, __shfl_xor_sync(0xffffffffu, mx0, 2));
        mx1 = fmaxf(mx1, __shfl_xor_sync(0xffffffffu, mx1, 1));
        mx1 = fmaxf(mx1, __shfl_xor_sync(0xffffffffu, mx1, 2));
        float nm0 = fmaxf(mr0, mx0), nm1 = fmaxf(mr1, mx1);
        float a0 = __expf(mr0 - nm0), a1 = __expf(mr1 - nm1);
        float ls0 = 0.0f, ls1 = 0.0f;
#pragma unroll
        for (int nt = 0; nt < 16; nt++) {
            float p0 = __expf(s[nt][0] - nm0);
            float p1 = __expf(s[nt][1] - nm0);
            float p2 = __expf(s[nt][2] - nm1);
            float p3 = __expf(s[nt][3] - nm1);
            s[nt][0] = p0; s[nt][1] = p1; s[nt][2] = p2; s[nt][3] = p3;
            ls0 += p0 + p1;
            ls1 += p2 + p3;
        }
        ls0 += __shfl_xor_sync(0xffffffffu, ls0, 1);
        ls0 += __shfl_xor_sync(0xffffffffu, ls0, 2);
        ls1 += __shfl_xor_sync(0xffffffffu, ls1, 1);
        ls1 += __shfl_xor_sync(0xffffffffu, ls1, 2);
        lr0 = lr0 * a0 + ls0;
        lr1 = lr1 * a1 + ls1;
        mr0 = nm0; mr1 = nm1;
#pragma unroll
        for (int nt = 0; nt < 8; nt++) {
            o[nt][0] *= a0; o[nt][1] *= a0;
            o[nt][2] *= a1; o[nt][3] *= a1;
        }

#pragma unroll
        for (int kk2 = 0; kk2 < 8; kk2++) {
            uint32_t pah[4], pal[4];
            split_pair_h(s[2 * kk2][0],     s[2 * kk2][1],     pah[0], pal[0]);
            split_pair_h(s[2 * kk2][2],     s[2 * kk2][3],     pah[1], pal[1]);
            split_pair_h(s[2 * kk2 + 1][0], s[2 * kk2 + 1][1], pah[2], pal[2]);
            split_pair_h(s[2 * kk2 + 1][2], s[2 * kk2 + 1][3], pah[3], pal[3]);
            int half = kk2 >> 2;
            int c16 = (kk2 & 3) * 2 + hB;
#pragma unroll
            for (int np = 0; np < 4; np++) {
                int row = rB + np * 16;
                uint32_t addr = stb + 32768 + half * 8192 + row * 128 +
                                (uint32_t)(((c16 ^ (row & 7))) << 4);
                uint32_t vb[4];
                ldm4(vb, addr);
                mma16816h(o[2 * np],     pah, vb[0], vb[1]);
                mma16816h(o[2 * np],     pal, vb[0], vb[1]);
                mma16816h(o[2 * np + 1], pah, vb[2], vb[3]);
                mma16816h(o[2 * np + 1], pal, vb[2], vb[3]);
            }
        }
    }

    float inv0 = 1.0f / lr0, inv1 = 1.0f / lr1;
    int b = bh >> 3, h = bh & 7;
    size_t z0 = (size_t)(b * SEQ + gr0) * FEAT + h * 64;
    size_t z1 = (size_t)(b * SEQ + gr1) * FEAT + h * 64;
#pragma unroll
    for (int nt = 0; nt < 8; nt++) {
        int col = nt * 8 + (lane & 3) * 2;
        __half2 hp0;
        hp0.x = __float2half(o[nt][0] * inv0);
        hp0.y = __float2half(o[nt][1] * inv0);
        __half2 hp1;
        hp1.x = __float2half(o[nt][2] * inv1);
        hp1.y = __float2half(o[nt][3] * inv1);
        *(__half2*)(g_z + z0 + col) = hp0;
        *(__half2*)(g_z + z1 + col) = hp1;
    }
}

// ---------------- launch ----------------
extern "C" void kernel_launch(void* const* d_in, const int* in_sizes, int n_in,
                              void* d_out, int out_size) {
    const float* x     = (const float*)d_in[0];
    const float* gamma = (const float*)d_in[1];
    const float* beta  = (const float*)d_in[2];
    const float* WQ    = (const float*)d_in[3];
    const float* bq    = (const float*)d_in[4];
    const float* WK    = (const float*)d_in[5];
    const float* bk    = (const float*)d_in[6];
    const float* WV    = (const float*)d_in[7];
    const float* bv    = (const float*)d_in[8];
    const float* WO    = (const float*)d_in[9];
    const float* bO    = (const float*)d_in[10];
    float* out = (float*)d_out;

    (void)in_sizes; (void)n_in; (void)out_size;

    cudaFuncSetAttribute(attn_mma, cudaFuncAttributeMaxDynamicSharedMemorySize, AT_SMEM);
    cudaFuncSetAttribute(gemm_qkv_mma, cudaFuncAttributeMaxDynamicSharedMemorySize, GSMEM);
    cudaFuncSetAttribute(gemm_out_mma, cudaFuncAttributeMaxDynamicSharedMemorySize, OSMEM);

    ln_kernel<<<MTOT, 128>>>(x, gamma, beta);
    repack_qkv<<<(NQKV * FEAT) / 256, 256>>>(WQ, WK, WV);
    repack_wo<<<(FEAT * FEAT) / 256, 256>>>(WO);
    gemm_qkv_mma<<<dim3(NQKV / 256, MTOT / 128), GTHREADS, GSMEM>>>(bq, bk, bv);
    attn_mma<<<dim3(SEQ / 128, BATCH * HEADS), 256, AT_SMEM>>>();
    gemm_out_mma<<<dim3(512 / 256, MTOT / 128), GTHREADS, OSMEM>>>(bO, out);
}

// round 14
// speedup vs baseline: 1.3758x; 1.1203x over previous
#include <cuda_runtime.h>
#include <cuda_bf16.h>
#include <cuda_fp16.h>
#include <cstdint>

#define BATCH 8
#define SEQ   1024
#define FEAT  512
#define HEADS 8
#define DKDIM 64
#define TCUT  823
#define MTOT  (BATCH * SEQ)     // 8192
#define NQKV  1536

// ---------------- scratch (device globals; no runtime alloc) ----------------
__device__ __align__(256) __nv_bfloat16 g_ah[MTOT * FEAT];        // xn hi   [m][k] bf16
__device__ __align__(256) __nv_bfloat16 g_al[MTOT * FEAT];        // xn lo   bf16
__device__ __align__(256) __nv_bfloat16 g_bh[NQKV * FEAT];        // W^T hi  [n][k] bf16
__device__ __align__(256) __nv_bfloat16 g_bl[NQKV * FEAT];        // W^T lo  bf16
__device__ __align__(256) __half        g_z [MTOT * FEAT];        // z fp16  [m][k]
__device__ __align__(256) __half        g_oh[FEAT * FEAT];        // WO^T hi [n][k] fp16
__device__ __align__(256) __half        g_ol[FEAT * FEAT];        // WO^T lo fp16
// q: fp16 single; k: fp16 hi/lo exact split; v transposed [b,h,d,s] fp16 single
__device__ __align__(256) __half        g_q [64 * SEQ * DKDIM];
__device__ __align__(256) __half        g_kh[64 * SEQ * DKDIM];
__device__ __align__(256) __half        g_kl[64 * SEQ * DKDIM];
__device__ __align__(256) __half        g_vt[64 * DKDIM * SEQ];

// ---------------- helpers ----------------
__device__ __forceinline__ uint32_t smem_u32(const void* p) {
    uint32_t a;
    asm("{ .reg .u64 t; cvta.to.shared.u64 t, %1; cvt.u32.u64 %0, t; }" : "=r"(a) : "l"(p));
    return a;
}
__device__ __forceinline__ void ldm4(uint32_t* r, uint32_t addr) {
    asm volatile("ldmatrix.sync.aligned.m8n8.x4.shared.b16 {%0,%1,%2,%3}, [%4];"
                 : "=r"(r[0]), "=r"(r[1]), "=r"(r[2]), "=r"(r[3]) : "r"(addr));
}
__device__ __forceinline__ void mma16816(float* c, const uint32_t* a, uint32_t b0, uint32_t b1) {
    asm volatile("mma.sync.aligned.m16n8k16.row.col.f32.bf16.bf16.f32 "
                 "{%0,%1,%2,%3}, {%4,%5,%6,%7}, {%8,%9}, {%0,%1,%2,%3};"
                 : "+f"(c[0]), "+f"(c[1]), "+f"(c[2]), "+f"(c[3])
                 : "r"(a[0]), "r"(a[1]), "r"(a[2]), "r"(a[3]), "r"(b0), "r"(b1));
}
__device__ __forceinline__ void mma16816h(float* c, const uint32_t* a, uint32_t b0, uint32_t b1) {
    asm volatile("mma.sync.aligned.m16n8k16.row.col.f32.f16.f16.f32 "
                 "{%0,%1,%2,%3}, {%4,%5,%6,%7}, {%8,%9}, {%0,%1,%2,%3};"
                 : "+f"(c[0]), "+f"(c[1]), "+f"(c[2]), "+f"(c[3])
                 : "r"(a[0]), "r"(a[1]), "r"(a[2]), "r"(a[3]), "r"(b0), "r"(b1));
}
__device__ __forceinline__ uint32_t pack_f16x2(float lo, float hi) {
    uint32_t r;
    asm("cvt.rn.f16x2.f32 %0, %1, %2;" : "=r"(r) : "f"(hi), "f"(lo));
    return r;
}
#define CP_ASYNC16(saddr, gaddr) \
    asm volatile("cp.async.ca.shared.global [%0], [%1], 16;" :: "r"(saddr), "l"(gaddr))
#define CP_COMMIT() asm volatile("cp.async.commit_group;" ::: "memory")
#define CP_WAIT0()  asm volatile("cp.async.wait_group 0;" ::: "memory")

// ---------------- LayerNorm -> bf16 hi/lo ----------------
__global__ __launch_bounds__(128) void ln_kernel(const float* __restrict__ x,
                                                 const float* __restrict__ gamma,
                                                 const float* __restrict__ beta) {
    int row = blockIdx.x;
    int tid = threadIdx.x;
    const float4 xv = *(const float4*)(x + (size_t)row * FEAT + tid * 4);
    float s  = xv.x + xv.y + xv.z + xv.w;
    float ss = xv.x * xv.x + xv.y * xv.y + xv.z * xv.z + xv.w * xv.w;
#pragma unroll
    for (int o = 16; o > 0; o >>= 1) {
        s  += __shfl_xor_sync(0xffffffffu, s, o);
        ss += __shfl_xor_sync(0xffffffffu, ss, o);
    }
    __shared__ float ws[4], wss[4];
    if ((tid & 31) == 0) { ws[tid >> 5] = s; wss[tid >> 5] = ss; }
    __syncthreads();
    float st  = ws[0] + ws[1] + ws[2] + ws[3];
    float sst = wss[0] + wss[1] + wss[2] + wss[3];
    float mu   = st * (1.0f / FEAT);
    float var  = sst * (1.0f / FEAT) - mu * mu;
    float rstd = rsqrtf(var + 1e-5f);
    float4 g  = *(const float4*)(gamma + tid * 4);
    float4 be = *(const float4*)(beta + tid * 4);
    float o[4];
    o[0] = (xv.x - mu) * rstd * g.x + be.x;
    o[1] = (xv.y - mu) * rstd * g.y + be.y;
    o[2] = (xv.z - mu) * rstd * g.z + be.z;
    o[3] = (xv.w - mu) * rstd * g.w + be.w;
    size_t off = (size_t)row * FEAT + tid * 4;
#pragma unroll
    for (int i = 0; i < 4; i++) {
        __nv_bfloat16 hi = __float2bfloat16(o[i]);
        g_ah[off + i] = hi;
        g_al[off + i] = __float2bfloat16(o[i] - __bfloat162float(hi));
    }
}

// ---------------- repack fused QKV weights W^T [1536][512] bf16 hi/lo ----------------
__global__ __launch_bounds__(256) void repack_qkv(const float* __restrict__ WQ,
                                                  const float* __restrict__ WK,
                                                  const float* __restrict__ WV) {
    int idx = blockIdx.x * 256 + threadIdx.x;
    int n = idx >> 9;
    int f = idx & 511;
    int which = n >> 9;
    int h = (n >> 6) & 7;
    int d = n & 63;
    const float* W = (which == 0) ? WQ : ((which == 1) ? WK : WV);
    float v = W[((size_t)h * FEAT + f) * DKDIM + d];
    __nv_bfloat16 hi = __float2bfloat16(v);
    g_bh[idx] = hi;
    g_bl[idx] = __float2bfloat16(v - __bfloat162float(hi));
}

// ---------------- repack WO^T [512][512] fp16 hi/lo ----------------
__global__ __launch_bounds__(256) void repack_wo(const float* __restrict__ WO) {
    int idx = blockIdx.x * 256 + threadIdx.x;
    int n = idx >> 9;
    int k = idx & 511;
    float v = WO[(size_t)k * 512 + n];
    __half hi = __float2half(v);
    g_oh[idx] = hi;
    g_ol[idx] = __float2half(v - __half2float(hi));
}

// ---------------- QKV GEMM: 128x256 tile, 3-term bf16, 512 thr, 2-stage (R13 proven) --
#define GSTG 98304
#define GSMEM (2 * GSTG)
#define GTHREADS 512

__device__ __forceinline__ void stage_load4(uint32_t sb, int stage, int chunk,
                                            int m0, int n0) {
    int tid = threadIdx.x;
    uint32_t base = sb + stage * GSTG;
#pragma unroll
    for (int t = 0; t < 12; t++) {
        int idx = tid + t * GTHREADS;
        if (idx < 2048) {
            int whichA = idx >> 10;
            int pos = idx & 1023;
            int row = pos >> 3, cu = pos & 7;
            const __nv_bfloat16* src =
                (whichA ? g_al : g_ah) + (size_t)(m0 + row) * FEAT + chunk * 64 + cu * 8;
            CP_ASYNC16(base + whichA * 16384 + row * 128 +
                       (uint32_t)((cu ^ (row & 7)) << 4), src);
        } else {
            int j = idx - 2048;
            int whichB = j >> 11;
            int pos = j & 2047;
            int row = pos >> 3, cu = pos & 7;
            const __nv_bfloat16* src =
                (whichB ? g_bl : g_bh) + (size_t)(n0 + row) * FEAT + chunk * 64 + cu * 8;
            CP_ASYNC16(base + 32768 + whichB * 32768 + row * 128 +
                       (uint32_t)((cu ^ (row & 7)) << 4), src);
        }
    }
    CP_COMMIT();
}

__global__ __launch_bounds__(GTHREADS, 1) void gemm_qkv_mma(const float* __restrict__ bq,
                                                            const float* __restrict__ bk,
                                                            const float* __restrict__ bv) {
    extern __shared__ char smem[];
    uint32_t sb = smem_u32(smem);
    int tid = threadIdx.x;
    int wid = tid >> 5, lane = tid & 31;
    int wm = wid & 3, wn = wid >> 2;
    int m0 = blockIdx.y * 128;
    int n0 = blockIdx.x * 256;

    float acc[2][8][4];
#pragma unroll
    for (int mt = 0; mt < 2; mt++)
#pragma unroll
        for (int nt = 0; nt < 8; nt++)
#pragma unroll
            for (int i = 0; i < 4; i++) acc[mt][nt][i] = 0.0f;

    int rA = wm * 32 + (lane & 7) + ((lane >> 3) & 1) * 8;
    int hA = lane >> 4;
    int rB = wn * 64 + (lane & 7) + ((lane >> 4) & 1) * 8;
    int hB = (lane >> 3) & 1;

    stage_load4(sb, 0, 0, m0, n0);

    for (int c = 0; c < 8; c++) {
        CP_WAIT0();
        __syncthreads();
        if (c < 7)
            stage_load4(sb, (c + 1) & 1, c + 1, m0, n0);
        uint32_t buf = sb + (c & 1) * GSTG;
#pragma unroll
        for (int ks = 0; ks < 4; ks++) {
            uint32_t ah[2][4], al[2][4];
#pragma unroll
            for (int mt = 0; mt < 2; mt++) {
                int row = rA + mt * 16;
                int c16 = ks * 2 + hA;
                uint32_t addr = buf + row * 128 + (uint32_t)(((c16 ^ (row & 7))) << 4);
                ldm4(ah[mt], addr);
                ldm4(al[mt], addr + 16384);
            }
#pragma unroll
            for (int np = 0; np < 4; np++) {
                int row = rB + np * 16;
                int c16 = ks * 2 + hB;
                uint32_t addr = buf + 32768 + row * 128 + (uint32_t)(((c16 ^ (row & 7))) << 4);
                uint32_t bh4[4], bl4[4];
                ldm4(bh4, addr);
                ldm4(bl4, addr + 32768);
#pragma unroll
                for (int mt = 0; mt < 2; mt++) {
#pragma unroll
                    for (int sub = 0; sub < 2; sub++) {
                        int nt = np * 2 + sub;
                        int sel = sub * 2;
                        mma16816(acc[mt][nt], ah[mt], bh4[sel], bh4[sel + 1]);
                        mma16816(acc[mt][nt], ah[mt], bl4[sel], bl4[sel + 1]);
                        mma16816(acc[mt][nt], al[mt], bh4[sel], bh4[sel + 1]);
                    }
                }
            }
        }
    }

    int r = lane >> 2, cp2 = (lane & 3) * 2;
#pragma unroll
    for (int nt = 0; nt < 8; nt++) {
        int col = n0 + wn * 64 + nt * 8 + cp2;
        int which = col >> 9, h = (col >> 6) & 7, d = col & 63;
        const float* bias = (which == 0) ? bq : ((which == 1) ? bk : bv);
        float b0v = bias[h * 64 + d], b1v = bias[h * 64 + d + 1];
#pragma unroll
        for (int mt = 0; mt < 2; mt++) {
#pragma unroll
            for (int half = 0; half < 2; half++) {
                int m = m0 + wm * 32 + mt * 16 + r + half * 8;
                int bb = m >> 10, ss = m & 1023;
                int bh = bb * 8 + h;
                float v0 = acc[mt][nt][half * 2 + 0] + b0v;
                float v1 = acc[mt][nt][half * 2 + 1] + b1v;
                if (which == 2) {
                    size_t vi = ((size_t)bh * 64 + d) * 1024 + ss;
                    g_vt[vi] = __float2half(v0);
                    g_vt[vi + 1024] = __float2half(v1);
                } else if (which == 0) {
                    size_t qi = ((size_t)bh * 1024 + ss) * 64 + d;
                    __half2 qp; qp.x = __float2half(v0); qp.y = __float2half(v1);
                    *(__half2*)(g_q + qi) = qp;
                } else {
                    __half h0 = __float2half(v0);
                    __half h1 = __float2half(v1);
                    __half l0 = __float2half(v0 - __half2float(h0));
                    __half l1 = __float2half(v1 - __half2float(h1));
                    size_t qi = ((size_t)bh * 1024 + ss) * 64 + d;
                    __half2 hp; hp.x = h0; hp.y = h1;
                    __half2 lp; lp.x = l0; lp.y = l1;
                    *(__half2*)(g_kh + qi) = hp;
                    *(__half2*)(g_kl + qi) = lp;
                }
            }
        }
    }
}

// ---------------- out GEMM: 128x256 tile, 2-term fp16, 512 thr, 2-stage (R13) --------
#define OSTG 81920
#define OSMEM (2 * OSTG)

__device__ __forceinline__ void stage_load3(uint32_t sb, int stage, int chunk,
                                            int m0, int n0) {
    int tid = threadIdx.x;
    uint32_t base = sb + stage * OSTG;
#pragma unroll
    for (int t = 0; t < 10; t++) {
        int idx = tid + t * GTHREADS;
        if (idx < 1024) {
            int row = idx >> 3, cu = idx & 7;
            const __half* src = g_z + (size_t)(m0 + row) * FEAT + chunk * 64 + cu * 8;
            CP_ASYNC16(base + row * 128 + (uint32_t)((cu ^ (row & 7)) << 4), src);
        } else {
            int j = idx - 1024;
            int whichB = j >> 11;
            int pos = j & 2047;
            int row = pos >> 3, cu = pos & 7;
            const __half* src =
                (whichB ? g_ol : g_oh) + (size_t)(n0 + row) * FEAT + chunk * 64 + cu * 8;
            CP_ASYNC16(base + 16384 + whichB * 32768 + row * 128 +
                       (uint32_t)((cu ^ (row & 7)) << 4), src);
        }
    }
    CP_COMMIT();
}

__global__ __launch_bounds__(GTHREADS, 1) void gemm_out_mma(const float* __restrict__ bO,
                                                            float* __restrict__ out) {
    extern __shared__ char smem[];
    uint32_t sb = smem_u32(smem);
    int tid = threadIdx.x;
    int wid = tid >> 5, lane = tid & 31;
    int wm = wid & 3, wn = wid >> 2;
    int m0 = blockIdx.y * 128;
    int n0 = blockIdx.x * 256;

    float acc[2][8][4];
#pragma unroll
    for (int mt = 0; mt < 2; mt++)
#pragma unroll
        for (int nt = 0; nt < 8; nt++)
#pragma unroll
            for (int i = 0; i < 4; i++) acc[mt][nt][i] = 0.0f;

    int rA = wm * 32 + (lane & 7) + ((lane >> 3) & 1) * 8;
    int hA = lane >> 4;
    int rB = wn * 64 + (lane & 7) + ((lane >> 4) & 1) * 8;
    int hB = (lane >> 3) & 1;

    stage_load3(sb, 0, 0, m0, n0);

    for (int c = 0; c < 8; c++) {
        CP_WAIT0();
        __syncthreads();
        if (c < 7)
            stage_load3(sb, (c + 1) & 1, c + 1, m0, n0);
        uint32_t buf = sb + (c & 1) * OSTG;
#pragma unroll
        for (int ks = 0; ks < 4; ks++) {
            uint32_t ah[2][4];
#pragma unroll
            for (int mt = 0; mt < 2; mt++) {
                int row = rA + mt * 16;
                int c16 = ks * 2 + hA;
                ldm4(ah[mt], buf + row * 128 + (uint32_t)(((c16 ^ (row & 7))) << 4));
            }
#pragma unroll
            for (int np = 0; np < 4; np++) {
                int row = rB + np * 16;
                int c16 = ks * 2 + hB;
                uint32_t addr = buf + 16384 + row * 128 + (uint32_t)(((c16 ^ (row & 7))) << 4);
                uint32_t bh4[4], bl4[4];
                ldm4(bh4, addr);
                ldm4(bl4, addr + 32768);
#pragma unroll
                for (int mt = 0; mt < 2; mt++) {
#pragma unroll
                    for (int sub = 0; sub < 2; sub++) {
                        int nt = np * 2 + sub;
                        int sel = sub * 2;
                        mma16816h(acc[mt][nt], ah[mt], bh4[sel], bh4[sel + 1]);
                        mma16816h(acc[mt][nt], ah[mt], bl4[sel], bl4[sel + 1]);
                    }
                }
            }
        }
    }

    int r = lane >> 2, cp2 = (lane & 3) * 2;
#pragma unroll
    for (int nt = 0; nt < 8; nt++) {
        int col = n0 + wn * 64 + nt * 8 + cp2;
        float b0v = bO[col], b1v = bO[col + 1];
#pragma unroll
        for (int mt = 0; mt < 2; mt++) {
            int m = m0 + wm * 32 + mt * 16 + r;
            *(float2*)(out + (size_t)m * 512 + col) =
                make_float2(acc[mt][nt][0] + b0v, acc[mt][nt][1] + b1v);
            *(float2*)(out + (size_t)(m + 8) * 512 + col) =
                make_float2(acc[mt][nt][2] + b0v, acc[mt][nt][3] + b1v);
        }
    }
}

// ---------------- flash attention: QK 2-term fp16 (q single, k hi/lo), PV 1-term ------
// smem: Q fp16 16KB @0; stage s (s=0,1) @16384 + s*49152:
//       K hi @+0 (16KB), K lo @+16384, VT fp16 @+32768 (16KB)
#define ASTG 49152
#define AT_SMEM (16384 + 2 * ASTG)

__device__ __forceinline__ void attn_stage_load(uint32_t sb, int stage, int k0,
                                                size_t qkb, int bh) {
    int tid = threadIdx.x;
    uint32_t stb = sb + 16384 + stage * ASTG;
#pragma unroll
    for (int tt = 0; tt < 8; tt++) {
        int idx = tid + tt * 256;
        int mat = idx >> 10;           // 0 Kh, 1 Kl
        int pos = idx & 1023;
        int row = pos >> 3, cu = pos & 7;
        const __half* src = (mat ? g_kl : g_kh) + qkb + (size_t)(k0 + row) * 64 + cu * 8;
        CP_ASYNC16(stb + mat * 16384 + row * 128 + (uint32_t)((cu ^ (row & 7)) << 4), src);
    }
#pragma unroll
    for (int tt = 0; tt < 4; tt++) {
        int pos = tid + tt * 256;
        int half = pos >> 9;
        int d = (pos >> 3) & 63, cu = pos & 7;
        const __half* src = g_vt + ((size_t)bh * 64 + d) * 1024 + k0 + half * 64 + cu * 8;
        CP_ASYNC16(stb + 32768 + half * 8192 + d * 128 +
                   (uint32_t)((cu ^ (d & 7)) << 4), src);
    }
    CP_COMMIT();
}

__global__ __launch_bounds__(256, 1) void attn_mma() {
    extern __shared__ char smc[];
    uint32_t sb = smem_u32(smc);
    int tid = threadIdx.x, wid = tid >> 5, lane = tid & 31;
    int bh = blockIdx.y;
    int q0 = blockIdx.x * 128;
    size_t qkb = (size_t)bh * (SEQ * DKDIM);

    int last = q0 + 127;
    int blk_lim = (last < TCUT) ? TCUT : ((last == SEQ - 1) ? SEQ : last);
    int ntiles = (blk_lim + 127) >> 7;

    // ---- prologue: Q (fp16 single, 16KB) + stage 0 ----
#pragma unroll
    for (int t = 0; t < 4; t++) {
        int idx = tid + t * 256;
        int row = idx >> 3, cu = idx & 7;
        const __half* src = g_q + qkb + (size_t)(q0 + row) * 64 + cu * 8;
        CP_ASYNC16(sb + row * 128 + (uint32_t)((cu ^ (row & 7)) << 4), src);
    }
    CP_COMMIT();
    attn_stage_load(sb, 0, 0, qkb, bh);

    int gr0 = q0 + wid * 16 + (lane >> 2);
    int gr1 = gr0 + 8;
    int lim0 = (gr0 < TCUT) ? TCUT : ((gr0 == SEQ - 1) ? SEQ : gr0);
    int lim1 = (gr1 < TCUT) ? TCUT : ((gr1 == SEQ - 1) ? SEQ : gr1);

    float mr0 = -1e30f, mr1 = -1e30f, lr0 = 0.0f, lr1 = 0.0f;
    float o[8][4];
#pragma unroll
    for (int nt = 0; nt < 8; nt++)
#pragma unroll
        for (int i = 0; i < 4; i++) o[nt][i] = 0.0f;

    CP_WAIT0();
    __syncthreads();

    // ---- loop-invariant Q fragments (single) ----
    uint32_t qf[4][4];
    {
        int rqa = wid * 16 + (lane & 7) + ((lane >> 3) & 1) * 8;
        int hA = lane >> 4;
#pragma unroll
        for (int kk = 0; kk < 4; kk++) {
            int c16 = kk * 2 + hA;
            ldm4(qf[kk], sb + rqa * 128 + (uint32_t)(((c16 ^ (rqa & 7))) << 4));
        }
    }

    int rB = (lane & 7) + ((lane >> 4) & 1) * 8;
    int hB = (lane >> 3) & 1;

    for (int t = 0; t < ntiles; t++) {
        int k0 = t * 128;
        if (t > 0) {
            CP_WAIT0();
            __syncthreads();
        }
        if (t + 1 < ntiles)
            attn_stage_load(sb, (t + 1) & 1, (t + 1) * 128, qkb, bh);

        uint32_t stb = sb + 16384 + (t & 1) * ASTG;

        // ---- S = Q K^T (2-term fp16: q single, k hi/lo) ----
        float s[16][4];
#pragma unroll
        for (int nt = 0; nt < 16; nt++)
#pragma unroll
            for (int i = 0; i < 4; i++) s[nt][i] = 0.0f;
#pragma unroll
        for (int kk = 0; kk < 4; kk++) {
#pragma unroll
            for (int np = 0; np < 8; np++) {
                int row = rB + np * 16;
                int c16 = kk * 2 + hB;
                uint32_t addr = stb + row * 128 + (uint32_t)(((c16 ^ (row & 7))) << 4);
                uint32_t kbh[4], kbl[4];
                ldm4(kbh, addr);
                ldm4(kbl, addr + 16384);
                mma16816h(s[2 * np],     qf[kk], kbh[0], kbh[1]);
                mma16816h(s[2 * np],     qf[kk], kbl[0], kbl[1]);
                mma16816h(s[2 * np + 1], qf[kk], kbh[2], kbh[3]);
                mma16816h(s[2 * np + 1], qf[kk], kbl[2], kbl[3]);
            }
        }

        // ---- mask (only needed when tile reaches key >= TCUT) + online softmax ----
        float mx0 = -1e30f, mx1 = -1e30f;
        if (k0 + 128 > TCUT) {
#pragma unroll
            for (int nt = 0; nt < 16; nt++) {
                int kb = k0 + nt * 8 + (lane & 3) * 2;
                float v0 = (kb     < lim0) ? s[nt][0] * 0.125f : -1e30f;
                float v1 = (kb + 1 < lim0) ? s[nt][1] * 0.125f : -1e30f;
                float v2 = (kb     < lim1) ? s[nt][2] * 0.125f : -1e30f;
                float v3 = (kb + 1 < lim1) ? s[nt][3] * 0.125f : -1e30f;
                s[nt][0] = v0; s[nt][1] = v1; s[nt][2] = v2; s[nt][3] = v3;
                mx0 = fmaxf(mx0, fmaxf(v0, v1));
                mx1 = fmaxf(mx1, fmaxf(v2, v3));
            }
        } else {
#pragma unroll
            for (int nt = 0; nt < 16; nt++) {
                float v0 = s[nt][0] * 0.125f;
                float v1 = s[nt][1] * 0.125f;
                float v2 = s[nt][2] * 0.125f;
                float v3 = s[nt][3] * 0.125f;
                s[nt][0] = v0; s[nt][1] = v1; s[nt][2] = v2; s[nt][3] = v3;
                mx0 = fmaxf(mx0, fmaxf(v0, v1));
                mx1 = fmaxf(mx1, fmaxf(v2, v3));
            }
        }
        mx0 = fmaxf(mx0, __shfl_xor_sync(0xffffffffu, mx0, 1));
        mx0 = fmaxf(mx0, __shfl_xor_sync(0xffffffffu, mx0, 2));
        mx1 = fmaxf(mx1, __shfl_xor_sync(0xffffffffu, mx1, 1));
        mx1 = fmaxf(mx1, __shfl_xor_sync(0xffffffffu, mx1, 2));
        float nm0 = fmaxf(mr0, mx0), nm1 = fmaxf(mr1, mx1);
        float a0 = __expf(mr0 - nm0), a1 = __expf(mr1 - nm1);
        float ls0 = 0.0f, ls1 = 0.0f;
#pragma unroll
        for (int nt = 0; nt < 16; nt++) {
            float p0 = __expf(s[nt][0] - nm0);
            float p1 = __expf(s[nt][1] - nm0);
            float p2 = __expf(s[nt][2] - nm1);
            float p3 = __expf(s[nt][3] - nm1);
            s[nt][0] = p0; s[nt][1] = p1; s[nt][2] = p2; s[nt][3] = p3;
            ls0 += p0 + p1;
            ls1 += p2 + p3;
        }
        ls0 += __shfl_xor_sync(0xffffffffu, ls0, 1);
        ls0 += __shfl_xor_sync(0xffffffffu, ls0, 2);
        ls1 += __shfl_xor_sync(0xffffffffu, ls1, 1);
        ls1 += __shfl_xor_sync(0xffffffffu, ls1, 2);
        lr0 = lr0 * a0 + ls0;
        lr1 = lr1 * a1 + ls1;
        mr0 = nm0; mr1 = nm1;
#pragma unroll
        for (int nt = 0; nt < 8; nt++) {
            o[nt][0] *= a0; o[nt][1] *= a0;
            o[nt][2] *= a1; o[nt][3] *= a1;
        }

        // ---- O += P V (1-term: P fp16 single, V fp16 single) ----
#pragma unroll
        for (int kk2 = 0; kk2 < 8; kk2++) {
            uint32_t pah[4];
            pah[0] = pack_f16x2(s[2 * kk2][0],     s[2 * kk2][1]);
            pah[1] = pack_f16x2(s[2 * kk2][2],     s[2 * kk2][3]);
            pah[2] = pack_f16x2(s[2 * kk2 + 1][0], s[2 * kk2 + 1][1]);
            pah[3] = pack_f16x2(s[2 * kk2 + 1][2], s[2 * kk2 + 1][3]);
            int half = kk2 >> 2;
            int c16 = (kk2 & 3) * 2 + hB;
#pragma unroll
            for (int np = 0; np < 4; np++) {
                int row = rB + np * 16;
                uint32_t addr = stb + 32768 + half * 8192 + row * 128 +
                                (uint32_t)(((c16 ^ (row & 7))) << 4);
                uint32_t vb[4];
                ldm4(vb, addr);
                mma16816h(o[2 * np],     pah, vb[0], vb[1]);
                mma16816h(o[2 * np + 1], pah, vb[2], vb[3]);
            }
        }
    }

    // ---- epilogue: z fp16 single ----
    float inv0 = 1.0f / lr0, inv1 = 1.0f / lr1;
    int b = bh >> 3, h = bh & 7;
    size_t z0 = (size_t)(b * SEQ + gr0) * FEAT + h * 64;
    size_t z1 = (size_t)(b * SEQ + gr1) * FEAT + h * 64;
#pragma unroll
    for (int nt = 0; nt < 8; nt++) {
        int col = nt * 8 + (lane & 3) * 2;
        __half2 hp0;
        hp0.x = __float2half(o[nt][0] * inv0);
        hp0.y = __float2half(o[nt][1] * inv0);
        __half2 hp1;
        hp1.x = __float2half(o[nt][2] * inv1);
        hp1.y = __float2half(o[nt][3] * inv1);
        *(__half2*)(g_z + z0 + col) = hp0;
        *(__half2*)(g_z + z1 + col) = hp1;
    }
}

// ---------------- launch ----------------
extern "C" void kernel_launch(void* const* d_in, const int* in_sizes, int n_in,
                              void* d_out, int out_size) {
    const float* x     = (const float*)d_in[0];
    const float* gamma = (const float*)d_in[1];
    const float* beta  = (const float*)d_in[2];
    const float* WQ    = (const float*)d_in[3];
    const float* bq    = (const float*)d_in[4];
    const float* WK    = (const float*)d_in[5];
    const float* bk    = (const float*)d_in[6];
    const float* WV    = (const float*)d_in[7];
    const float* bv    = (const float*)d_in[8];
    const float* WO    = (const float*)d_in[9];
    const float* bO    = (const float*)d_in[10];
    float* out = (float*)d_out;

    (void)in_sizes; (void)n_in; (void)out_size;

    cudaFuncSetAttribute(attn_mma, cudaFuncAttributeMaxDynamicSharedMemorySize, AT_SMEM);
    cudaFuncSetAttribute(gemm_qkv_mma, cudaFuncAttributeMaxDynamicSharedMemorySize, GSMEM);
    cudaFuncSetAttribute(gemm_out_mma, cudaFuncAttributeMaxDynamicSharedMemorySize, OSMEM);

    ln_kernel<<<MTOT, 128>>>(x, gamma, beta);
    repack_qkv<<<(NQKV * FEAT) / 256, 256>>>(WQ, WK, WV);
    repack_wo<<<(FEAT * FEAT) / 256, 256>>>(WO);
    gemm_qkv_mma<<<dim3(NQKV / 256, MTOT / 128), GTHREADS, GSMEM>>>(bq, bk, bv);
    attn_mma<<<dim3(SEQ / 128, BATCH * HEADS), 256, AT_SMEM>>>();
    gemm_out_mma<<<dim3(512 / 256, MTOT / 128), GTHREADS, OSMEM>>>(bO, out);
}

// round 15
// speedup vs baseline: 1.6022x; 1.1646x over previous
#include <cuda_runtime.h>
#include <cuda_bf16.h>
#include <cuda_fp16.h>
#include <cstdint>

#define BATCH 8
#define SEQ   1024
#define FEAT  512
#define HEADS 8
#define DKDIM 64
#define TCUT  823
#define MTOT  (BATCH * SEQ)     // 8192
#define NQKV  1536

// ---------------- scratch (device globals; no runtime alloc) ----------------
__device__ __align__(256) __half g_ah[MTOT * FEAT];        // xn hi  [m][k] fp16
__device__ __align__(256) __half g_al[MTOT * FEAT];        // xn lo  fp16 (exact split)
__device__ __align__(256) __half g_bw[NQKV * FEAT];        // W^T    [n][k] fp16 single
__device__ __align__(256) __half g_z [MTOT * FEAT];        // z fp16 [m][k]
__device__ __align__(256) __half g_oh[FEAT * FEAT];        // WO^T hi [n][k] fp16
__device__ __align__(256) __half g_ol[FEAT * FEAT];        // WO^T lo fp16
// q: fp16 single; k: fp16 hi/lo exact split; v transposed [b,h,d,s] fp16 single
__device__ __align__(256) __half g_q [64 * SEQ * DKDIM];
__device__ __align__(256) __half g_kh[64 * SEQ * DKDIM];
__device__ __align__(256) __half g_kl[64 * SEQ * DKDIM];
__device__ __align__(256) __half g_vt[64 * DKDIM * SEQ];

// ---------------- helpers ----------------
__device__ __forceinline__ uint32_t smem_u32(const void* p) {
    uint32_t a;
    asm("{ .reg .u64 t; cvta.to.shared.u64 t, %1; cvt.u32.u64 %0, t; }" : "=r"(a) : "l"(p));
    return a;
}
__device__ __forceinline__ void ldm4(uint32_t* r, uint32_t addr) {
    asm volatile("ldmatrix.sync.aligned.m8n8.x4.shared.b16 {%0,%1,%2,%3}, [%4];"
                 : "=r"(r[0]), "=r"(r[1]), "=r"(r[2]), "=r"(r[3]) : "r"(addr));
}
__device__ __forceinline__ void mma16816h(float* c, const uint32_t* a, uint32_t b0, uint32_t b1) {
    asm volatile("mma.sync.aligned.m16n8k16.row.col.f32.f16.f16.f32 "
                 "{%0,%1,%2,%3}, {%4,%5,%6,%7}, {%8,%9}, {%0,%1,%2,%3};"
                 : "+f"(c[0]), "+f"(c[1]), "+f"(c[2]), "+f"(c[3])
                 : "r"(a[0]), "r"(a[1]), "r"(a[2]), "r"(a[3]), "r"(b0), "r"(b1));
}
__device__ __forceinline__ uint32_t pack_f16x2(float lo, float hi) {
    uint32_t r;
    asm("cvt.rn.f16x2.f32 %0, %1, %2;" : "=r"(r) : "f"(hi), "f"(lo));
    return r;
}
#define CP_ASYNC16(saddr, gaddr) \
    asm volatile("cp.async.ca.shared.global [%0], [%1], 16;" :: "r"(saddr), "l"(gaddr))
#define CP_COMMIT() asm volatile("cp.async.commit_group;" ::: "memory")
#define CP_WAIT0()  asm volatile("cp.async.wait_group 0;" ::: "memory")

// ---------------- LayerNorm -> fp16 hi/lo ----------------
__global__ __launch_bounds__(128) void ln_kernel(const float* __restrict__ x,
                                                 const float* __restrict__ gamma,
                                                 const float* __restrict__ beta) {
    int row = blockIdx.x;
    int tid = threadIdx.x;
    const float4 xv = *(const float4*)(x + (size_t)row * FEAT + tid * 4);
    float s  = xv.x + xv.y + xv.z + xv.w;
    float ss = xv.x * xv.x + xv.y * xv.y + xv.z * xv.z + xv.w * xv.w;
#pragma unroll
    for (int o = 16; o > 0; o >>= 1) {
        s  += __shfl_xor_sync(0xffffffffu, s, o);
        ss += __shfl_xor_sync(0xffffffffu, ss, o);
    }
    __shared__ float ws[4], wss[4];
    if ((tid & 31) == 0) { ws[tid >> 5] = s; wss[tid >> 5] = ss; }
    __syncthreads();
    float st  = ws[0] + ws[1] + ws[2] + ws[3];
    float sst = wss[0] + wss[1] + wss[2] + wss[3];
    float mu   = st * (1.0f / FEAT);
    float var  = sst * (1.0f / FEAT) - mu * mu;
    float rstd = rsqrtf(var + 1e-5f);
    float4 g  = *(const float4*)(gamma + tid * 4);
    float4 be = *(const float4*)(beta + tid * 4);
    float o[4];
    o[0] = (xv.x - mu) * rstd * g.x + be.x;
    o[1] = (xv.y - mu) * rstd * g.y + be.y;
    o[2] = (xv.z - mu) * rstd * g.z + be.z;
    o[3] = (xv.w - mu) * rstd * g.w + be.w;
    size_t off = (size_t)row * FEAT + tid * 4;
#pragma unroll
    for (int i = 0; i < 4; i++) {
        __half hi = __float2half(o[i]);
        g_ah[off + i] = hi;
        g_al[off + i] = __float2half(o[i] - __half2float(hi));
    }
}

// ---------------- repack fused QKV weights W^T [1536][512] fp16 single ----------------
__global__ __launch_bounds__(256) void repack_qkv(const float* __restrict__ WQ,
                                                  const float* __restrict__ WK,
                                                  const float* __restrict__ WV) {
    int idx = blockIdx.x * 256 + threadIdx.x;
    int n = idx >> 9;
    int f = idx & 511;
    int which = n >> 9;
    int h = (n >> 6) & 7;
    int d = n & 63;
    const float* W = (which == 0) ? WQ : ((which == 1) ? WK : WV);
    g_bw[idx] = __float2half(W[((size_t)h * FEAT + f) * DKDIM + d]);
}

// ---------------- repack WO^T [512][512] fp16 hi/lo ----------------
__global__ __launch_bounds__(256) void repack_wo(const float* __restrict__ WO) {
    int idx = blockIdx.x * 256 + threadIdx.x;
    int n = idx >> 9;
    int k = idx & 511;
    float v = WO[(size_t)k * 512 + n];
    __half hi = __float2half(v);
    g_oh[idx] = hi;
    g_ol[idx] = __float2half(v - __half2float(hi));
}

// ---------------- QKV GEMM: 128x256 tile, 2-term fp16 (A hi/lo, B single), 2-stage ----
// Stage (64KB): Ah [128][64] 16KB @0, Al @16384, B [256][64] 32KB @32768.
#define GSTG 65536
#define GSMEM (2 * GSTG)
#define GTHREADS 512

__device__ __forceinline__ void stage_load4(uint32_t sb, int stage, int chunk,
                                            int m0, int n0) {
    int tid = threadIdx.x;
    uint32_t base = sb + stage * GSTG;
#pragma unroll
    for (int t = 0; t < 8; t++) {
        int idx = tid + t * GTHREADS;   // 0..4095; region constant per t
        if (idx < 2048) {
            int whichA = idx >> 10;
            int pos = idx & 1023;
            int row = pos >> 3, cu = pos & 7;
            const __half* src =
                (whichA ? g_al : g_ah) + (size_t)(m0 + row) * FEAT + chunk * 64 + cu * 8;
            CP_ASYNC16(base + whichA * 16384 + row * 128 +
                       (uint32_t)((cu ^ (row & 7)) << 4), src);
        } else {
            int j = idx - 2048;         // 0..2047
            int row = j >> 3, cu = j & 7;   // row 0..255
            const __half* src = g_bw + (size_t)(n0 + row) * FEAT + chunk * 64 + cu * 8;
            CP_ASYNC16(base + 32768 + row * 128 +
                       (uint32_t)((cu ^ (row & 7)) << 4), src);
        }
    }
    CP_COMMIT();
}

__global__ __launch_bounds__(GTHREADS, 1) void gemm_qkv_mma(const float* __restrict__ bq,
                                                            const float* __restrict__ bk,
                                                            const float* __restrict__ bv) {
    extern __shared__ char smem[];
    uint32_t sb = smem_u32(smem);
    int tid = threadIdx.x;
    int wid = tid >> 5, lane = tid & 31;
    int wm = wid & 3, wn = wid >> 2;
    int m0 = blockIdx.y * 128;
    int n0 = blockIdx.x * 256;

    float acc[2][8][4];
#pragma unroll
    for (int mt = 0; mt < 2; mt++)
#pragma unroll
        for (int nt = 0; nt < 8; nt++)
#pragma unroll
            for (int i = 0; i < 4; i++) acc[mt][nt][i] = 0.0f;

    int rA = wm * 32 + (lane & 7) + ((lane >> 3) & 1) * 8;
    int hA = lane >> 4;
    int rB = wn * 64 + (lane & 7) + ((lane >> 4) & 1) * 8;
    int hB = (lane >> 3) & 1;

    stage_load4(sb, 0, 0, m0, n0);

    for (int c = 0; c < 8; c++) {
        CP_WAIT0();
        __syncthreads();
        if (c < 7)
            stage_load4(sb, (c + 1) & 1, c + 1, m0, n0);
        uint32_t buf = sb + (c & 1) * GSTG;
#pragma unroll
        for (int ks = 0; ks < 4; ks++) {
            uint32_t ah[2][4], al[2][4];
#pragma unroll
            for (int mt = 0; mt < 2; mt++) {
                int row = rA + mt * 16;
                int c16 = ks * 2 + hA;
                uint32_t addr = buf + row * 128 + (uint32_t)(((c16 ^ (row & 7))) << 4);
                ldm4(ah[mt], addr);
                ldm4(al[mt], addr + 16384);
            }
#pragma unroll
            for (int np = 0; np < 4; np++) {
                int row = rB + np * 16;
                int c16 = ks * 2 + hB;
                uint32_t addr = buf + 32768 + row * 128 + (uint32_t)(((c16 ^ (row & 7))) << 4);
                uint32_t b4[4];
                ldm4(b4, addr);
#pragma unroll
                for (int mt = 0; mt < 2; mt++) {
#pragma unroll
                    for (int sub = 0; sub < 2; sub++) {
                        int nt = np * 2 + sub;
                        int sel = sub * 2;
                        mma16816h(acc[mt][nt], ah[mt], b4[sel], b4[sel + 1]);
                        mma16816h(acc[mt][nt], al[mt], b4[sel], b4[sel + 1]);
                    }
                }
            }
        }
    }

    int r = lane >> 2, cp2 = (lane & 3) * 2;
#pragma unroll
    for (int nt = 0; nt < 8; nt++) {
        int col = n0 + wn * 64 + nt * 8 + cp2;
        int which = col >> 9, h = (col >> 6) & 7, d = col & 63;
        const float* bias = (which == 0) ? bq : ((which == 1) ? bk : bv);
        float b0v = bias[h * 64 + d], b1v = bias[h * 64 + d + 1];
#pragma unroll
        for (int mt = 0; mt < 2; mt++) {
#pragma unroll
            for (int half = 0; half < 2; half++) {
                int m = m0 + wm * 32 + mt * 16 + r + half * 8;
                int bb = m >> 10, ss = m & 1023;
                int bh = bb * 8 + h;
                float v0 = acc[mt][nt][half * 2 + 0] + b0v;
                float v1 = acc[mt][nt][half * 2 + 1] + b1v;
                if (which == 2) {
                    size_t vi = ((size_t)bh * 64 + d) * 1024 + ss;
                    g_vt[vi] = __float2half(v0);
                    g_vt[vi + 1024] = __float2half(v1);
                } else if (which == 0) {
                    size_t qi = ((size_t)bh * 1024 + ss) * 64 + d;
                    __half2 qp; qp.x = __float2half(v0); qp.y = __float2half(v1);
                    *(__half2*)(g_q + qi) = qp;
                } else {
                    __half h0 = __float2half(v0);
                    __half h1 = __float2half(v1);
                    __half l0 = __float2half(v0 - __half2float(h0));
                    __half l1 = __float2half(v1 - __half2float(h1));
                    size_t qi = ((size_t)bh * 1024 + ss) * 64 + d;
                    __half2 hp; hp.x = h0; hp.y = h1;
                    __half2 lp; lp.x = l0; lp.y = l1;
                    *(__half2*)(g_kh + qi) = hp;
                    *(__half2*)(g_kl + qi) = lp;
                }
            }
        }
    }
}

// ---------------- out GEMM: 128x256 tile, 2-term fp16, 512 thr, 2-stage (R13 proven) --
#define OSTG 81920
#define OSMEM (2 * OSTG)

__device__ __forceinline__ void stage_load3(uint32_t sb, int stage, int chunk,
                                            int m0, int n0) {
    int tid = threadIdx.x;
    uint32_t base = sb + stage * OSTG;
#pragma unroll
    for (int t = 0; t < 10; t++) {
        int idx = tid + t * GTHREADS;
        if (idx < 1024) {
            int row = idx >> 3, cu = idx & 7;
            const __half* src = g_z + (size_t)(m0 + row) * FEAT + chunk * 64 + cu * 8;
            CP_ASYNC16(base + row * 128 + (uint32_t)((cu ^ (row & 7)) << 4), src);
        } else {
            int j = idx - 1024;
            int whichB = j >> 11;
            int pos = j & 2047;
            int row = pos >> 3, cu = pos & 7;
            const __half* src =
                (whichB ? g_ol : g_oh) + (size_t)(n0 + row) * FEAT + chunk * 64 + cu * 8;
            CP_ASYNC16(base + 16384 + whichB * 32768 + row * 128 +
                       (uint32_t)((cu ^ (row & 7)) << 4), src);
        }
    }
    CP_COMMIT();
}

__global__ __launch_bounds__(GTHREADS, 1) void gemm_out_mma(const float* __restrict__ bO,
                                                            float* __restrict__ out) {
    extern __shared__ char smem[];
    uint32_t sb = smem_u32(smem);
    int tid = threadIdx.x;
    int wid = tid >> 5, lane = tid & 31;
    int wm = wid & 3, wn = wid >> 2;
    int m0 = blockIdx.y * 128;
    int n0 = blockIdx.x * 256;

    float acc[2][8][4];
#pragma unroll
    for (int mt = 0; mt < 2; mt++)
#pragma unroll
        for (int nt = 0; nt < 8; nt++)
#pragma unroll
            for (int i = 0; i < 4; i++) acc[mt][nt][i] = 0.0f;

    int rA = wm * 32 + (lane & 7) + ((lane >> 3) & 1) * 8;
    int hA = lane >> 4;
    int rB = wn * 64 + (lane & 7) + ((lane >> 4) & 1) * 8;
    int hB = (lane >> 3) & 1;

    stage_load3(sb, 0, 0, m0, n0);

    for (int c = 0; c < 8; c++) {
        CP_WAIT0();
        __syncthreads();
        if (c < 7)
            stage_load3(sb, (c + 1) & 1, c + 1, m0, n0);
        uint32_t buf = sb + (c & 1) * OSTG;
#pragma unroll
        for (int ks = 0; ks < 4; ks++) {
            uint32_t ah[2][4];
#pragma unroll
            for (int mt = 0; mt < 2; mt++) {
                int row = rA + mt * 16;
                int c16 = ks * 2 + hA;
                ldm4(ah[mt], buf + row * 128 + (uint32_t)(((c16 ^ (row & 7))) << 4));
            }
#pragma unroll
            for (int np = 0; np < 4; np++) {
                int row = rB + np * 16;
                int c16 = ks * 2 + hB;
                uint32_t addr = buf + 16384 + row * 128 + (uint32_t)(((c16 ^ (row & 7))) << 4);
                uint32_t bh4[4], bl4[4];
                ldm4(bh4, addr);
                ldm4(bl4, addr + 32768);
#pragma unroll
                for (int mt = 0; mt < 2; mt++) {
#pragma unroll
                    for (int sub = 0; sub < 2; sub++) {
                        int nt = np * 2 + sub;
                        int sel = sub * 2;
                        mma16816h(acc[mt][nt], ah[mt], bh4[sel], bh4[sel + 1]);
                        mma16816h(acc[mt][nt], ah[mt], bl4[sel], bl4[sel + 1]);
                    }
                }
            }
        }
    }

    int r = lane >> 2, cp2 = (lane & 3) * 2;
#pragma unroll
    for (int nt = 0; nt < 8; nt++) {
        int col = n0 + wn * 64 + nt * 8 + cp2;
        float b0v = bO[col], b1v = bO[col + 1];
#pragma unroll
        for (int mt = 0; mt < 2; mt++) {
            int m = m0 + wm * 32 + mt * 16 + r;
            *(float2*)(out + (size_t)m * 512 + col) =
                make_float2(acc[mt][nt][0] + b0v, acc[mt][nt][1] + b1v);
            *(float2*)(out + (size_t)(m + 8) * 512 + col) =
                make_float2(acc[mt][nt][2] + b0v, acc[mt][nt][3] + b1v);
        }
    }
}

// ---------------- flash attention: QK 2-term fp16, PV 1-term (R14 proven) -------------
#define ASTG 49152
#define AT_SMEM (16384 + 2 * ASTG)

__device__ __forceinline__ void attn_stage_load(uint32_t sb, int stage, int k0,
                                                size_t qkb, int bh) {
    int tid = threadIdx.x;
    uint32_t stb = sb + 16384 + stage * ASTG;
#pragma unroll
    for (int tt = 0; tt < 8; tt++) {
        int idx = tid + tt * 256;
        int mat = idx >> 10;
        int pos = idx & 1023;
        int row = pos >> 3, cu = pos & 7;
        const __half* src = (mat ? g_kl : g_kh) + qkb + (size_t)(k0 + row) * 64 + cu * 8;
        CP_ASYNC16(stb + mat * 16384 + row * 128 + (uint32_t)((cu ^ (row & 7)) << 4), src);
    }
#pragma unroll
    for (int tt = 0; tt < 4; tt++) {
        int pos = tid + tt * 256;
        int half = pos >> 9;
        int d = (pos >> 3) & 63, cu = pos & 7;
        const __half* src = g_vt + ((size_t)bh * 64 + d) * 1024 + k0 + half * 64 + cu * 8;
        CP_ASYNC16(stb + 32768 + half * 8192 + d * 128 +
                   (uint32_t)((cu ^ (d & 7)) << 4), src);
    }
    CP_COMMIT();
}

__global__ __launch_bounds__(256, 1) void attn_mma() {
    extern __shared__ char smc[];
    uint32_t sb = smem_u32(smc);
    int tid = threadIdx.x, wid = tid >> 5, lane = tid & 31;
    int bh = blockIdx.y;
    int q0 = blockIdx.x * 128;
    size_t qkb = (size_t)bh * (SEQ * DKDIM);

    int last = q0 + 127;
    int blk_lim = (last < TCUT) ? TCUT : ((last == SEQ - 1) ? SEQ : last);
    int ntiles = (blk_lim + 127) >> 7;

#pragma unroll
    for (int t = 0; t < 4; t++) {
        int idx = tid + t * 256;
        int row = idx >> 3, cu = idx & 7;
        const __half* src = g_q + qkb + (size_t)(q0 + row) * 64 + cu * 8;
        CP_ASYNC16(sb + row * 128 + (uint32_t)((cu ^ (row & 7)) << 4), src);
    }
    CP_COMMIT();
    attn_stage_load(sb, 0, 0, qkb, bh);

    int gr0 = q0 + wid * 16 + (lane >> 2);
    int gr1 = gr0 + 8;
    int lim0 = (gr0 < TCUT) ? TCUT : ((gr0 == SEQ - 1) ? SEQ : gr0);
    int lim1 = (gr1 < TCUT) ? TCUT : ((gr1 == SEQ - 1) ? SEQ : gr1);

    float mr0 = -1e30f, mr1 = -1e30f, lr0 = 0.0f, lr1 = 0.0f;
    float o[8][4];
#pragma unroll
    for (int nt = 0; nt < 8; nt++)
#pragma unroll
        for (int i = 0; i < 4; i++) o[nt][i] = 0.0f;

    CP_WAIT0();
    __syncthreads();

    uint32_t qf[4][4];
    {
        int rqa = wid * 16 + (lane & 7) + ((lane >> 3) & 1) * 8;
        int hA = lane >> 4;
#pragma unroll
        for (int kk = 0; kk < 4; kk++) {
            int c16 = kk * 2 + hA;
            ldm4(qf[kk], sb + rqa * 128 + (uint32_t)(((c16 ^ (rqa & 7))) << 4));
        }
    }

    int rB = (lane & 7) + ((lane >> 4) & 1) * 8;
    int hB = (lane >> 3) & 1;

    for (int t = 0; t < ntiles; t++) {
        int k0 = t * 128;
        if (t > 0) {
            CP_WAIT0();
            __syncthreads();
        }
        if (t + 1 < ntiles)
            attn_stage_load(sb, (t + 1) & 1, (t + 1) * 128, qkb, bh);

        uint32_t stb = sb + 16384 + (t & 1) * ASTG;

        float s[16][4];
#pragma unroll
        for (int nt = 0; nt < 16; nt++)
#pragma unroll
            for (int i = 0; i < 4; i++) s[nt][i] = 0.0f;
#pragma unroll
        for (int kk = 0; kk < 4; kk++) {
#pragma unroll
            for (int np = 0; np < 8; np++) {
                int row = rB + np * 16;
                int c16 = kk * 2 + hB;
                uint32_t addr = stb + row * 128 + (uint32_t)(((c16 ^ (row & 7))) << 4);
                uint32_t kbh[4], kbl[4];
                ldm4(kbh, addr);
                ldm4(kbl, addr + 16384);
                mma16816h(s[2 * np],     qf[kk], kbh[0], kbh[1]);
                mma16816h(s[2 * np],     qf[kk], kbl[0], kbl[1]);
                mma16816h(s[2 * np + 1], qf[kk], kbh[2], kbh[3]);
                mma16816h(s[2 * np + 1], qf[kk], kbl[2], kbl[3]);
            }
        }

        float mx0 = -1e30f, mx1 = -1e30f;
        if (k0 + 128 > TCUT) {
#pragma unroll
            for (int nt = 0; nt < 16; nt++) {
                int kb = k0 + nt * 8 + (lane & 3) * 2;
                float v0 = (kb     < lim0) ? s[nt][0] * 0.125f : -1e30f;
                float v1 = (kb + 1 < lim0) ? s[nt][1] * 0.125f : -1e30f;
                float v2 = (kb     < lim1) ? s[nt][2] * 0.125f : -1e30f;
                float v3 = (kb + 1 < lim1) ? s[nt][3] * 0.125f : -1e30f;
                s[nt][0] = v0; s[nt][1] = v1; s[nt][2] = v2; s[nt][3] = v3;
                mx0 = fmaxf(mx0, fmaxf(v0, v1));
                mx1 = fmaxf(mx1, fmaxf(v2, v3));
            }
        } else {
#pragma unroll
            for (int nt = 0; nt < 16; nt++) {
                float v0 = s[nt][0] * 0.125f;
                float v1 = s[nt][1] * 0.125f;
                float v2 = s[nt][2] * 0.125f;
                float v3 = s[nt][3] * 0.125f;
                s[nt][0] = v0; s[nt][1] = v1; s[nt][2] = v2; s[nt][3] = v3;
                mx0 = fmaxf(mx0, fmaxf(v0, v1));
                mx1 = fmaxf(mx1, fmaxf(v2, v3));
            }
        }
        mx0 = fmaxf(mx0, __shfl_xor_sync(0xffffffffu, mx0, 1));
        mx0 = fmaxf(mx0, __shfl_xor_sync(0xffffffffu, mx0, 2));
        mx1 = fmaxf(mx1, __shfl_xor_sync(0xffffffffu, mx1, 1));
        mx1 = fmaxf(mx1, __shfl_xor_sync(0xffffffffu, mx1, 2));
        float nm0 = fmaxf(mr0, mx0), nm1 = fmaxf(mr1, mx1);
        float a0 = __expf(mr0 - nm0), a1 = __expf(mr1 - nm1);
        float ls0 = 0.0f, ls1 = 0.0f;
#pragma unroll
        for (int nt = 0; nt < 16; nt++) {
            float p0 = __expf(s[nt][0] - nm0);
            float p1 = __expf(s[nt][1] - nm0);
            float p2 = __expf(s[nt][2] - nm1);
            float p3 = __expf(s[nt][3] - nm1);
            s[nt][0] = p0; s[nt][1] = p1; s[nt][2] = p2; s[nt][3] = p3;
            ls0 += p0 + p1;
            ls1 += p2 + p3;
        }
        ls0 += __shfl_xor_sync(0xffffffffu, ls0, 1);
        ls0 += __shfl_xor_sync(0xffffffffu, ls0, 2);
        ls1 += __shfl_xor_sync(0xffffffffu, ls1, 1);
        ls1 += __shfl_xor_sync(0xffffffffu, ls1, 2);
        lr0 = lr0 * a0 + ls0;
        lr1 = lr1 * a1 + ls1;
        mr0 = nm0; mr1 = nm1;
#pragma unroll
        for (int nt = 0; nt < 8; nt++) {
            o[nt][0] *= a0; o[nt][1] *= a0;
            o[nt][2] *= a1; o[nt][3] *= a1;
        }

#pragma unroll
        for (int kk2 = 0; kk2 < 8; kk2++) {
            uint32_t pah[4];
            pah[0] = pack_f16x2(s[2 * kk2][0],     s[2 * kk2][1]);
            pah[1] = pack_f16x2(s[2 * kk2][2],     s[2 * kk2][3]);
            pah[2] = pack_f16x2(s[2 * kk2 + 1][0], s[2 * kk2 + 1][1]);
            pah[3] = pack_f16x2(s[2 * kk2 + 1][2], s[2 * kk2 + 1][3]);
            int half = kk2 >> 2;
            int c16 = (kk2 & 3) * 2 + hB;
#pragma unroll
            for (int np = 0; np < 4; np++) {
                int row = rB + np * 16;
                uint32_t addr = stb + 32768 + half * 8192 + row * 128 +
                                (uint32_t)(((c16 ^ (row & 7))) << 4);
                uint32_t vb[4];
                ldm4(vb, addr);
                mma16816h(o[2 * np],     pah, vb[0], vb[1]);
                mma16816h(o[2 * np + 1], pah, vb[2], vb[3]);
            }
        }
    }

    float inv0 = 1.0f / lr0, inv1 = 1.0f / lr1;
    int b = bh >> 3, h = bh & 7;
    size_t z0 = (size_t)(b * SEQ + gr0) * FEAT + h * 64;
    size_t z1 = (size_t)(b * SEQ + gr1) * FEAT + h * 64;
#pragma unroll
    for (int nt = 0; nt < 8; nt++) {
        int col = nt * 8 + (lane & 3) * 2;
        __half2 hp0;
        hp0.x = __float2half(o[nt][0] * inv0);
        hp0.y = __float2half(o[nt][1] * inv0);
        __half2 hp1;
        hp1.x = __float2half(o[nt][2] * inv1);
        hp1.y = __float2half(o[nt][3] * inv1);
        *(__half2*)(g_z + z0 + col) = hp0;
        *(__half2*)(g_z + z1 + col) = hp1;
    }
}

// ---------------- launch ----------------
extern "C" void kernel_launch(void* const* d_in, const int* in_sizes, int n_in,
                              void* d_out, int out_size) {
    const float* x     = (const float*)d_in[0];
    const float* gamma = (const float*)d_in[1];
    const float* beta  = (const float*)d_in[2];
    const float* WQ    = (const float*)d_in[3];
    const float* bq    = (const float*)d_in[4];
    const float* WK    = (const float*)d_in[5];
    const float* bk    = (const float*)d_in[6];
    const float* WV    = (const float*)d_in[7];
    const float* bv    = (const float*)d_in[8];
    const float* WO    = (const float*)d_in[9];
    const float* bO    = (const float*)d_in[10];
    float* out = (float*)d_out;

    (void)in_sizes; (void)n_in; (void)out_size;

    cudaFuncSetAttribute(attn_mma, cudaFuncAttributeMaxDynamicSharedMemorySize, AT_SMEM);
    cudaFuncSetAttribute(gemm_qkv_mma, cudaFuncAttributeMaxDynamicSharedMemorySize, GSMEM);
    cudaFuncSetAttribute(gemm_out_mma, cudaFuncAttributeMaxDynamicSharedMemorySize, OSMEM);

    ln_kernel<<<MTOT, 128>>>(x, gamma, beta);
    repack_qkv<<<(NQKV * FEAT) / 256, 256>>>(WQ, WK, WV);
    repack_wo<<<(FEAT * FEAT) / 256, 256>>>(WO);
    gemm_qkv_mma<<<dim3(NQKV / 256, MTOT / 128), GTHREADS, GSMEM>>>(bq, bk, bv);
    attn_mma<<<dim3(SEQ / 128, BATCH * HEADS), 256, AT_SMEM>>>();
    gemm_out_mma<<<dim3(512 / 256, MTOT / 128), GTHREADS, OSMEM>>>(bO, out);
}

// round 16
// speedup vs baseline: 1.9250x; 1.2014x over previous
#include <cuda_runtime.h>
#include <cuda_fp16.h>
#include <cstdint>

#define BATCH 8
#define SEQ   1024
#define FEAT  512
#define HEADS 8
#define DKDIM 64
#define TCUT  823
#define MTOT  (BATCH * SEQ)     // 8192
#define NQKV  1536

// ---------------- scratch (device globals; no runtime alloc) ----------------
__device__ __align__(256) __half g_ah[MTOT * FEAT];        // xn hi  [m][k] fp16
__device__ __align__(256) __half g_al[MTOT * FEAT];        // xn lo  fp16 (exact split)
__device__ __align__(256) __half g_bw[NQKV * FEAT];        // W^T    [n][k] fp16 single
__device__ __align__(256) __half g_z [MTOT * FEAT];        // z fp16 [m][k]
__device__ __align__(256) __half g_wo[FEAT * FEAT];        // WO^T   [n][k] fp16 single
// q,k: fp16 single [b,h,s,d]; v transposed [b,h,d,s] fp16 single
__device__ __align__(256) __half g_q [64 * SEQ * DKDIM];
__device__ __align__(256) __half g_k [64 * SEQ * DKDIM];
__device__ __align__(256) __half g_vt[64 * DKDIM * SEQ];

// ---------------- helpers ----------------
__device__ __forceinline__ uint32_t smem_u32(const void* p) {
    uint32_t a;
    asm("{ .reg .u64 t; cvta.to.shared.u64 t, %1; cvt.u32.u64 %0, t; }" : "=r"(a) : "l"(p));
    return a;
}
__device__ __forceinline__ void ldm4(uint32_t* r, uint32_t addr) {
    asm volatile("ldmatrix.sync.aligned.m8n8.x4.shared.b16 {%0,%1,%2,%3}, [%4];"
                 : "=r"(r[0]), "=r"(r[1]), "=r"(r[2]), "=r"(r[3]) : "r"(addr));
}
__device__ __forceinline__ void mma16816h(float* c, const uint32_t* a, uint32_t b0, uint32_t b1) {
    asm volatile("mma.sync.aligned.m16n8k16.row.col.f32.f16.f16.f32 "
                 "{%0,%1,%2,%3}, {%4,%5,%6,%7}, {%8,%9}, {%0,%1,%2,%3};"
                 : "+f"(c[0]), "+f"(c[1]), "+f"(c[2]), "+f"(c[3])
                 : "r"(a[0]), "r"(a[1]), "r"(a[2]), "r"(a[3]), "r"(b0), "r"(b1));
}
__device__ __forceinline__ uint32_t pack_f16x2(float lo, float hi) {
    uint32_t r;
    asm("cvt.rn.f16x2.f32 %0, %1, %2;" : "=r"(r) : "f"(hi), "f"(lo));
    return r;
}
#define CP_ASYNC16(saddr, gaddr) \
    asm volatile("cp.async.ca.shared.global [%0], [%1], 16;" :: "r"(saddr), "l"(gaddr))
#define CP_COMMIT() asm volatile("cp.async.commit_group;" ::: "memory")
#define CP_WAIT0()  asm volatile("cp.async.wait_group 0;" ::: "memory")

// ---------------- LayerNorm -> fp16 hi/lo ----------------
__global__ __launch_bounds__(128) void ln_kernel(const float* __restrict__ x,
                                                 const float* __restrict__ gamma,
                                                 const float* __restrict__ beta) {
    int row = blockIdx.x;
    int tid = threadIdx.x;
    const float4 xv = *(const float4*)(x + (size_t)row * FEAT + tid * 4);
    float s  = xv.x + xv.y + xv.z + xv.w;
    float ss = xv.x * xv.x + xv.y * xv.y + xv.z * xv.z + xv.w * xv.w;
#pragma unroll
    for (int o = 16; o > 0; o >>= 1) {
        s  += __shfl_xor_sync(0xffffffffu, s, o);
        ss += __shfl_xor_sync(0xffffffffu, ss, o);
    }
    __shared__ float ws[4], wss[4];
    if ((tid & 31) == 0) { ws[tid >> 5] = s; wss[tid >> 5] = ss; }
    __syncthreads();
    float st  = ws[0] + ws[1] + ws[2] + ws[3];
    float sst = wss[0] + wss[1] + wss[2] + wss[3];
    float mu   = st * (1.0f / FEAT);
    float var  = sst * (1.0f / FEAT) - mu * mu;
    float rstd = rsqrtf(var + 1e-5f);
    float4 g  = *(const float4*)(gamma + tid * 4);
    float4 be = *(const float4*)(beta + tid * 4);
    float o[4];
    o[0] = (xv.x - mu) * rstd * g.x + be.x;
    o[1] = (xv.y - mu) * rstd * g.y + be.y;
    o[2] = (xv.z - mu) * rstd * g.z + be.z;
    o[3] = (xv.w - mu) * rstd * g.w + be.w;
    size_t off = (size_t)row * FEAT + tid * 4;
#pragma unroll
    for (int i = 0; i < 4; i++) {
        __half hi = __float2half(o[i]);
        g_ah[off + i] = hi;
        g_al[off + i] = __float2half(o[i] - __half2float(hi));
    }
}

// ---------------- repack fused QKV weights W^T [1536][512] fp16 single ----------------
__global__ __launch_bounds__(256) void repack_qkv(const float* __restrict__ WQ,
                                                  const float* __restrict__ WK,
                                                  const float* __restrict__ WV) {
    int idx = blockIdx.x * 256 + threadIdx.x;
    int n = idx >> 9;
    int f = idx & 511;
    int which = n >> 9;
    int h = (n >> 6) & 7;
    int d = n & 63;
    const float* W = (which == 0) ? WQ : ((which == 1) ? WK : WV);
    g_bw[idx] = __float2half(W[((size_t)h * FEAT + f) * DKDIM + d]);
}

// ---------------- repack WO^T [512][512] fp16 single ----------------
__global__ __launch_bounds__(256) void repack_wo(const float* __restrict__ WO) {
    int idx = blockIdx.x * 256 + threadIdx.x;
    int n = idx >> 9;
    int k = idx & 511;
    g_wo[idx] = __float2half(WO[(size_t)k * 512 + n]);
}

// ---------------- QKV GEMM: 128x256 tile, 2-term fp16 (A hi/lo, B single), 2-stage ----
// Stage (64KB): Ah [128][64] 16KB @0, Al @16384, B [256][64] 32KB @32768.
#define GSTG 65536
#define GSMEM (2 * GSTG)
#define GTHREADS 512

__device__ __forceinline__ void stage_load4(uint32_t sb, int stage, int chunk,
                                            int m0, int n0) {
    int tid = threadIdx.x;
    uint32_t base = sb + stage * GSTG;
#pragma unroll
    for (int t = 0; t < 8; t++) {
        int idx = tid + t * GTHREADS;
        if (idx < 2048) {
            int whichA = idx >> 10;
            int pos = idx & 1023;
            int row = pos >> 3, cu = pos & 7;
            const __half* src =
                (whichA ? g_al : g_ah) + (size_t)(m0 + row) * FEAT + chunk * 64 + cu * 8;
            CP_ASYNC16(base + whichA * 16384 + row * 128 +
                       (uint32_t)((cu ^ (row & 7)) << 4), src);
        } else {
            int j = idx - 2048;
            int row = j >> 3, cu = j & 7;
            const __half* src = g_bw + (size_t)(n0 + row) * FEAT + chunk * 64 + cu * 8;
            CP_ASYNC16(base + 32768 + row * 128 +
                       (uint32_t)((cu ^ (row & 7)) << 4), src);
        }
    }
    CP_COMMIT();
}

__global__ __launch_bounds__(GTHREADS, 1) void gemm_qkv_mma(const float* __restrict__ bq,
                                                            const float* __restrict__ bk,
                                                            const float* __restrict__ bv) {
    extern __shared__ char smem[];
    uint32_t sb = smem_u32(smem);
    int tid = threadIdx.x;
    int wid = tid >> 5, lane = tid & 31;
    int wm = wid & 3, wn = wid >> 2;
    int m0 = blockIdx.y * 128;
    int n0 = blockIdx.x * 256;

    float acc[2][8][4];
#pragma unroll
    for (int mt = 0; mt < 2; mt++)
#pragma unroll
        for (int nt = 0; nt < 8; nt++)
#pragma unroll
            for (int i = 0; i < 4; i++) acc[mt][nt][i] = 0.0f;

    int rA = wm * 32 + (lane & 7) + ((lane >> 3) & 1) * 8;
    int hA = lane >> 4;
    int rB = wn * 64 + (lane & 7) + ((lane >> 4) & 1) * 8;
    int hB = (lane >> 3) & 1;

    stage_load4(sb, 0, 0, m0, n0);

    for (int c = 0; c < 8; c++) {
        CP_WAIT0();
        __syncthreads();
        if (c < 7)
            stage_load4(sb, (c + 1) & 1, c + 1, m0, n0);
        uint32_t buf = sb + (c & 1) * GSTG;
#pragma unroll
        for (int ks = 0; ks < 4; ks++) {
            uint32_t ah[2][4], al[2][4];
#pragma unroll
            for (int mt = 0; mt < 2; mt++) {
                int row = rA + mt * 16;
                int c16 = ks * 2 + hA;
                uint32_t addr = buf + row * 128 + (uint32_t)(((c16 ^ (row & 7))) << 4);
                ldm4(ah[mt], addr);
                ldm4(al[mt], addr + 16384);
            }
#pragma unroll
            for (int np = 0; np < 4; np++) {
                int row = rB + np * 16;
                int c16 = ks * 2 + hB;
                uint32_t addr = buf + 32768 + row * 128 + (uint32_t)(((c16 ^ (row & 7))) << 4);
                uint32_t b4[4];
                ldm4(b4, addr);
#pragma unroll
                for (int mt = 0; mt < 2; mt++) {
#pragma unroll
                    for (int sub = 0; sub < 2; sub++) {
                        int nt = np * 2 + sub;
                        int sel = sub * 2;
                        mma16816h(acc[mt][nt], ah[mt], b4[sel], b4[sel + 1]);
                        mma16816h(acc[mt][nt], al[mt], b4[sel], b4[sel + 1]);
                    }
                }
            }
        }
    }

    int r = lane >> 2, cp2 = (lane & 3) * 2;
#pragma unroll
    for (int nt = 0; nt < 8; nt++) {
        int col = n0 + wn * 64 + nt * 8 + cp2;
        int which = col >> 9, h = (col >> 6) & 7, d = col & 63;
        const float* bias = (which == 0) ? bq : ((which == 1) ? bk : bv);
        float b0v = bias[h * 64 + d], b1v = bias[h * 64 + d + 1];
#pragma unroll
        for (int mt = 0; mt < 2; mt++) {
#pragma unroll
            for (int half = 0; half < 2; half++) {
                int m = m0 + wm * 32 + mt * 16 + r + half * 8;
                int bb = m >> 10, ss = m & 1023;
                int bh = bb * 8 + h;
                float v0 = acc[mt][nt][half * 2 + 0] + b0v;
                float v1 = acc[mt][nt][half * 2 + 1] + b1v;
                if (which == 2) {
                    size_t vi = ((size_t)bh * 64 + d) * 1024 + ss;
                    g_vt[vi] = __float2half(v0);
                    g_vt[vi + 1024] = __float2half(v1);
                } else {
                    size_t qi = ((size_t)bh * 1024 + ss) * 64 + d;
                    __half2 qp; qp.x = __float2half(v0); qp.y = __float2half(v1);
                    *(__half2*)(((which == 0) ? g_q : g_k) + qi) = qp;
                }
            }
        }
    }
}

// ---------------- out GEMM: 128x256 tile, 1-term fp16 (z single, WO single), 2-stage --
// Stage (48KB): z [128][64] 16KB @0, WO [256][64] 32KB @16384.
#define OSTG 49152
#define OSMEM (2 * OSTG)

__device__ __forceinline__ void stage_load3(uint32_t sb, int stage, int chunk,
                                            int m0, int n0) {
    int tid = threadIdx.x;
    uint32_t base = sb + stage * OSTG;
#pragma unroll
    for (int t = 0; t < 6; t++) {
        int idx = tid + t * GTHREADS;   // 0..3071
        if (idx < 1024) {
            int row = idx >> 3, cu = idx & 7;
            const __half* src = g_z + (size_t)(m0 + row) * FEAT + chunk * 64 + cu * 8;
            CP_ASYNC16(base + row * 128 + (uint32_t)((cu ^ (row & 7)) << 4), src);
        } else {
            int j = idx - 1024;         // 0..2047
            int row = j >> 3, cu = j & 7;
            const __half* src = g_wo + (size_t)(n0 + row) * FEAT + chunk * 64 + cu * 8;
            CP_ASYNC16(base + 16384 + row * 128 +
                       (uint32_t)((cu ^ (row & 7)) << 4), src);
        }
    }
    CP_COMMIT();
}

__global__ __launch_bounds__(GTHREADS, 1) void gemm_out_mma(const float* __restrict__ bO,
                                                            float* __restrict__ out) {
    extern __shared__ char smem[];
    uint32_t sb = smem_u32(smem);
    int tid = threadIdx.x;
    int wid = tid >> 5, lane = tid & 31;
    int wm = wid & 3, wn = wid >> 2;
    int m0 = blockIdx.y * 128;
    int n0 = blockIdx.x * 256;

    float acc[2][8][4];
#pragma unroll
    for (int mt = 0; mt < 2; mt++)
#pragma unroll
        for (int nt = 0; nt < 8; nt++)
#pragma unroll
            for (int i = 0; i < 4; i++) acc[mt][nt][i] = 0.0f;

    int rA = wm * 32 + (lane & 7) + ((lane >> 3) & 1) * 8;
    int hA = lane >> 4;
    int rB = wn * 64 + (lane & 7) + ((lane >> 4) & 1) * 8;
    int hB = (lane >> 3) & 1;

    stage_load3(sb, 0, 0, m0, n0);

    for (int c = 0; c < 8; c++) {
        CP_WAIT0();
        __syncthreads();
        if (c < 7)
            stage_load3(sb, (c + 1) & 1, c + 1, m0, n0);
        uint32_t buf = sb + (c & 1) * OSTG;
#pragma unroll
        for (int ks = 0; ks < 4; ks++) {
            uint32_t ah[2][4];
#pragma unroll
            for (int mt = 0; mt < 2; mt++) {
                int row = rA + mt * 16;
                int c16 = ks * 2 + hA;
                ldm4(ah[mt], buf + row * 128 + (uint32_t)(((c16 ^ (row & 7))) << 4));
            }
#pragma unroll
            for (int np = 0; np < 4; np++) {
                int row = rB + np * 16;
                int c16 = ks * 2 + hB;
                uint32_t addr = buf + 16384 + row * 128 + (uint32_t)(((c16 ^ (row & 7))) << 4);
                uint32_t b4[4];
                ldm4(b4, addr);
#pragma unroll
                for (int mt = 0; mt < 2; mt++) {
#pragma unroll
                    for (int sub = 0; sub < 2; sub++) {
                        int nt = np * 2 + sub;
                        int sel = sub * 2;
                        mma16816h(acc[mt][nt], ah[mt], b4[sel], b4[sel + 1]);
                    }
                }
            }
        }
    }

    int r = lane >> 2, cp2 = (lane & 3) * 2;
#pragma unroll
    for (int nt = 0; nt < 8; nt++) {
        int col = n0 + wn * 64 + nt * 8 + cp2;
        float b0v = bO[col], b1v = bO[col + 1];
#pragma unroll
        for (int mt = 0; mt < 2; mt++) {
            int m = m0 + wm * 32 + mt * 16 + r;
            *(float2*)(out + (size_t)m * 512 + col) =
                make_float2(acc[mt][nt][0] + b0v, acc[mt][nt][1] + b1v);
            *(float2*)(out + (size_t)(m + 8) * 512 + col) =
                make_float2(acc[mt][nt][2] + b0v, acc[mt][nt][3] + b1v);
        }
    }
}

// ---------------- flash attention: QK 1-term fp16, PV 1-term fp16 ---------------------
// smem: Q fp16 16KB @0; stage s (s=0,1) @16384 + s*32768:
//       K @+0 (16KB), VT @+16384 (16KB)
#define ASTG 32768
#define AT_SMEM (16384 + 2 * ASTG)

__device__ __forceinline__ void attn_stage_load(uint32_t sb, int stage, int k0,
                                                size_t qkb, int bh) {
    int tid = threadIdx.x;
    uint32_t stb = sb + 16384 + stage * ASTG;
#pragma unroll
    for (int tt = 0; tt < 4; tt++) {
        int idx = tid + tt * 256;      // 0..1023 : K tile
        int row = idx >> 3, cu = idx & 7;
        const __half* src = g_k + qkb + (size_t)(k0 + row) * 64 + cu * 8;
        CP_ASYNC16(stb + row * 128 + (uint32_t)((cu ^ (row & 7)) << 4), src);
    }
#pragma unroll
    for (int tt = 0; tt < 4; tt++) {
        int pos = tid + tt * 256;      // 0..1023 : VT tile
        int half = pos >> 9;
        int d = (pos >> 3) & 63, cu = pos & 7;
        const __half* src = g_vt + ((size_t)bh * 64 + d) * 1024 + k0 + half * 64 + cu * 8;
        CP_ASYNC16(stb + 16384 + half * 8192 + d * 128 +
                   (uint32_t)((cu ^ (d & 7)) << 4), src);
    }
    CP_COMMIT();
}

__global__ __launch_bounds__(256, 1) void attn_mma() {
    extern __shared__ char smc[];
    uint32_t sb = smem_u32(smc);
    int tid = threadIdx.x, wid = tid >> 5, lane = tid & 31;
    int bh = blockIdx.y;
    int q0 = blockIdx.x * 128;
    size_t qkb = (size_t)bh * (SEQ * DKDIM);

    int last = q0 + 127;
    int blk_lim = (last < TCUT) ? TCUT : ((last == SEQ - 1) ? SEQ : last);
    int ntiles = (blk_lim + 127) >> 7;

#pragma unroll
    for (int t = 0; t < 4; t++) {
        int idx = tid + t * 256;
        int row = idx >> 3, cu = idx & 7;
        const __half* src = g_q + qkb + (size_t)(q0 + row) * 64 + cu * 8;
        CP_ASYNC16(sb + row * 128 + (uint32_t)((cu ^ (row & 7)) << 4), src);
    }
    CP_COMMIT();
    attn_stage_load(sb, 0, 0, qkb, bh);

    int gr0 = q0 + wid * 16 + (lane >> 2);
    int gr1 = gr0 + 8;
    int lim0 = (gr0 < TCUT) ? TCUT : ((gr0 == SEQ - 1) ? SEQ : gr0);
    int lim1 = (gr1 < TCUT) ? TCUT : ((gr1 == SEQ - 1) ? SEQ : gr1);

    float mr0 = -1e30f, mr1 = -1e30f, lr0 = 0.0f, lr1 = 0.0f;
    float o[8][4];
#pragma unroll
    for (int nt = 0; nt < 8; nt++)
#pragma unroll
        for (int i = 0; i < 4; i++) o[nt][i] = 0.0f;

    CP_WAIT0();
    __syncthreads();

    uint32_t qf[4][4];
    {
        int rqa = wid * 16 + (lane & 7) + ((lane >> 3) & 1) * 8;
        int hA = lane >> 4;
#pragma unroll
        for (int kk = 0; kk < 4; kk++) {
            int c16 = kk * 2 + hA;
            ldm4(qf[kk], sb + rqa * 128 + (uint32_t)(((c16 ^ (rqa & 7))) << 4));
        }
    }

    int rB = (lane & 7) + ((lane >> 4) & 1) * 8;
    int hB = (lane >> 3) & 1;

    for (int t = 0; t < ntiles; t++) {
        int k0 = t * 128;
        if (t > 0) {
            CP_WAIT0();
            __syncthreads();
        }
        if (t + 1 < ntiles)
            attn_stage_load(sb, (t + 1) & 1, (t + 1) * 128, qkb, bh);

        uint32_t stb = sb + 16384 + (t & 1) * ASTG;

        // ---- S = Q K^T (1-term fp16) ----
        float s[16][4];
#pragma unroll
        for (int nt = 0; nt < 16; nt++)
#pragma unroll
            for (int i = 0; i < 4; i++) s[nt][i] = 0.0f;
#pragma unroll
        for (int kk = 0; kk < 4; kk++) {
#pragma unroll
            for (int np = 0; np < 8; np++) {
                int row = rB + np * 16;
                int c16 = kk * 2 + hB;
                uint32_t addr = stb + row * 128 + (uint32_t)(((c16 ^ (row & 7))) << 4);
                uint32_t kb4[4];
                ldm4(kb4, addr);
                mma16816h(s[2 * np],     qf[kk], kb4[0], kb4[1]);
                mma16816h(s[2 * np + 1], qf[kk], kb4[2], kb4[3]);
            }
        }

        // ---- mask + online softmax ----
        float mx0 = -1e30f, mx1 = -1e30f;
        if (k0 + 128 > TCUT) {
#pragma unroll
            for (int nt = 0; nt < 16; nt++) {
                int kb = k0 + nt * 8 + (lane & 3) * 2;
                float v0 = (kb     < lim0) ? s[nt][0] * 0.125f : -1e30f;
                float v1 = (kb + 1 < lim0) ? s[nt][1] * 0.125f : -1e30f;
                float v2 = (kb     < lim1) ? s[nt][2] * 0.125f : -1e30f;
                float v3 = (kb + 1 < lim1) ? s[nt][3] * 0.125f : -1e30f;
                s[nt][0] = v0; s[nt][1] = v1; s[nt][2] = v2; s[nt][3] = v3;
                mx0 = fmaxf(mx0, fmaxf(v0, v1));
                mx1 = fmaxf(mx1, fmaxf(v2, v3));
            }
        } else {
#pragma unroll
            for (int nt = 0; nt < 16; nt++) {
                float v0 = s[nt][0] * 0.125f;
                float v1 = s[nt][1] * 0.125f;
                float v2 = s[nt][2] * 0.125f;
                float v3 = s[nt][3] * 0.125f;
                s[nt][0] = v0; s[nt][1] = v1; s[nt][2] = v2; s[nt][3] = v3;
                mx0 = fmaxf(mx0, fmaxf(v0, v1));
                mx1 = fmaxf(mx1, fmaxf(v2, v3));
            }
        }
        mx0 = fmaxf(mx0, __shfl_xor_sync(0xffffffffu, mx0, 1));
        mx0 = fmaxf(mx0, __shfl_xor_sync(0xffffffffu, mx0, 2));
        mx1 = fmaxf(mx1, __shfl_xor_sync(0xffffffffu, mx1, 1));
        mx1 = fmaxf(mx1, __shfl_xor_sync(0xffffffffu, mx1, 2));
        float nm0 = fmaxf(mr0, mx0), nm1 = fmaxf(mr1, mx1);
        float a0 = __expf(mr0 - nm0), a1 = __expf(mr1 - nm1);
        float ls0 = 0.0f, ls1 = 0.0f;
#pragma unroll
        for (int nt = 0; nt < 16; nt++) {
            float p0 = __expf(s[nt][0] - nm0);
            float p1 = __expf(s[nt][1] - nm0);
            float p2 = __expf(s[nt][2] - nm1);
            float p3 = __expf(s[nt][3] - nm1);
            s[nt][0] = p0; s[nt][1] = p1; s[nt][2] = p2; s[nt][3] = p3;
            ls0 += p0 + p1;
            ls1 += p2 + p3;
        }
        ls0 += __shfl_xor_sync(0xffffffffu, ls0, 1);
        ls0 += __shfl_xor_sync(0xffffffffu, ls0, 2);
        ls1 += __shfl_xor_sync(0xffffffffu, ls1, 1);
        ls1 += __shfl_xor_sync(0xffffffffu, ls1, 2);
        lr0 = lr0 * a0 + ls0;
        lr1 = lr1 * a1 + ls1;
        mr0 = nm0; mr1 = nm1;
#pragma unroll
        for (int nt = 0; nt < 8; nt++) {
            o[nt][0] *= a0; o[nt][1] *= a0;
            o[nt][2] *= a1; o[nt][3] *= a1;
        }

        // ---- O += P V (1-term fp16) ----
#pragma unroll
        for (int kk2 = 0; kk2 < 8; kk2++) {
            uint32_t pah[4];
            pah[0] = pack_f16x2(s[2 * kk2][0],     s[2 * kk2][1]);
            pah[1] = pack_f16x2(s[2 * kk2][2],     s[2 * kk2][3]);
            pah[2] = pack_f16x2(s[2 * kk2 + 1][0], s[2 * kk2 + 1][1]);
            pah[3] = pack_f16x2(s[2 * kk2 + 1][2], s[2 * kk2 + 1][3]);
            int half = kk2 >> 2;
            int c16 = (kk2 & 3) * 2 + hB;
#pragma unroll
            for (int np = 0; np < 4; np++) {
                int row = rB + np * 16;
                uint32_t addr = stb + 16384 + half * 8192 + row * 128 +
                                (uint32_t)(((c16 ^ (row & 7))) << 4);
                uint32_t vb[4];
                ldm4(vb, addr);
                mma16816h(o[2 * np],     pah, vb[0], vb[1]);
                mma16816h(o[2 * np + 1], pah, vb[2], vb[3]);
            }
        }
    }

    float inv0 = 1.0f / lr0, inv1 = 1.0f / lr1;
    int b = bh >> 3, h = bh & 7;
    size_t z0 = (size_t)(b * SEQ + gr0) * FEAT + h * 64;
    size_t z1 = (size_t)(b * SEQ + gr1) * FEAT + h * 64;
#pragma unroll
    for (int nt = 0; nt < 8; nt++) {
        int col = nt * 8 + (lane & 3) * 2;
        __half2 hp0;
        hp0.x = __float2half(o[nt][0] * inv0);
        hp0.y = __float2half(o[nt][1] * inv0);
        __half2 hp1;
        hp1.x = __float2half(o[nt][2] * inv1);
        hp1.y = __float2half(o[nt][3] * inv1);
        *(__half2*)(g_z + z0 + col) = hp0;
        *(__half2*)(g_z + z1 + col) = hp1;
    }
}

// ---------------- launch ----------------
extern "C" void kernel_launch(void* const* d_in, const int* in_sizes, int n_in,
                              void* d_out, int out_size) {
    const float* x     = (const float*)d_in[0];
    const float* gamma = (const float*)d_in[1];
    const float* beta  = (const float*)d_in[2];
    const float* WQ    = (const float*)d_in[3];
    const float* bq    = (const float*)d_in[4];
    const float* WK    = (const float*)d_in[5];
    const float* bk    = (const float*)d_in[6];
    const float* WV    = (const float*)d_in[7];
    const float* bv    = (const float*)d_in[8];
    const float* WO    = (const float*)d_in[9];
    const float* bO    = (const float*)d_in[10];
    float* out = (float*)d_out;

    (void)in_sizes; (void)n_in; (void)out_size;

    cudaFuncSetAttribute(attn_mma, cudaFuncAttributeMaxDynamicSharedMemorySize, AT_SMEM);
    cudaFuncSetAttribute(gemm_qkv_mma, cudaFuncAttributeMaxDynamicSharedMemorySize, GSMEM);
    cudaFuncSetAttribute(gemm_out_mma, cudaFuncAttributeMaxDynamicSharedMemorySize, OSMEM);

    ln_kernel<<<MTOT, 128>>>(x, gamma, beta);
    repack_qkv<<<(NQKV * FEAT) / 256, 256>>>(WQ, WK, WV);
    repack_wo<<<(FEAT * FEAT) / 256, 256>>>(WO);
    gemm_qkv_mma<<<dim3(NQKV / 256, MTOT / 128), GTHREADS, GSMEM>>>(bq, bk, bv);
    attn_mma<<<dim3(SEQ / 128, BATCH * HEADS), 256, AT_SMEM>>>();
    gemm_out_mma<<<dim3(512 / 256, MTOT / 128), GTHREADS, OSMEM>>>(bO, out);
}

// round 17
// speedup vs baseline: 1.9976x; 1.0377x over previous
#include <cuda_runtime.h>
#include <cuda_fp16.h>
#include <cstdint>

#define BATCH 8
#define SEQ   1024
#define FEAT  512
#define HEADS 8
#define DKDIM 64
#define TCUT  823
#define MTOT  (BATCH * SEQ)     // 8192
#define NQKV  1536

// ---------------- scratch (device globals; no runtime alloc) ----------------
__device__ __align__(256) __half g_ah[MTOT * FEAT];        // xn hi  [m][k] fp16
__device__ __align__(256) __half g_al[MTOT * FEAT];        // xn lo  fp16 (exact split)
__device__ __align__(256) __half g_bw[NQKV * FEAT];        // W^T    [n][k] fp16 single
__device__ __align__(256) __half g_z [MTOT * FEAT];        // z fp16 [m][k]
__device__ __align__(256) __half g_wo[FEAT * FEAT];        // WO^T   [n][k] fp16 single
// q,k: fp16 single [b,h,s,d]; v transposed [b,h,d,s] fp16 single
__device__ __align__(256) __half g_q [64 * SEQ * DKDIM];
__device__ __align__(256) __half g_k [64 * SEQ * DKDIM];
__device__ __align__(256) __half g_vt[64 * DKDIM * SEQ];

// ---------------- helpers ----------------
__device__ __forceinline__ uint32_t smem_u32(const void* p) {
    uint32_t a;
    asm("{ .reg .u64 t; cvta.to.shared.u64 t, %1; cvt.u32.u64 %0, t; }" : "=r"(a) : "l"(p));
    return a;
}
__device__ __forceinline__ void ldm4(uint32_t* r, uint32_t addr) {
    asm volatile("ldmatrix.sync.aligned.m8n8.x4.shared.b16 {%0,%1,%2,%3}, [%4];"
                 : "=r"(r[0]), "=r"(r[1]), "=r"(r[2]), "=r"(r[3]) : "r"(addr));
}
__device__ __forceinline__ void mma16816h(float* c, const uint32_t* a, uint32_t b0, uint32_t b1) {
    asm volatile("mma.sync.aligned.m16n8k16.row.col.f32.f16.f16.f32 "
                 "{%0,%1,%2,%3}, {%4,%5,%6,%7}, {%8,%9}, {%0,%1,%2,%3};"
                 : "+f"(c[0]), "+f"(c[1]), "+f"(c[2]), "+f"(c[3])
                 : "r"(a[0]), "r"(a[1]), "r"(a[2]), "r"(a[3]), "r"(b0), "r"(b1));
}
__device__ __forceinline__ uint32_t pack_f16x2(float lo, float hi) {
    uint32_t r;
    asm("cvt.rn.f16x2.f32 %0, %1, %2;" : "=r"(r) : "f"(hi), "f"(lo));
    return r;
}
#define CP_ASYNC16(saddr, gaddr) \
    asm volatile("cp.async.ca.shared.global [%0], [%1], 16;" :: "r"(saddr), "l"(gaddr))
#define CP_COMMIT() asm volatile("cp.async.commit_group;" ::: "memory")
#define CP_WAIT0()  asm volatile("cp.async.wait_group 0;" ::: "memory")

// ---------------- prep: LN (blocks 0..8191) + repack W (6144) + repack WO (2048) ------
__global__ __launch_bounds__(128) void prep_kernel(const float* __restrict__ x,
                                                   const float* __restrict__ gamma,
                                                   const float* __restrict__ beta,
                                                   const float* __restrict__ WQ,
                                                   const float* __restrict__ WK,
                                                   const float* __restrict__ WV,
                                                   const float* __restrict__ WO) {
    int bid = blockIdx.x;
    int tid = threadIdx.x;
    if (bid < MTOT) {
        // ---- LayerNorm row -> fp16 hi/lo ----
        int row = bid;
        const float4 xv = *(const float4*)(x + (size_t)row * FEAT + tid * 4);
        float s  = xv.x + xv.y + xv.z + xv.w;
        float ss = xv.x * xv.x + xv.y * xv.y + xv.z * xv.z + xv.w * xv.w;
#pragma unroll
        for (int o = 16; o > 0; o >>= 1) {
            s  += __shfl_xor_sync(0xffffffffu, s, o);
            ss += __shfl_xor_sync(0xffffffffu, ss, o);
        }
        __shared__ float ws[4], wss[4];
        if ((tid & 31) == 0) { ws[tid >> 5] = s; wss[tid >> 5] = ss; }
        __syncthreads();
        float st  = ws[0] + ws[1] + ws[2] + ws[3];
        float sst = wss[0] + wss[1] + wss[2] + wss[3];
        float mu   = st * (1.0f / FEAT);
        float var  = sst * (1.0f / FEAT) - mu * mu;
        float rstd = rsqrtf(var + 1e-5f);
        float4 g  = *(const float4*)(gamma + tid * 4);
        float4 be = *(const float4*)(beta + tid * 4);
        float o[4];
        o[0] = (xv.x - mu) * rstd * g.x + be.x;
        o[1] = (xv.y - mu) * rstd * g.y + be.y;
        o[2] = (xv.z - mu) * rstd * g.z + be.z;
        o[3] = (xv.w - mu) * rstd * g.w + be.w;
        size_t off = (size_t)row * FEAT + tid * 4;
#pragma unroll
        for (int i = 0; i < 4; i++) {
            __half hi = __float2half(o[i]);
            g_ah[off + i] = hi;
            g_al[off + i] = __float2half(o[i] - __half2float(hi));
        }
    } else if (bid < MTOT + 6144) {
        // ---- repack fused QKV weights W^T [1536][512] fp16 single ----
        int idx = (bid - MTOT) * 128 + tid;     // 0..786431
        int n = idx >> 9;
        int f = idx & 511;
        int which = n >> 9;
        int h = (n >> 6) & 7;
        int d = n & 63;
        const float* W = (which == 0) ? WQ : ((which == 1) ? WK : WV);
        g_bw[idx] = __float2half(W[((size_t)h * FEAT + f) * DKDIM + d]);
    } else {
        // ---- repack WO^T [512][512] fp16 single ----
        int idx = (bid - MTOT - 6144) * 128 + tid;   // 0..262143
        int n = idx >> 9;
        int k = idx & 511;
        g_wo[idx] = __float2half(WO[(size_t)k * 512 + n]);
    }
}

// ---------------- QKV GEMM: 128x256 tile, 2-term for q/k cols, 1-term for v cols ------
// Stage (64KB): Ah [128][64] 16KB @0, Al @16384, B [256][64] 32KB @32768.
#define GSTG 65536
#define GSMEM (2 * GSTG)
#define GTHREADS 512

__device__ __forceinline__ void stage_load4(uint32_t sb, int stage, int chunk,
                                            int m0, int n0) {
    int tid = threadIdx.x;
    uint32_t base = sb + stage * GSTG;
#pragma unroll
    for (int t = 0; t < 8; t++) {
        int idx = tid + t * GTHREADS;
        if (idx < 2048) {
            int whichA = idx >> 10;
            int pos = idx & 1023;
            int row = pos >> 3, cu = pos & 7;
            const __half* src =
                (whichA ? g_al : g_ah) + (size_t)(m0 + row) * FEAT + chunk * 64 + cu * 8;
            CP_ASYNC16(base + whichA * 16384 + row * 128 +
                       (uint32_t)((cu ^ (row & 7)) << 4), src);
        } else {
            int j = idx - 2048;
            int row = j >> 3, cu = j & 7;
            const __half* src = g_bw + (size_t)(n0 + row) * FEAT + chunk * 64 + cu * 8;
            CP_ASYNC16(base + 32768 + row * 128 +
                       (uint32_t)((cu ^ (row & 7)) << 4), src);
        }
    }
    CP_COMMIT();
}

__global__ __launch_bounds__(GTHREADS, 1) void gemm_qkv_mma(const float* __restrict__ bq,
                                                            const float* __restrict__ bk,
                                                            const float* __restrict__ bv) {
    extern __shared__ char smem[];
    uint32_t sb = smem_u32(smem);
    int tid = threadIdx.x;
    int wid = tid >> 5, lane = tid & 31;
    int wm = wid & 3, wn = wid >> 2;
    int m0 = blockIdx.y * 128;
    int n0 = blockIdx.x * 256;
    const bool two_term = (n0 < 1024);   // v columns (>=1024) use 1-term

    float acc[2][8][4];
#pragma unroll
    for (int mt = 0; mt < 2; mt++)
#pragma unroll
        for (int nt = 0; nt < 8; nt++)
#pragma unroll
            for (int i = 0; i < 4; i++) acc[mt][nt][i] = 0.0f;

    int rA = wm * 32 + (lane & 7) + ((lane >> 3) & 1) * 8;
    int hA = lane >> 4;
    int rB = wn * 64 + (lane & 7) + ((lane >> 4) & 1) * 8;
    int hB = (lane >> 3) & 1;

    stage_load4(sb, 0, 0, m0, n0);

    for (int c = 0; c < 8; c++) {
        CP_WAIT0();
        __syncthreads();
        if (c < 7)
            stage_load4(sb, (c + 1) & 1, c + 1, m0, n0);
        uint32_t buf = sb + (c & 1) * GSTG;
#pragma unroll
        for (int ks = 0; ks < 4; ks++) {
            uint32_t ah[2][4], al[2][4];
#pragma unroll
            for (int mt = 0; mt < 2; mt++) {
                int row = rA + mt * 16;
                int c16 = ks * 2 + hA;
                uint32_t addr = buf + row * 128 + (uint32_t)(((c16 ^ (row & 7))) << 4);
                ldm4(ah[mt], addr);
                if (two_term) ldm4(al[mt], addr + 16384);
            }
#pragma unroll
            for (int np = 0; np < 4; np++) {
                int row = rB + np * 16;
                int c16 = ks * 2 + hB;
                uint32_t addr = buf + 32768 + row * 128 + (uint32_t)(((c16 ^ (row & 7))) << 4);
                uint32_t b4[4];
                ldm4(b4, addr);
#pragma unroll
                for (int mt = 0; mt < 2; mt++) {
#pragma unroll
                    for (int sub = 0; sub < 2; sub++) {
                        int nt = np * 2 + sub;
                        int sel = sub * 2;
                        mma16816h(acc[mt][nt], ah[mt], b4[sel], b4[sel + 1]);
                        if (two_term)
                            mma16816h(acc[mt][nt], al[mt], b4[sel], b4[sel + 1]);
                    }
                }
            }
        }
    }

    int r = lane >> 2, cp2 = (lane & 3) * 2;
#pragma unroll
    for (int nt = 0; nt < 8; nt++) {
        int col = n0 + wn * 64 + nt * 8 + cp2;
        int which = col >> 9, h = (col >> 6) & 7, d = col & 63;
        const float* bias = (which == 0) ? bq : ((which == 1) ? bk : bv);
        float b0v = bias[h * 64 + d], b1v = bias[h * 64 + d + 1];
#pragma unroll
        for (int mt = 0; mt < 2; mt++) {
#pragma unroll
            for (int half = 0; half < 2; half++) {
                int m = m0 + wm * 32 + mt * 16 + r + half * 8;
                int bb = m >> 10, ss = m & 1023;
                int bh = bb * 8 + h;
                float v0 = acc[mt][nt][half * 2 + 0] + b0v;
                float v1 = acc[mt][nt][half * 2 + 1] + b1v;
                if (which == 2) {
                    size_t vi = ((size_t)bh * 64 + d) * 1024 + ss;
                    g_vt[vi] = __float2half(v0);
                    g_vt[vi + 1024] = __float2half(v1);
                } else {
                    size_t qi = ((size_t)bh * 1024 + ss) * 64 + d;
                    __half2 qp; qp.x = __float2half(v0); qp.y = __float2half(v1);
                    *(__half2*)(((which == 0) ? g_q : g_k) + qi) = qp;
                }
            }
        }
    }
}

// ---------------- out GEMM: 128x256 tile, 1-term fp16, 2-stage (R16 proven) -----------
#define OSTG 49152
#define OSMEM (2 * OSTG)

__device__ __forceinline__ void stage_load3(uint32_t sb, int stage, int chunk,
                                            int m0, int n0) {
    int tid = threadIdx.x;
    uint32_t base = sb + stage * OSTG;
#pragma unroll
    for (int t = 0; t < 6; t++) {
        int idx = tid + t * GTHREADS;
        if (idx < 1024) {
            int row = idx >> 3, cu = idx & 7;
            const __half* src = g_z + (size_t)(m0 + row) * FEAT + chunk * 64 + cu * 8;
            CP_ASYNC16(base + row * 128 + (uint32_t)((cu ^ (row & 7)) << 4), src);
        } else {
            int j = idx - 1024;
            int row = j >> 3, cu = j & 7;
            const __half* src = g_wo + (size_t)(n0 + row) * FEAT + chunk * 64 + cu * 8;
            CP_ASYNC16(base + 16384 + row * 128 +
                       (uint32_t)((cu ^ (row & 7)) << 4), src);
        }
    }
    CP_COMMIT();
}

__global__ __launch_bounds__(GTHREADS, 1) void gemm_out_mma(const float* __restrict__ bO,
                                                            float* __restrict__ out) {
    extern __shared__ char smem[];
    uint32_t sb = smem_u32(smem);
    int tid = threadIdx.x;
    int wid = tid >> 5, lane = tid & 31;
    int wm = wid & 3, wn = wid >> 2;
    int m0 = blockIdx.y * 128;
    int n0 = blockIdx.x * 256;

    float acc[2][8][4];
#pragma unroll
    for (int mt = 0; mt < 2; mt++)
#pragma unroll
        for (int nt = 0; nt < 8; nt++)
#pragma unroll
            for (int i = 0; i < 4; i++) acc[mt][nt][i] = 0.0f;

    int rA = wm * 32 + (lane & 7) + ((lane >> 3) & 1) * 8;
    int hA = lane >> 4;
    int rB = wn * 64 + (lane & 7) + ((lane >> 4) & 1) * 8;
    int hB = (lane >> 3) & 1;

    stage_load3(sb, 0, 0, m0, n0);

    for (int c = 0; c < 8; c++) {
        CP_WAIT0();
        __syncthreads();
        if (c < 7)
            stage_load3(sb, (c + 1) & 1, c + 1, m0, n0);
        uint32_t buf = sb + (c & 1) * OSTG;
#pragma unroll
        for (int ks = 0; ks < 4; ks++) {
            uint32_t ah[2][4];
#pragma unroll
            for (int mt = 0; mt < 2; mt++) {
                int row = rA + mt * 16;
                int c16 = ks * 2 + hA;
                ldm4(ah[mt], buf + row * 128 + (uint32_t)(((c16 ^ (row & 7))) << 4));
            }
#pragma unroll
            for (int np = 0; np < 4; np++) {
                int row = rB + np * 16;
                int c16 = ks * 2 + hB;
                uint32_t addr = buf + 16384 + row * 128 + (uint32_t)(((c16 ^ (row & 7))) << 4);
                uint32_t b4[4];
                ldm4(b4, addr);
#pragma unroll
                for (int mt = 0; mt < 2; mt++) {
#pragma unroll
                    for (int sub = 0; sub < 2; sub++) {
                        int nt = np * 2 + sub;
                        int sel = sub * 2;
                        mma16816h(acc[mt][nt], ah[mt], b4[sel], b4[sel + 1]);
                    }
                }
            }
        }
    }

    int r = lane >> 2, cp2 = (lane & 3) * 2;
#pragma unroll
    for (int nt = 0; nt < 8; nt++) {
        int col = n0 + wn * 64 + nt * 8 + cp2;
        float b0v = bO[col], b1v = bO[col + 1];
#pragma unroll
        for (int mt = 0; mt < 2; mt++) {
            int m = m0 + wm * 32 + mt * 16 + r;
            *(float2*)(out + (size_t)m * 512 + col) =
                make_float2(acc[mt][nt][0] + b0v, acc[mt][nt][1] + b1v);
            *(float2*)(out + (size_t)(m + 8) * 512 + col) =
                make_float2(acc[mt][nt][2] + b0v, acc[mt][nt][3] + b1v);
        }
    }
}

// ---------------- flash attention: QK 1-term fp16, PV 1-term fp16 (R16 proven) --------
#define ASTG 32768
#define AT_SMEM (16384 + 2 * ASTG)

__device__ __forceinline__ void attn_stage_load(uint32_t sb, int stage, int k0,
                                                size_t qkb, int bh) {
    int tid = threadIdx.x;
    uint32_t stb = sb + 16384 + stage * ASTG;
#pragma unroll
    for (int tt = 0; tt < 4; tt++) {
        int idx = tid + tt * 256;
        int row = idx >> 3, cu = idx & 7;
        const __half* src = g_k + qkb + (size_t)(k0 + row) * 64 + cu * 8;
        CP_ASYNC16(stb + row * 128 + (uint32_t)((cu ^ (row & 7)) << 4), src);
    }
#pragma unroll
    for (int tt = 0; tt < 4; tt++) {
        int pos = tid + tt * 256;
        int half = pos >> 9;
        int d = (pos >> 3) & 63, cu = pos & 7;
        const __half* src = g_vt + ((size_t)bh * 64 + d) * 1024 + k0 + half * 64 + cu * 8;
        CP_ASYNC16(stb + 16384 + half * 8192 + d * 128 +
                   (uint32_t)((cu ^ (d & 7)) << 4), src);
    }
    CP_COMMIT();
}

__global__ __launch_bounds__(256, 1) void attn_mma() {
    extern __shared__ char smc[];
    uint32_t sb = smem_u32(smc);
    int tid = threadIdx.x, wid = tid >> 5, lane = tid & 31;
    int bh = blockIdx.y;
    int q0 = blockIdx.x * 128;
    size_t qkb = (size_t)bh * (SEQ * DKDIM);

    int last = q0 + 127;
    int blk_lim = (last < TCUT) ? TCUT : ((last == SEQ - 1) ? SEQ : last);
    int ntiles = (blk_lim + 127) >> 7;

#pragma unroll
    for (int t = 0; t < 4; t++) {
        int idx = tid + t * 256;
        int row = idx >> 3, cu = idx & 7;
        const __half* src = g_q + qkb + (size_t)(q0 + row) * 64 + cu * 8;
        CP_ASYNC16(sb + row * 128 + (uint32_t)((cu ^ (row & 7)) << 4), src);
    }
    CP_COMMIT();
    attn_stage_load(sb, 0, 0, qkb, bh);

    int gr0 = q0 + wid * 16 + (lane >> 2);
    int gr1 = gr0 + 8;
    int lim0 = (gr0 < TCUT) ? TCUT : ((gr0 == SEQ - 1) ? SEQ : gr0);
    int lim1 = (gr1 < TCUT) ? TCUT : ((gr1 == SEQ - 1) ? SEQ : gr1);

    float mr0 = -1e30f, mr1 = -1e30f, lr0 = 0.0f, lr1 = 0.0f;
    float o[8][4];
#pragma unroll
    for (int nt = 0; nt < 8; nt++)
#pragma unroll
        for (int i = 0; i < 4; i++) o[nt][i] = 0.0f;

    CP_WAIT0();
    __syncthreads();

    uint32_t qf[4][4];
    {
        int rqa = wid * 16 + (lane & 7) + ((lane >> 3) & 1) * 8;
        int hA = lane >> 4;
#pragma unroll
        for (int kk = 0; kk < 4; kk++) {
            int c16 = kk * 2 + hA;
            ldm4(qf[kk], sb + rqa * 128 + (uint32_t)(((c16 ^ (rqa & 7))) << 4));
        }
    }

    int rB = (lane & 7) + ((lane >> 4) & 1) * 8;
    int hB = (lane >> 3) & 1;

    for (int t = 0; t < ntiles; t++) {
        int k0 = t * 128;
        if (t > 0) {
            CP_WAIT0();
            __syncthreads();
        }
        if (t + 1 < ntiles)
            attn_stage_load(sb, (t + 1) & 1, (t + 1) * 128, qkb, bh);

        uint32_t stb = sb + 16384 + (t & 1) * ASTG;

        float s[16][4];
#pragma unroll
        for (int nt = 0; nt < 16; nt++)
#pragma unroll
            for (int i = 0; i < 4; i++) s[nt][i] = 0.0f;
#pragma unroll
        for (int kk = 0; kk < 4; kk++) {
#pragma unroll
            for (int np = 0; np < 8; np++) {
                int row = rB + np * 16;
                int c16 = kk * 2 + hB;
                uint32_t addr = stb + row * 128 + (uint32_t)(((c16 ^ (row & 7))) << 4);
                uint32_t kb4[4];
                ldm4(kb4, addr);
                mma16816h(s[2 * np],     qf[kk], kb4[0], kb4[1]);
                mma16816h(s[2 * np + 1], qf[kk], kb4[2], kb4[3]);
            }
        }

        float mx0 = -1e30f, mx1 = -1e30f;
        if (k0 + 128 > TCUT) {
#pragma unroll
            for (int nt = 0; nt < 16; nt++) {
                int kb = k0 + nt * 8 + (lane & 3) * 2;
                float v0 = (kb     < lim0) ? s[nt][0] * 0.125f : -1e30f;
                float v1 = (kb + 1 < lim0) ? s[nt][1] * 0.125f : -1e30f;
                float v2 = (kb     < lim1) ? s[nt][2] * 0.125f : -1e30f;
                float v3 = (kb + 1 < lim1) ? s[nt][3] * 0.125f : -1e30f;
                s[nt][0] = v0; s[nt][1] = v1; s[nt][2] = v2; s[nt][3] = v3;
                mx0 = fmaxf(mx0, fmaxf(v0, v1));
                mx1 = fmaxf(mx1, fmaxf(v2, v3));
            }
        } else {
#pragma unroll
            for (int nt = 0; nt < 16; nt++) {
                float v0 = s[nt][0] * 0.125f;
                float v1 = s[nt][1] * 0.125f;
                float v2 = s[nt][2] * 0.125f;
                float v3 = s[nt][3] * 0.125f;
                s[nt][0] = v0; s[nt][1] = v1; s[nt][2] = v2; s[nt][3] = v3;
                mx0 = fmaxf(mx0, fmaxf(v0, v1));
                mx1 = fmaxf(mx1, fmaxf(v2, v3));
            }
        }
        mx0 = fmaxf(mx0, __shfl_xor_sync(0xffffffffu, mx0, 1));
        mx0 = fmaxf(mx0, __shfl_xor_sync(0xffffffffu, mx0, 2));
        mx1 = fmaxf(mx1, __shfl_xor_sync(0xffffffffu, mx1, 1));
        mx1 = fmaxf(mx1, __shfl_xor_sync(0xffffffffu, mx1, 2));
        float nm0 = fmaxf(mr0, mx0), nm1 = fmaxf(mr1, mx1);
        float a0 = __expf(mr0 - nm0), a1 = __expf(mr1 - nm1);
        float ls0 = 0.0f, ls1 = 0.0f;
#pragma unroll
        for (int nt = 0; nt < 16; nt++) {
            float p0 = __expf(s[nt][0] - nm0);
            float p1 = __expf(s[nt][1] - nm0);
            float p2 = __expf(s[nt][2] - nm1);
            float p3 = __expf(s[nt][3] - nm1);
            s[nt][0] = p0; s[nt][1] = p1; s[nt][2] = p2; s[nt][3] = p3;
            ls0 += p0 + p1;
            ls1 += p2 + p3;
        }
        ls0 += __shfl_xor_sync(0xffffffffu, ls0, 1);
        ls0 += __shfl_xor_sync(0xffffffffu, ls0, 2);
        ls1 += __shfl_xor_sync(0xffffffffu, ls1, 1);
        ls1 += __shfl_xor_sync(0xffffffffu, ls1, 2);
        lr0 = lr0 * a0 + ls0;
        lr1 = lr1 * a1 + ls1;
        mr0 = nm0; mr1 = nm1;
#pragma unroll
        for (int nt = 0; nt < 8; nt++) {
            o[nt][0] *= a0; o[nt][1] *= a0;
            o[nt][2] *= a1; o[nt][3] *= a1;
        }

#pragma unroll
        for (int kk2 = 0; kk2 < 8; kk2++) {
            uint32_t pah[4];
            pah[0] = pack_f16x2(s[2 * kk2][0],     s[2 * kk2][1]);
            pah[1] = pack_f16x2(s[2 * kk2][2],     s[2 * kk2][3]);
            pah[2] = pack_f16x2(s[2 * kk2 + 1][0], s[2 * kk2 + 1][1]);
            pah[3] = pack_f16x2(s[2 * kk2 + 1][2], s[2 * kk2 + 1][3]);
            int half = kk2 >> 2;
            int c16 = (kk2 & 3) * 2 + hB;
#pragma unroll
            for (int np = 0; np < 4; np++) {
                int row = rB + np * 16;
                uint32_t addr = stb + 16384 + half * 8192 + row * 128 +
                                (uint32_t)(((c16 ^ (row & 7))) << 4);
                uint32_t vb[4];
                ldm4(vb, addr);
                mma16816h(o[2 * np],     pah, vb[0], vb[1]);
                mma16816h(o[2 * np + 1], pah, vb[2], vb[3]);
            }
        }
    }

    float inv0 = 1.0f / lr0, inv1 = 1.0f / lr1;
    int b = bh >> 3, h = bh & 7;
    size_t z0 = (size_t)(b * SEQ + gr0) * FEAT + h * 64;
    size_t z1 = (size_t)(b * SEQ + gr1) * FEAT + h * 64;
#pragma unroll
    for (int nt = 0; nt < 8; nt++) {
        int col = nt * 8 + (lane & 3) * 2;
        __half2 hp0;
        hp0.x = __float2half(o[nt][0] * inv0);
        hp0.y = __float2half(o[nt][1] * inv0);
        __half2 hp1;
        hp1.x = __float2half(o[nt][2] * inv1);
        hp1.y = __float2half(o[nt][3] * inv1);
        *(__half2*)(g_z + z0 + col) = hp0;
        *(__half2*)(g_z + z1 + col) = hp1;
    }
}

// ---------------- launch ----------------
extern "C" void kernel_launch(void* const* d_in, const int* in_sizes, int n_in,
                              void* d_out, int out_size) {
    const float* x     = (const float*)d_in[0];
    const float* gamma = (const float*)d_in[1];
    const float* beta  = (const float*)d_in[2];
    const float* WQ    = (const float*)d_in[3];
    const float* bq    = (const float*)d_in[4];
    const float* WK    = (const float*)d_in[5];
    const float* bk    = (const float*)d_in[6];
    const float* WV    = (const float*)d_in[7];
    const float* bv    = (const float*)d_in[8];
    const float* WO    = (const float*)d_in[9];
    const float* bO    = (const float*)d_in[10];
    float* out = (float*)d_out;

    (void)in_sizes; (void)n_in; (void)out_size;

    cudaFuncSetAttribute(attn_mma, cudaFuncAttributeMaxDynamicSharedMemorySize, AT_SMEM);
    cudaFuncSetAttribute(gemm_qkv_mma, cudaFuncAttributeMaxDynamicSharedMemorySize, GSMEM);
    cudaFuncSetAttribute(gemm_out_mma, cudaFuncAttributeMaxDynamicSharedMemorySize, OSMEM);

    prep_kernel<<<MTOT + 6144 + 2048, 128>>>(x, gamma, beta, WQ, WK, WV, WO);
    gemm_qkv_mma<<<dim3(NQKV / 256, MTOT / 128), GTHREADS, GSMEM>>>(bq, bk, bv);
    attn_mma<<<dim3(SEQ / 128, BATCH * HEADS), 256, AT_SMEM>>>();
    gemm_out_mma<<<dim3(512 / 256, MTOT / 128), GTHREADS, OSMEM>>>(bO, out);
}